// round 2
// baseline (speedup 1.0000x reference)
#include <cuda_runtime.h>
#include <cstdint>

#define N_NODES 50000
#define N_EDGES 800000
#define H 128

// Scratch (allocation-free rule: __device__ globals)
__device__ __align__(16) float g_agg_msg[(size_t)N_NODES * H];
__device__ __align__(16) float g_agg_coord[(size_t)N_NODES * 3];
__device__ __align__(16) float g_count[N_NODES];

__device__ __forceinline__ float silu_f(float v) {
    return v * (1.0f / (1.0f + __expf(-v)));
}

// Tiled GEMM step: acc[4][8] += As(64x128, row-major smem) @ Wg(128x128, global row-major)
// Block: 256 threads, tn = tid&15 (8 cols each), tm = tid>>4 (4 rows each).
__device__ __forceinline__ void gemm128(const float* __restrict__ As,
                                        const float* __restrict__ Wg,
                                        float* sW,
                                        float acc[4][8],
                                        int tm, int tn, int tid)
{
    for (int kt = 0; kt < 128; kt += 16) {
        __syncthreads();  // protect sW from previous chunk's readers
        const float4* Wv = (const float4*)(Wg + (size_t)kt * H);
        float4* sWv = (float4*)sW;
        sWv[tid]       = Wv[tid];
        sWv[tid + 256] = Wv[tid + 256];
        __syncthreads();
#pragma unroll
        for (int kk = 0; kk < 16; kk++) {
            float a[4];
#pragma unroll
            for (int m = 0; m < 4; m++) a[m] = As[(tm * 4 + m) * H + kt + kk];
            float4 w0 = *(const float4*)&sW[kk * H + tn * 8];
            float4 w1 = *(const float4*)&sW[kk * H + tn * 8 + 4];
#pragma unroll
            for (int m = 0; m < 4; m++) {
                acc[m][0] += a[m] * w0.x; acc[m][1] += a[m] * w0.y;
                acc[m][2] += a[m] * w0.z; acc[m][3] += a[m] * w0.w;
                acc[m][4] += a[m] * w1.x; acc[m][5] += a[m] * w1.y;
                acc[m][6] += a[m] * w1.z; acc[m][7] += a[m] * w1.w;
            }
        }
    }
}

__device__ __forceinline__ void init_bias(float acc[4][8], const float* __restrict__ bias, int tn)
{
    float4 b0 = *(const float4*)(bias + tn * 8);
    float4 b1 = *(const float4*)(bias + tn * 8 + 4);
#pragma unroll
    for (int m = 0; m < 4; m++) {
        acc[m][0] = b0.x; acc[m][1] = b0.y; acc[m][2] = b0.z; acc[m][3] = b0.w;
        acc[m][4] = b1.x; acc[m][5] = b1.y; acc[m][6] = b1.z; acc[m][7] = b1.w;
    }
}

__device__ __forceinline__ void apply_silu(float acc[4][8])
{
#pragma unroll
    for (int m = 0; m < 4; m++)
#pragma unroll
        for (int n = 0; n < 8; n++)
            acc[m][n] = silu_f(acc[m][n]);
}

__device__ __forceinline__ void store_act(float* dst, const float acc[4][8], int tm, int tn)
{
#pragma unroll
    for (int m = 0; m < 4; m++) {
        int row = tm * 4 + m;
        float4 v0 = make_float4(acc[m][0], acc[m][1], acc[m][2], acc[m][3]);
        float4 v1 = make_float4(acc[m][4], acc[m][5], acc[m][6], acc[m][7]);
        *(float4*)&dst[row * H + tn * 8]     = v0;
        *(float4*)&dst[row * H + tn * 8 + 4] = v1;
    }
}

// ---------------------------------------------------------------------------
// Zero scratch
// ---------------------------------------------------------------------------
__global__ void zero_kernel()
{
    int i = blockIdx.x * blockDim.x + threadIdx.x;
    if (i < N_NODES * H) g_agg_msg[i] = 0.0f;
    if (i < N_NODES * 3) g_agg_coord[i] = 0.0f;
    if (i < N_NODES)     g_count[i] = 0.0f;
}

// ---------------------------------------------------------------------------
// Fused edge kernel: 64 edges per block.
//   msg = silu(silu([h_s|h_d|ea|d2] @ W1 + b1) @ W2 + b2)
//   cw  = silu(msg @ Wc1 + bc1) @ Wc2 + bc2
//   atomics: agg_msg += msg, agg_coord += rel*cw, count += 1
// ---------------------------------------------------------------------------
__global__ __launch_bounds__(256, 2) void edge_kernel(
    const float* __restrict__ h,   const float* __restrict__ x,
    const int*   __restrict__ ei,  const float* __restrict__ ea,
    const float* __restrict__ W1,  const float* __restrict__ b1,
    const float* __restrict__ W2,  const float* __restrict__ b2,
    const float* __restrict__ Wc1, const float* __restrict__ bc1,
    const float* __restrict__ Wc2, const float* __restrict__ bc2)
{
    extern __shared__ float smem[];
    float* sA   = smem;               // 64*128  (h_src, later hidden1)
    float* sB   = sA + 64 * H;        // 64*128  (h_dst, later msg)
    float* sW   = sB + 64 * H;        // 16*128
    float* sRel = sW + 16 * H;        // 64*3
    float* sEa  = sRel + 64 * 3;      // 64*3
    float* sDsq = sEa + 64 * 3;       // 64
    int*   sSrc = (int*)(sDsq + 64);  // 64
    int*   sDst = sSrc + 64;          // 64

    int tid = threadIdx.x;
    int tn = tid & 15;
    int tm = tid >> 4;
    int ebase = blockIdx.x * 64;

    if (tid < 64) {
        int e = ebase + tid;
        int s = ei[e];
        int d = ei[N_EDGES + e];
        sSrc[tid] = s;
        sDst[tid] = d;
        float rx = x[s * 3 + 0] - x[d * 3 + 0];
        float ry = x[s * 3 + 1] - x[d * 3 + 1];
        float rz = x[s * 3 + 2] - x[d * 3 + 2];
        sRel[tid * 3 + 0] = rx; sRel[tid * 3 + 1] = ry; sRel[tid * 3 + 2] = rz;
        sDsq[tid] = rx * rx + ry * ry + rz * rz;
        sEa[tid * 3 + 0] = ea[e * 3 + 0];
        sEa[tid * 3 + 1] = ea[e * 3 + 1];
        sEa[tid * 3 + 2] = ea[e * 3 + 2];
    }
    __syncthreads();

    // gather h[src] -> sA, h[dst] -> sB (vectorized, coalesced along cols)
    {
        const float4* hv = (const float4*)h;
        float4* sA4 = (float4*)sA;
        float4* sB4 = (float4*)sB;
#pragma unroll
        for (int j = 0; j < 8; j++) {
            int idx = tid + j * 256;          // 0..2047
            int row = idx >> 5;
            int c4  = idx & 31;
            sA4[idx] = hv[(size_t)sSrc[row] * 32 + c4];
            sB4[idx] = hv[(size_t)sDst[row] * 32 + c4];
        }
    }

    float acc[4][8];

    // ---- stage 1: msg_in @ W1 + b1, K = 260 ----
    init_bias(acc, b1, tn);
    gemm128(sA, W1, sW, acc, tm, tn, tid);            // k in [0,128)   : h_src
    gemm128(sB, W1 + 128 * H, sW, acc, tm, tn, tid);  // k in [128,256) : h_dst
    // tail k = 256..259 : edge_attr(3), dist_sq(1)
    __syncthreads();
    if (tid < 128) ((float4*)sW)[tid] = ((const float4*)(W1 + 256 * H))[tid];
    __syncthreads();
#pragma unroll
    for (int m = 0; m < 4; m++) {
        int row = tm * 4 + m;
        float av[4] = { sEa[row * 3 + 0], sEa[row * 3 + 1], sEa[row * 3 + 2], sDsq[row] };
#pragma unroll
        for (int kk = 0; kk < 4; kk++) {
            float4 w0 = *(const float4*)&sW[kk * H + tn * 8];
            float4 w1 = *(const float4*)&sW[kk * H + tn * 8 + 4];
            acc[m][0] += av[kk] * w0.x; acc[m][1] += av[kk] * w0.y;
            acc[m][2] += av[kk] * w0.z; acc[m][3] += av[kk] * w0.w;
            acc[m][4] += av[kk] * w1.x; acc[m][5] += av[kk] * w1.y;
            acc[m][6] += av[kk] * w1.z; acc[m][7] += av[kk] * w1.w;
        }
    }
    apply_silu(acc);
    __syncthreads();
    store_act(sA, acc, tm, tn);   // hidden1 -> sA

    // ---- stage 2: msg = silu(hidden1 @ W2 + b2) ----
    init_bias(acc, b2, tn);
    gemm128(sA, W2, sW, acc, tm, tn, tid);
    apply_silu(acc);
    __syncthreads();
    store_act(sB, acc, tm, tn);   // msg -> sB

    // ---- stage 3: c1 = silu(msg @ Wc1 + bc1) ----
    init_bias(acc, bc1, tn);
    gemm128(sB, Wc1, sW, acc, tm, tn, tid);
    apply_silu(acc);

    // coord_w = c1 @ Wc2 + bc2 : per-row dot over 128, partial over this thread's 8 cols
    {
        float4 c0 = *(const float4*)(Wc2 + tn * 8);
        float4 c1v = *(const float4*)(Wc2 + tn * 8 + 4);
        float pw[4];
#pragma unroll
        for (int m = 0; m < 4; m++) {
            pw[m] = acc[m][0] * c0.x + acc[m][1] * c0.y + acc[m][2] * c0.z + acc[m][3] * c0.w
                  + acc[m][4] * c1v.x + acc[m][5] * c1v.y + acc[m][6] * c1v.z + acc[m][7] * c1v.w;
        }
#pragma unroll
        for (int off = 1; off < 16; off <<= 1) {
#pragma unroll
            for (int m = 0; m < 4; m++)
                pw[m] += __shfl_xor_sync(0xffffffffu, pw[m], off);
        }
        if (tn == 0) {
            float bcc = bc2[0];
#pragma unroll
            for (int m = 0; m < 4; m++) {
                int row = tm * 4 + m;
                int d = sDst[row];
                float w = pw[m] + bcc;
                atomicAdd(&g_agg_coord[(size_t)d * 3 + 0], sRel[row * 3 + 0] * w);
                atomicAdd(&g_agg_coord[(size_t)d * 3 + 1], sRel[row * 3 + 1] * w);
                atomicAdd(&g_agg_coord[(size_t)d * 3 + 2], sRel[row * 3 + 2] * w);
                atomicAdd(&g_count[d], 1.0f);
            }
        }
    }

    // ---- agg_msg atomics (msg is in sB) ----
#pragma unroll
    for (int m = 0; m < 4; m++) {
        int row = tm * 4 + m;
        int d = sDst[row];
        float* dp = &g_agg_msg[(size_t)d * H + tn * 8];
        float4 v0 = *(const float4*)&sB[row * H + tn * 8];
        float4 v1 = *(const float4*)&sB[row * H + tn * 8 + 4];
        atomicAdd(dp + 0, v0.x); atomicAdd(dp + 1, v0.y);
        atomicAdd(dp + 2, v0.z); atomicAdd(dp + 3, v0.w);
        atomicAdd(dp + 4, v1.x); atomicAdd(dp + 5, v1.y);
        atomicAdd(dp + 6, v1.z); atomicAdd(dp + 7, v1.w);
    }
}

// ---------------------------------------------------------------------------
// Fused node kernel: 64 nodes per block.
//   h_upd = silu([h|agg] @ Wn1 + bn1) @ Wn2 + bn2
//   h_out = LN(h + h_upd); x_out = x + agg_coord / max(count,1)
// ---------------------------------------------------------------------------
__global__ __launch_bounds__(256, 2) void node_kernel(
    const float* __restrict__ h,   const float* __restrict__ x,
    const float* __restrict__ Wn1, const float* __restrict__ bn1,
    const float* __restrict__ Wn2, const float* __restrict__ bn2,
    const float* __restrict__ gamma, const float* __restrict__ beta,
    float* __restrict__ out_h, float* __restrict__ out_x)
{
    extern __shared__ float smem[];
    float* sA = smem;            // 64*128 : h tile (kept for residual)
    float* sB = sA + 64 * H;     // 64*128 : agg -> t1 -> y
    float* sW = sB + 64 * H;     // 16*128

    int tid = threadIdx.x;
    int tn = tid & 15;
    int tm = tid >> 4;
    int nbase = blockIdx.x * 64;

    // gather h and agg_msg tiles (guard tail)
    {
        const float4* hv = (const float4*)h;
        const float4* av = (const float4*)g_agg_msg;
        float4* sA4 = (float4*)sA;
        float4* sB4 = (float4*)sB;
        float4 z = make_float4(0.f, 0.f, 0.f, 0.f);
#pragma unroll
        for (int j = 0; j < 8; j++) {
            int idx = tid + j * 256;
            int row = idx >> 5;
            int c4  = idx & 31;
            int node = nbase + row;
            if (node < N_NODES) {
                sA4[idx] = hv[(size_t)node * 32 + c4];
                sB4[idx] = av[(size_t)node * 32 + c4];
            } else {
                sA4[idx] = z; sB4[idx] = z;
            }
        }
    }

    float acc[4][8];

    // ---- t1 = silu([h|agg] @ Wn1 + bn1), K = 256 ----
    init_bias(acc, bn1, tn);
    gemm128(sA, Wn1, sW, acc, tm, tn, tid);
    gemm128(sB, Wn1 + 128 * H, sW, acc, tm, tn, tid);
    apply_silu(acc);
    __syncthreads();
    store_act(sB, acc, tm, tn);   // t1 -> sB

    // ---- h_upd = t1 @ Wn2 + bn2 ----
    init_bias(acc, bn2, tn);
    gemm128(sB, Wn2, sW, acc, tm, tn, tid);

    // y = h + h_upd -> sB
    __syncthreads();
#pragma unroll
    for (int m = 0; m < 4; m++) {
        int row = tm * 4 + m;
        float4 h0 = *(const float4*)&sA[row * H + tn * 8];
        float4 h1 = *(const float4*)&sA[row * H + tn * 8 + 4];
        float4 y0 = make_float4(h0.x + acc[m][0], h0.y + acc[m][1], h0.z + acc[m][2], h0.w + acc[m][3]);
        float4 y1 = make_float4(h1.x + acc[m][4], h1.y + acc[m][5], h1.z + acc[m][6], h1.w + acc[m][7]);
        *(float4*)&sB[row * H + tn * 8]     = y0;
        *(float4*)&sB[row * H + tn * 8 + 4] = y1;
    }
    __syncthreads();

    // ---- LayerNorm over 128 : 4 threads per row ----
    {
        int row = tid >> 2;
        int part = tid & 3;
        int node = nbase + row;
        const float4* yv = (const float4*)sB;
        float s = 0.f, sq = 0.f;
        float4 vals[8];
#pragma unroll
        for (int j = 0; j < 8; j++) {
            float4 v = yv[row * 32 + part * 8 + j];
            vals[j] = v;
            s  += v.x + v.y + v.z + v.w;
            sq += v.x * v.x + v.y * v.y + v.z * v.z + v.w * v.w;
        }
        s  += __shfl_xor_sync(0xffffffffu, s, 1);
        sq += __shfl_xor_sync(0xffffffffu, sq, 1);
        s  += __shfl_xor_sync(0xffffffffu, s, 2);
        sq += __shfl_xor_sync(0xffffffffu, sq, 2);
        float mu  = s * (1.0f / 128.0f);
        float var = sq * (1.0f / 128.0f) - mu * mu;
        float inv = rsqrtf(var + 1e-5f);
        if (node < N_NODES) {
            float4* ov = (float4*)(out_h + (size_t)node * H);
#pragma unroll
            for (int j = 0; j < 8; j++) {
                int c4 = part * 8 + j;
                float4 g = *(const float4*)(gamma + c4 * 4);
                float4 b = *(const float4*)(beta + c4 * 4);
                float4 v = vals[j];
                float4 o;
                o.x = (v.x - mu) * inv * g.x + b.x;
                o.y = (v.y - mu) * inv * g.y + b.y;
                o.z = (v.z - mu) * inv * g.z + b.z;
                o.w = (v.w - mu) * inv * g.w + b.w;
                ov[c4] = o;
            }
        }
    }

    // ---- x_out ----
    if (tid < 192) {
        int r = tid / 3, c = tid % 3;
        int node = nbase + r;
        if (node < N_NODES) {
            float cnt = fmaxf(g_count[node], 1.0f);
            out_x[(size_t)node * 3 + c] = x[(size_t)node * 3 + c]
                                        + g_agg_coord[(size_t)node * 3 + c] / cnt;
        }
    }
}

// ---------------------------------------------------------------------------
extern "C" void kernel_launch(void* const* d_in, const int* in_sizes, int n_in,
                              void* d_out, int out_size)
{
    const float* h    = (const float*)d_in[0];
    const float* x    = (const float*)d_in[1];
    const int*   eidx = (const int*)  d_in[2];
    const float* ea   = (const float*)d_in[3];
    const float* W1   = (const float*)d_in[4];
    const float* b1   = (const float*)d_in[5];
    const float* W2   = (const float*)d_in[6];
    const float* b2   = (const float*)d_in[7];
    const float* Wc1  = (const float*)d_in[8];
    const float* bc1  = (const float*)d_in[9];
    const float* Wc2  = (const float*)d_in[10];
    const float* bc2  = (const float*)d_in[11];
    const float* Wn1  = (const float*)d_in[12];
    const float* bn1  = (const float*)d_in[13];
    const float* Wn2  = (const float*)d_in[14];
    const float* bn2  = (const float*)d_in[15];
    const float* gamma = (const float*)d_in[16];
    const float* beta  = (const float*)d_in[17];

    float* out_h = (float*)d_out;
    float* out_x = out_h + (size_t)N_NODES * H;

    const int EDGE_SMEM = (64 * H + 64 * H + 16 * H + 64 * 3 + 64 * 3 + 64 + 64 + 64) * 4;
    const int NODE_SMEM = (64 * H + 64 * H + 16 * H) * 4;
    cudaFuncSetAttribute(edge_kernel, cudaFuncAttributeMaxDynamicSharedMemorySize, EDGE_SMEM);
    cudaFuncSetAttribute(node_kernel, cudaFuncAttributeMaxDynamicSharedMemorySize, NODE_SMEM);

    zero_kernel<<<(N_NODES * H + 255) / 256, 256>>>();
    edge_kernel<<<N_EDGES / 64, 256, EDGE_SMEM>>>(h, x, eidx, ea,
                                                  W1, b1, W2, b2, Wc1, bc1, Wc2, bc2);
    node_kernel<<<(N_NODES + 63) / 64, 256, NODE_SMEM>>>(h, x, Wn1, bn1, Wn2, bn2,
                                                         gamma, beta, out_h, out_x);
}

// round 4
// speedup vs baseline: 2.0594x; 2.0594x over previous
#include <cuda_runtime.h>
#include <cuda_bf16.h>
#include <cstdint>

#define N_NODES 50000
#define N_EDGES 800000
#define H 128

// ---------------- device scratch ----------------
__device__ __align__(16) float g_agg_msg[(size_t)N_NODES * H];
__device__ __align__(16) float g_agg_coord4[(size_t)N_NODES * 4];  // x,y,z,count
// Weights in B-fragment layout, bf16 hi/lo planes, chunked by k32.
__device__ __align__(16) unsigned short g_W1b[9 * 4096 * 2];
__device__ __align__(16) unsigned short g_W2b[4 * 4096 * 2];
__device__ __align__(16) unsigned short g_Wc1b[4 * 4096 * 2];

// ---------------- helpers ----------------
__device__ __forceinline__ uint32_t smem_u32(const void* p) {
    uint32_t a;
    asm("{ .reg .u64 t; cvta.to.shared.u64 t, %1; cvt.u32.u64 %0, t; }" : "=r"(a) : "l"(p));
    return a;
}
__device__ __forceinline__ float bf16rt(float v) {
    return __bfloat162float(__float2bfloat16(v));
}
__device__ __forceinline__ uint32_t pack2bf(float a, float b) {
    unsigned short ua = __bfloat16_as_ushort(__float2bfloat16(a));
    unsigned short ub = __bfloat16_as_ushort(__float2bfloat16(b));
    return (uint32_t)ua | ((uint32_t)ub << 16);
}
__device__ __forceinline__ float silu_f(float v) {
    return v * (1.0f / (1.0f + __expf(-v)));
}
__device__ __forceinline__ void redv2(float* p, float a, float b) {
    asm volatile("red.global.add.v2.f32 [%0], {%1, %2};" :: "l"(p), "f"(a), "f"(b) : "memory");
}
__device__ __forceinline__ void redv4(float* p, float a, float b, float c, float d) {
    asm volatile("red.global.add.v4.f32 [%0], {%1, %2, %3, %4};"
                 :: "l"(p), "f"(a), "f"(b), "f"(c), "f"(d) : "memory");
}
__device__ __forceinline__ void ldm4(uint32_t* r, uint32_t addr) {
    asm volatile("ldmatrix.sync.aligned.m8n8.x4.shared.b16 {%0,%1,%2,%3}, [%4];"
                 : "=r"(r[0]), "=r"(r[1]), "=r"(r[2]), "=r"(r[3]) : "r"(addr));
}
__device__ __forceinline__ void mma_bf16(float* d, const uint32_t* a, uint32_t b0, uint32_t b1) {
    asm volatile("mma.sync.aligned.m16n8k16.row.col.f32.bf16.bf16.f32 "
                 "{%0,%1,%2,%3}, {%4,%5,%6,%7}, {%8,%9}, {%0,%1,%2,%3};"
                 : "+f"(d[0]), "+f"(d[1]), "+f"(d[2]), "+f"(d[3])
                 : "r"(a[0]), "r"(a[1]), "r"(a[2]), "r"(a[3]), "r"(b0), "r"(b1));
}

// ---------------- smem layout (edge kernel) ----------------
// A-full: 4 chunks(k32) x [hi plane | lo plane], each plane 128 rows x 20 words(80B)
#define AF_OFF   0         // 4 * 20480 = 81920
#define BB_OFF   81920     // B chunk: 4096 words = 16384 B
#define BIAS_OFF 98304     // b1,b2,bc1,Wc2 : 4*512
#define REL_OFF  100352    // 128*3 floats
#define EA_OFF   101888
#define DSQ_OFF  103424
#define SRC_OFF  103936
#define DST_OFF  104448
#define PW_OFF   104960    // 2*128 floats
#define EDGE_SMEM 105984

// ---------------- zero / prep ----------------
__global__ void zero_kernel()
{
    int i = blockIdx.x * blockDim.x + threadIdx.x;
    if (i < N_NODES * H) g_agg_msg[i] = 0.0f;
    if (i < N_NODES * 4) g_agg_coord4[i] = 0.0f;
}

// W[K,128] -> bf16 hi/lo in exact mma B-fragment layout.
// word idx (per chunk k32): ((ks*2+plane)*16+nf)*64 + reg*32 + lane ; chunk stride 4096 words.
__global__ void prep_kernel(const float* __restrict__ W, int which, int Kact, int Kpad)
{
    int idx = blockIdx.x * blockDim.x + threadIdx.x;
    if (idx >= 128 * Kpad) return;
    int k = idx >> 7;
    int n = idx & 127;
    float v = (k < Kact) ? W[k * 128 + n] : 0.0f;
    float fhi = bf16rt(v);
    float flo = v - fhi;
    int chunk = k >> 5, ks = (k >> 4) & 1, reg = (k >> 3) & 1;
    int kr = k & 7, nf = n >> 3, lanep = ((n & 7) << 2) | (kr >> 1), half = k & 1;
    unsigned short* dst = (which == 0) ? g_W1b : (which == 1) ? g_W2b : g_Wc1b;
    int wi_hi = chunk * 4096 + ((ks * 2 + 0) * 16 + nf) * 64 + reg * 32 + lanep;
    int wi_lo = wi_hi + 1024;  // plane 1
    dst[wi_hi * 2 + half] = __bfloat16_as_ushort(__float2bfloat16(fhi));
    dst[wi_lo * 2 + half] = __bfloat16_as_ushort(__float2bfloat16(flo));
}

// ---------------- edge kernel stages ----------------
__device__ __forceinline__ void init_d(float d[2][8][4], const float* sBias,
                                       int stage, int lane, int wc)
{
#pragma unroll
    for (int nf = 0; nf < 8; nf++) {
        int c0 = wc * 64 + nf * 8 + (lane & 3) * 2;
        float b0v = sBias[stage * 128 + c0];
        float b1v = sBias[stage * 128 + c0 + 1];
#pragma unroll
        for (int mf = 0; mf < 2; mf++) {
            d[mf][nf][0] = b0v; d[mf][nf][1] = b1v;
            d[mf][nf][2] = b0v; d[mf][nf][3] = b1v;
        }
    }
}

template<int STAGE>
__device__ __forceinline__ void run_stage(char* sb, uint32_t sbase, const float4* hv,
                                          const int* sSrc, const int* sDst,
                                          const float* sEa, const float* sDsq,
                                          float d[2][8][4], int tid, int lane, int wm, int wc)
{
    const int NC = (STAGE == 0) ? 9 : 4;
    const unsigned short* gW = (STAGE == 0) ? g_W1b : (STAGE == 1) ? g_W2b : g_Wc1b;
    const uint4* gW4 = (const uint4*)gW;
    uint32_t* bw = (uint32_t*)(sb + BB_OFF);

#pragma unroll 1
    for (int c = 0; c < NC; c++) {
        __syncthreads();  // prior mma done reading B/A buffers
        // ---- B chunk copy (16KB) ----
        {
            uint4* bdst = (uint4*)(sb + BB_OFF);
            const uint4* bsrc = gW4 + (size_t)c * 1024;
#pragma unroll
            for (int i = 0; i < 4; i++) bdst[tid + i * 256] = bsrc[tid + i * 256];
        }
        int slot = (STAGE == 0) ? (c & 3) : c;
        // ---- A chunk build (stage 0 only) ----
        if (STAGE == 0) {
            int row = tid >> 1, halfq = tid & 1;
            uint32_t* ph = (uint32_t*)(sb + AF_OFF + slot * 20480 + row * 80);
            uint32_t* pl = (uint32_t*)((char*)ph + 10240);
            if (c < 8) {
                int node = ((c < 4) ? sSrc : sDst)[row];
                int cb = c & 3;
#pragma unroll
                for (int j = 0; j < 4; j++) {
                    float4 v = hv[(size_t)node * 32 + cb * 8 + halfq * 4 + j];
                    int w0 = halfq * 8 + j * 2;
                    ph[w0]     = pack2bf(v.x, v.y);
                    ph[w0 + 1] = pack2bf(v.z, v.w);
                    pl[w0]     = pack2bf(v.x - bf16rt(v.x), v.y - bf16rt(v.y));
                    pl[w0 + 1] = pack2bf(v.z - bf16rt(v.z), v.w - bf16rt(v.w));
                }
            } else {  // tail chunk: [ea0,ea1,ea2,dsq, 0 ...]
                uint32_t* p = halfq ? pl : ph;
                if (halfq == 0) {
                    p[0] = pack2bf(sEa[row * 3 + 0], sEa[row * 3 + 1]);
                    p[1] = pack2bf(sEa[row * 3 + 2], sDsq[row]);
                } else {
                    float e0 = sEa[row * 3 + 0], e1 = sEa[row * 3 + 1];
                    float e2 = sEa[row * 3 + 2], dq = sDsq[row];
                    p[0] = pack2bf(e0 - bf16rt(e0), e1 - bf16rt(e1));
                    p[1] = pack2bf(e2 - bf16rt(e2), dq - bf16rt(dq));
                }
#pragma unroll
                for (int w = 2; w < 16; w++) p[w] = 0u;
            }
        }
        __syncthreads();

        // ---- mma: 2 ksteps x 8 nfrags x 2 mfrags x 3 products ----
        uint32_t aBase = sbase + AF_OFF + slot * 20480
                       + (uint32_t)(wm * 32 + (lane & 15)) * 80
                       + ((lane & 16) ? 16u : 0u);
#pragma unroll
        for (int ks = 0; ks < 2; ks++) {
            uint32_t aHi[2][4], aLo[2][4];
#pragma unroll
            for (int mf = 0; mf < 2; mf++) {
                uint32_t ad = aBase + mf * 1280 + ks * 32;
                ldm4(aHi[mf], ad);
                ldm4(aLo[mf], ad + 10240);
            }
#pragma unroll
            for (int nf = 0; nf < 8; nf++) {
                int nfg = wc * 8 + nf;
                int bi_hi = ((ks * 2 + 0) * 16 + nfg) * 64 + lane;
                int bi_lo = ((ks * 2 + 1) * 16 + nfg) * 64 + lane;
                uint32_t bh0 = bw[bi_hi], bh1 = bw[bi_hi + 32];
                uint32_t bl0 = bw[bi_lo], bl1 = bw[bi_lo + 32];
#pragma unroll
                for (int mf = 0; mf < 2; mf++) {
                    mma_bf16(d[mf][nf], aHi[mf], bh0, bh1);
                    mma_bf16(d[mf][nf], aHi[mf], bl0, bl1);
                    mma_bf16(d[mf][nf], aLo[mf], bh0, bh1);
                }
            }
        }
    }
}

// epilogue: silu(d) -> (STAGE 0/1: write A-full splits; STAGE 1: + red agg_msg;
//                       STAGE 2: dot Wc2 -> coord red)
template<int STAGE>
__device__ __forceinline__ void epilogue(char* sb, float d[2][8][4],
                                         const int* sDst, const float* sRel,
                                         const float* bc2, float* sPw,
                                         int tid, int lane, int wm, int wc)
{
    __syncthreads();  // all warps done reading A-full / B
    const float* sBias = (const float*)(sb + BIAS_OFF);
    float pw0[2] = {0.f, 0.f}, pw1[2] = {0.f, 0.f};
#pragma unroll
    for (int mf = 0; mf < 2; mf++) {
        int r0 = wm * 32 + mf * 16 + (lane >> 2);
        int r1 = r0 + 8;
#pragma unroll
        for (int nf = 0; nf < 8; nf++) {
            int c0 = wc * 64 + nf * 8 + (lane & 3) * 2;
            float v0 = silu_f(d[mf][nf][0]);
            float v1 = silu_f(d[mf][nf][1]);
            float v2 = silu_f(d[mf][nf][2]);
            float v3 = silu_f(d[mf][nf][3]);
            if (STAGE == 2) {
                float w0 = sBias[384 + c0], w1 = sBias[384 + c0 + 1];
                pw0[mf] += v0 * w0 + v1 * w1;
                pw1[mf] += v2 * w0 + v3 * w1;
            } else {
                if (STAGE == 1) {
                    redv2(&g_agg_msg[(size_t)sDst[r0] * H + c0], v0, v1);
                    redv2(&g_agg_msg[(size_t)sDst[r1] * H + c0], v2, v3);
                }
                int chunk = c0 >> 5;
                int wofs = (c0 & 31) >> 1;
                uint32_t* ph0 = (uint32_t*)(sb + AF_OFF + chunk * 20480 + r0 * 80) + wofs;
                uint32_t* ph1 = (uint32_t*)(sb + AF_OFF + chunk * 20480 + r1 * 80) + wofs;
                ph0[0]    = pack2bf(v0, v1);
                ph0[2560] = pack2bf(v0 - bf16rt(v0), v1 - bf16rt(v1));  // +10240B
                ph1[0]    = pack2bf(v2, v3);
                ph1[2560] = pack2bf(v2 - bf16rt(v2), v3 - bf16rt(v3));
            }
        }
    }
    if (STAGE == 2) {
#pragma unroll
        for (int o = 1; o < 4; o <<= 1) {
            pw0[0] += __shfl_xor_sync(0xffffffffu, pw0[0], o);
            pw0[1] += __shfl_xor_sync(0xffffffffu, pw0[1], o);
            pw1[0] += __shfl_xor_sync(0xffffffffu, pw1[0], o);
            pw1[1] += __shfl_xor_sync(0xffffffffu, pw1[1], o);
        }
        if ((lane & 3) == 0) {
            int r = wm * 32 + (lane >> 2);
            sPw[wc * 128 + r]      = pw0[0];
            sPw[wc * 128 + r + 8]  = pw1[0];
            sPw[wc * 128 + r + 16] = pw0[1];
            sPw[wc * 128 + r + 24] = pw1[1];
        }
        __syncthreads();
        if (tid < 128) {
            float w = sPw[tid] + sPw[128 + tid] + bc2[0];
            int dd = sDst[tid];
            redv4(&g_agg_coord4[(size_t)dd * 4],
                  sRel[tid * 3 + 0] * w, sRel[tid * 3 + 1] * w, sRel[tid * 3 + 2] * w, 1.0f);
        }
    }
}

__global__ __launch_bounds__(256, 1) void edge_kernel(
    const float* __restrict__ h,  const float* __restrict__ x,
    const int*   __restrict__ ei, const float* __restrict__ ea,
    const float* __restrict__ b1, const float* __restrict__ b2,
    const float* __restrict__ bc1, const float* __restrict__ Wc2,
    const float* __restrict__ bc2)
{
    extern __shared__ char sb[];
    uint32_t sbase = smem_u32(sb);
    int tid = threadIdx.x, lane = tid & 31, wid = tid >> 5;
    int wm = wid & 3, wc = wid >> 2;
    int ebase = blockIdx.x * 128;

    float* sBias = (float*)(sb + BIAS_OFF);
    float* sRel  = (float*)(sb + REL_OFF);
    float* sEa   = (float*)(sb + EA_OFF);
    float* sDsq  = (float*)(sb + DSQ_OFF);
    int*   sSrc  = (int*)(sb + SRC_OFF);
    int*   sDst  = (int*)(sb + DST_OFF);
    float* sPw   = (float*)(sb + PW_OFF);

    if (tid < 128) {
        sBias[tid]       = b1[tid];
        sBias[128 + tid] = b2[tid];
        sBias[256 + tid] = bc1[tid];
        sBias[384 + tid] = Wc2[tid];
        int e = ebase + tid;
        int s = ei[e];
        int dd = ei[N_EDGES + e];
        sSrc[tid] = s; sDst[tid] = dd;
        float rx = x[s * 3 + 0] - x[dd * 3 + 0];
        float ry = x[s * 3 + 1] - x[dd * 3 + 1];
        float rz = x[s * 3 + 2] - x[dd * 3 + 2];
        sRel[tid * 3 + 0] = rx; sRel[tid * 3 + 1] = ry; sRel[tid * 3 + 2] = rz;
        sDsq[tid] = rx * rx + ry * ry + rz * rz;
        sEa[tid * 3 + 0] = ea[e * 3 + 0];
        sEa[tid * 3 + 1] = ea[e * 3 + 1];
        sEa[tid * 3 + 2] = ea[e * 3 + 2];
    }
    __syncthreads();

    const float4* hv = (const float4*)h;
    float d[2][8][4];

    init_d(d, sBias, 0, lane, wc);
    run_stage<0>(sb, sbase, hv, sSrc, sDst, sEa, sDsq, d, tid, lane, wm, wc);
    epilogue<0>(sb, d, sDst, sRel, bc2, sPw, tid, lane, wm, wc);

    init_d(d, sBias, 1, lane, wc);
    run_stage<1>(sb, sbase, hv, sSrc, sDst, sEa, sDsq, d, tid, lane, wm, wc);
    epilogue<1>(sb, d, sDst, sRel, bc2, sPw, tid, lane, wm, wc);

    init_d(d, sBias, 2, lane, wc);
    run_stage<2>(sb, sbase, hv, sSrc, sDst, sEa, sDsq, d, tid, lane, wm, wc);
    epilogue<2>(sb, d, sDst, sRel, bc2, sPw, tid, lane, wm, wc);
}

// ---------------- SIMT node kernel (64 nodes / block) ----------------
__device__ __forceinline__ void gemm128(const float* __restrict__ As,
                                        const float* __restrict__ Wg,
                                        float* sW, float acc[4][8],
                                        int tm, int tn, int tid)
{
    for (int kt = 0; kt < 128; kt += 16) {
        __syncthreads();
        const float4* Wv = (const float4*)(Wg + (size_t)kt * H);
        float4* sWv = (float4*)sW;
        sWv[tid]       = Wv[tid];
        sWv[tid + 256] = Wv[tid + 256];
        __syncthreads();
#pragma unroll
        for (int kk = 0; kk < 16; kk++) {
            float a[4];
#pragma unroll
            for (int m = 0; m < 4; m++) a[m] = As[(tm * 4 + m) * H + kt + kk];
            float4 w0 = *(const float4*)&sW[kk * H + tn * 8];
            float4 w1 = *(const float4*)&sW[kk * H + tn * 8 + 4];
#pragma unroll
            for (int m = 0; m < 4; m++) {
                acc[m][0] += a[m] * w0.x; acc[m][1] += a[m] * w0.y;
                acc[m][2] += a[m] * w0.z; acc[m][3] += a[m] * w0.w;
                acc[m][4] += a[m] * w1.x; acc[m][5] += a[m] * w1.y;
                acc[m][6] += a[m] * w1.z; acc[m][7] += a[m] * w1.w;
            }
        }
    }
}

__global__ __launch_bounds__(256, 2) void node_kernel(
    const float* __restrict__ h,   const float* __restrict__ x,
    const float* __restrict__ Wn1, const float* __restrict__ bn1,
    const float* __restrict__ Wn2, const float* __restrict__ bn2,
    const float* __restrict__ gamma, const float* __restrict__ beta,
    float* __restrict__ out_h, float* __restrict__ out_x)
{
    extern __shared__ float smem[];
    float* sA = smem;
    float* sB = sA + 64 * H;
    float* sW = sB + 64 * H;

    int tid = threadIdx.x;
    int tn = tid & 15;
    int tm = tid >> 4;
    int nbase = blockIdx.x * 64;

    {
        const float4* hv = (const float4*)h;
        const float4* av = (const float4*)g_agg_msg;
        float4* sA4 = (float4*)sA;
        float4* sB4 = (float4*)sB;
        float4 z = make_float4(0.f, 0.f, 0.f, 0.f);
#pragma unroll
        for (int j = 0; j < 8; j++) {
            int idx = tid + j * 256;
            int row = idx >> 5;
            int c4 = idx & 31;
            int node = nbase + row;
            if (node < N_NODES) {
                sA4[idx] = hv[(size_t)node * 32 + c4];
                sB4[idx] = av[(size_t)node * 32 + c4];
            } else { sA4[idx] = z; sB4[idx] = z; }
        }
    }

    float acc[4][8];
    {
        float4 b0 = *(const float4*)(bn1 + tn * 8);
        float4 b1v = *(const float4*)(bn1 + tn * 8 + 4);
#pragma unroll
        for (int m = 0; m < 4; m++) {
            acc[m][0] = b0.x; acc[m][1] = b0.y; acc[m][2] = b0.z; acc[m][3] = b0.w;
            acc[m][4] = b1v.x; acc[m][5] = b1v.y; acc[m][6] = b1v.z; acc[m][7] = b1v.w;
        }
    }
    gemm128(sA, Wn1, sW, acc, tm, tn, tid);
    gemm128(sB, Wn1 + 128 * H, sW, acc, tm, tn, tid);
#pragma unroll
    for (int m = 0; m < 4; m++)
#pragma unroll
        for (int n = 0; n < 8; n++)
            acc[m][n] = silu_f(acc[m][n]);
    __syncthreads();
#pragma unroll
    for (int m = 0; m < 4; m++) {
        int row = tm * 4 + m;
        *(float4*)&sB[row * H + tn * 8]     = make_float4(acc[m][0], acc[m][1], acc[m][2], acc[m][3]);
        *(float4*)&sB[row * H + tn * 8 + 4] = make_float4(acc[m][4], acc[m][5], acc[m][6], acc[m][7]);
    }

    {
        float4 b0 = *(const float4*)(bn2 + tn * 8);
        float4 b1v = *(const float4*)(bn2 + tn * 8 + 4);
#pragma unroll
        for (int m = 0; m < 4; m++) {
            acc[m][0] = b0.x; acc[m][1] = b0.y; acc[m][2] = b0.z; acc[m][3] = b0.w;
            acc[m][4] = b1v.x; acc[m][5] = b1v.y; acc[m][6] = b1v.z; acc[m][7] = b1v.w;
        }
    }
    gemm128(sB, Wn2, sW, acc, tm, tn, tid);

    __syncthreads();
#pragma unroll
    for (int m = 0; m < 4; m++) {
        int row = tm * 4 + m;
        float4 h0 = *(const float4*)&sA[row * H + tn * 8];
        float4 h1 = *(const float4*)&sA[row * H + tn * 8 + 4];
        *(float4*)&sB[row * H + tn * 8]     = make_float4(h0.x + acc[m][0], h0.y + acc[m][1], h0.z + acc[m][2], h0.w + acc[m][3]);
        *(float4*)&sB[row * H + tn * 8 + 4] = make_float4(h1.x + acc[m][4], h1.y + acc[m][5], h1.z + acc[m][6], h1.w + acc[m][7]);
    }
    __syncthreads();

    {
        int row = tid >> 2;
        int part = tid & 3;
        int node = nbase + row;
        const float4* yv = (const float4*)sB;
        float s = 0.f, sq = 0.f;
        float4 vals[8];
#pragma unroll
        for (int j = 0; j < 8; j++) {
            float4 v = yv[row * 32 + part * 8 + j];
            vals[j] = v;
            s  += v.x + v.y + v.z + v.w;
            sq += v.x * v.x + v.y * v.y + v.z * v.z + v.w * v.w;
        }
        s  += __shfl_xor_sync(0xffffffffu, s, 1);
        sq += __shfl_xor_sync(0xffffffffu, sq, 1);
        s  += __shfl_xor_sync(0xffffffffu, s, 2);
        sq += __shfl_xor_sync(0xffffffffu, sq, 2);
        float mu  = s * (1.0f / 128.0f);
        float var = sq * (1.0f / 128.0f) - mu * mu;
        float inv = rsqrtf(var + 1e-5f);
        if (node < N_NODES) {
            float4* ov = (float4*)(out_h + (size_t)node * H);
#pragma unroll
            for (int j = 0; j < 8; j++) {
                int c4 = part * 8 + j;
                float4 g = *(const float4*)(gamma + c4 * 4);
                float4 b = *(const float4*)(beta + c4 * 4);
                float4 v = vals[j];
                ov[c4] = make_float4((v.x - mu) * inv * g.x + b.x,
                                     (v.y - mu) * inv * g.y + b.y,
                                     (v.z - mu) * inv * g.z + b.z,
                                     (v.w - mu) * inv * g.w + b.w);
            }
        }
    }

    if (tid < 192) {
        int r = tid / 3, c = tid % 3;
        int node = nbase + r;
        if (node < N_NODES) {
            float cnt = fmaxf(g_agg_coord4[(size_t)node * 4 + 3], 1.0f);
            out_x[(size_t)node * 3 + c] = x[(size_t)node * 3 + c]
                                        + g_agg_coord4[(size_t)node * 4 + c] / cnt;
        }
    }
}

// ---------------------------------------------------------------------------
extern "C" void kernel_launch(void* const* d_in, const int* in_sizes, int n_in,
                              void* d_out, int out_size)
{
    const float* h    = (const float*)d_in[0];
    const float* x    = (const float*)d_in[1];
    const int*   eidx = (const int*)  d_in[2];
    const float* ea   = (const float*)d_in[3];
    const float* W1   = (const float*)d_in[4];
    const float* b1   = (const float*)d_in[5];
    const float* W2   = (const float*)d_in[6];
    const float* b2   = (const float*)d_in[7];
    const float* Wc1  = (const float*)d_in[8];
    const float* bc1  = (const float*)d_in[9];
    const float* Wc2  = (const float*)d_in[10];
    const float* bc2  = (const float*)d_in[11];
    const float* Wn1  = (const float*)d_in[12];
    const float* bn1  = (const float*)d_in[13];
    const float* Wn2  = (const float*)d_in[14];
    const float* bn2  = (const float*)d_in[15];
    const float* gamma = (const float*)d_in[16];
    const float* beta  = (const float*)d_in[17];

    float* out_h = (float*)d_out;
    float* out_x = out_h + (size_t)N_NODES * H;

    const int NODE_SMEM = (64 * H + 64 * H + 16 * H) * 4;
    cudaFuncSetAttribute(edge_kernel, cudaFuncAttributeMaxDynamicSharedMemorySize, EDGE_SMEM);
    cudaFuncSetAttribute(node_kernel, cudaFuncAttributeMaxDynamicSharedMemorySize, NODE_SMEM);

    zero_kernel<<<(N_NODES * H + 255) / 256, 256>>>();
    prep_kernel<<<(128 * 288 + 255) / 256, 256>>>(W1, 0, 260, 288);
    prep_kernel<<<(128 * 128 + 255) / 256, 256>>>(W2, 1, 128, 128);
    prep_kernel<<<(128 * 128 + 255) / 256, 256>>>(Wc1, 2, 128, 128);
    edge_kernel<<<N_EDGES / 128, 256, EDGE_SMEM>>>(h, x, eidx, ea, b1, b2, bc1, Wc2, bc2);
    node_kernel<<<(N_NODES + 63) / 64, 256, NODE_SMEM>>>(h, x, Wn1, bn1, Wn2, bn2,
                                                         gamma, beta, out_h, out_x);
}

// round 5
// speedup vs baseline: 2.3342x; 1.1334x over previous
#include <cuda_runtime.h>
#include <cuda_bf16.h>
#include <cstdint>

#define N_NODES 50000
#define N_EDGES 800000
#define H 128

// ---------------- device scratch ----------------
__device__ __align__(16) float g_agg_msg[(size_t)N_NODES * H];
__device__ __align__(16) float g_agg_coord4[(size_t)N_NODES * 4];  // x,y,z,count
// Weights in B-fragment layout, bf16 hi/lo planes, chunked by k32.
__device__ __align__(16) unsigned short g_W1b[9 * 4096 * 2];
__device__ __align__(16) unsigned short g_W2b[4 * 4096 * 2];
__device__ __align__(16) unsigned short g_Wc1b[4 * 4096 * 2];

// ---------------- helpers ----------------
__device__ __forceinline__ uint32_t smem_u32(const void* p) {
    uint32_t a;
    asm("{ .reg .u64 t; cvta.to.shared.u64 t, %1; cvt.u32.u64 %0, t; }" : "=r"(a) : "l"(p));
    return a;
}
__device__ __forceinline__ float bf16rt(float v) {
    return __bfloat162float(__float2bfloat16(v));
}
__device__ __forceinline__ uint32_t pack2bf(float a, float b) {
    unsigned short ua = __bfloat16_as_ushort(__float2bfloat16(a));
    unsigned short ub = __bfloat16_as_ushort(__float2bfloat16(b));
    return (uint32_t)ua | ((uint32_t)ub << 16);
}
__device__ __forceinline__ float silu_f(float v) {
    return v * (1.0f / (1.0f + __expf(-v)));
}
__device__ __forceinline__ void redv2(float* p, float a, float b) {
    asm volatile("red.global.add.v2.f32 [%0], {%1, %2};" :: "l"(p), "f"(a), "f"(b) : "memory");
}
__device__ __forceinline__ void redv4(float* p, float a, float b, float c, float d) {
    asm volatile("red.global.add.v4.f32 [%0], {%1, %2, %3, %4};"
                 :: "l"(p), "f"(a), "f"(b), "f"(c), "f"(d) : "memory");
}
__device__ __forceinline__ void ldm4(uint32_t* r, uint32_t addr) {
    asm volatile("ldmatrix.sync.aligned.m8n8.x4.shared.b16 {%0,%1,%2,%3}, [%4];"
                 : "=r"(r[0]), "=r"(r[1]), "=r"(r[2]), "=r"(r[3]) : "r"(addr));
}
__device__ __forceinline__ void mma_bf16(float* d, const uint32_t* a, uint32_t b0, uint32_t b1) {
    asm volatile("mma.sync.aligned.m16n8k16.row.col.f32.bf16.bf16.f32 "
                 "{%0,%1,%2,%3}, {%4,%5,%6,%7}, {%8,%9}, {%0,%1,%2,%3};"
                 : "+f"(d[0]), "+f"(d[1]), "+f"(d[2]), "+f"(d[3])
                 : "r"(a[0]), "r"(a[1]), "r"(a[2]), "r"(a[3]), "r"(b0), "r"(b1));
}
__device__ __forceinline__ void cp_async16(uint32_t dst, const void* src) {
    asm volatile("cp.async.cg.shared.global [%0], [%1], 16;" :: "r"(dst), "l"(src) : "memory");
}
#define CP_COMMIT  asm volatile("cp.async.commit_group;" ::: "memory")
#define CP_WAIT_1  asm volatile("cp.async.wait_group 1;" ::: "memory")
#define CP_WAIT_0  asm volatile("cp.async.wait_group 0;" ::: "memory")

// ---------------- smem layout (edge kernel) ----------------
// A-full: 4 chunks(k32) x [hi plane | lo plane], each plane 128 rows x 20 words(80B)
#define AF_OFF   0         // 4 * 20480 = 81920
#define BB_OFF   81920     // B double buffer: 2 x 16384
#define BIAS_OFF 114688    // b1,b2,bc1,Wc2 : 4*512
#define REL_OFF  116736
#define EA_OFF   118272
#define DSQ_OFF  119808
#define SRC_OFF  120320
#define DST_OFF  120832
#define PW_OFF   121344    // 2*128 floats
#define EDGE_SMEM 122368

// ---------------- zero / prep ----------------
__global__ void zero_kernel()
{
    int i = blockIdx.x * blockDim.x + threadIdx.x;
    if (i < N_NODES * H) g_agg_msg[i] = 0.0f;
    if (i < N_NODES * 4) g_agg_coord4[i] = 0.0f;
}

// W[K,128] -> bf16 hi/lo in exact mma B-fragment layout.
__global__ void prep_kernel(const float* __restrict__ W, int which, int Kact, int Kpad)
{
    int idx = blockIdx.x * blockDim.x + threadIdx.x;
    if (idx >= 128 * Kpad) return;
    int k = idx >> 7;
    int n = idx & 127;
    float v = (k < Kact) ? W[k * 128 + n] : 0.0f;
    float fhi = bf16rt(v);
    float flo = v - fhi;
    int chunk = k >> 5, ks = (k >> 4) & 1, reg = (k >> 3) & 1;
    int kr = k & 7, nf = n >> 3, lanep = ((n & 7) << 2) | (kr >> 1), half = k & 1;
    unsigned short* dst = (which == 0) ? g_W1b : (which == 1) ? g_W2b : g_Wc1b;
    int wi_hi = chunk * 4096 + ((ks * 2 + 0) * 16 + nf) * 64 + reg * 32 + lanep;
    int wi_lo = wi_hi + 1024;  // plane 1
    dst[wi_hi * 2 + half] = __bfloat16_as_ushort(__float2bfloat16(fhi));
    dst[wi_lo * 2 + half] = __bfloat16_as_ushort(__float2bfloat16(flo));
}

// ---------------- edge kernel pieces ----------------
__device__ __forceinline__ void init_d(float d[2][8][4], const float* sBias,
                                       int stage, int lane, int wc)
{
#pragma unroll
    for (int nf = 0; nf < 8; nf++) {
        int c0 = wc * 64 + nf * 8 + (lane & 3) * 2;
        float b0v = sBias[stage * 128 + c0];
        float b1v = sBias[stage * 128 + c0 + 1];
#pragma unroll
        for (int mf = 0; mf < 2; mf++) {
            d[mf][nf][0] = b0v; d[mf][nf][1] = b1v;
            d[mf][nf][2] = b0v; d[mf][nf][3] = b1v;
        }
    }
}

// prefetch B chunk cg (global schedule) into buf cg&1 via cp.async + commit
__device__ __forceinline__ void issueB(uint32_t sbase, int cg, int tid)
{
    int stage = (cg < 9) ? 0 : ((cg < 13) ? 1 : 2);
    int cin = cg - ((stage == 0) ? 0 : (stage == 1) ? 9 : 13);
    const unsigned short* gW = (stage == 0) ? g_W1b : (stage == 1) ? g_W2b : g_Wc1b;
    const uint4* bsrc = (const uint4*)gW + (size_t)cin * 1024;
    uint32_t bdst = sbase + BB_OFF + (uint32_t)(cg & 1) * 16384;
    int niter = (cg == 8) ? 2 : 4;  // tail chunk: only ks=0 planes (8KB)
#pragma unroll
    for (int i = 0; i < 4; i++) {
        if (i < niter)
            cp_async16(bdst + (uint32_t)(tid + i * 256) * 16, bsrc + tid + i * 256);
    }
    CP_COMMIT;
}

__device__ __forceinline__ void do_mma(uint32_t sbase, const uint32_t* bw,
                                       int slot, int lane, int wm, int wc,
                                       float d[2][8][4], int nks)
{
    uint32_t aBase = sbase + AF_OFF + (uint32_t)slot * 20480
                   + (uint32_t)(wm * 32 + (lane & 15)) * 80
                   + ((lane & 16) ? 16u : 0u);
#pragma unroll 2
    for (int ks = 0; ks < nks; ks++) {
        uint32_t aHi[2][4], aLo[2][4];
#pragma unroll
        for (int mf = 0; mf < 2; mf++) {
            uint32_t ad = aBase + mf * 1280 + ks * 32;
            ldm4(aHi[mf], ad);
            ldm4(aLo[mf], ad + 10240);
        }
#pragma unroll
        for (int nf = 0; nf < 8; nf++) {
            int nfg = wc * 8 + nf;
            int bi_hi = ((ks * 2 + 0) * 16 + nfg) * 64 + lane;
            int bi_lo = ((ks * 2 + 1) * 16 + nfg) * 64 + lane;
            uint32_t bh0 = bw[bi_hi], bh1 = bw[bi_hi + 32];
            uint32_t bl0 = bw[bi_lo], bl1 = bw[bi_lo + 32];
#pragma unroll
            for (int mf = 0; mf < 2; mf++) {
                mma_bf16(d[mf][nf], aHi[mf], bh0, bh1);
                mma_bf16(d[mf][nf], aHi[mf], bl0, bl1);
                mma_bf16(d[mf][nf], aLo[mf], bh0, bh1);
            }
        }
    }
}

// epilogue: silu(d) -> (STAGE 0/1: write A-full splits; STAGE 1: + red agg_msg;
//                       STAGE 2: dot Wc2 -> coord red)
template<int STAGE>
__device__ __forceinline__ void epilogue(char* sb, float d[2][8][4],
                                         const int* sDst, const float* sRel,
                                         const float* bc2, float* sPw,
                                         int tid, int lane, int wm, int wc)
{
    __syncthreads();  // all warps done reading A-full / B
    const float* sBias = (const float*)(sb + BIAS_OFF);
    float pw0[2] = {0.f, 0.f}, pw1[2] = {0.f, 0.f};
#pragma unroll
    for (int mf = 0; mf < 2; mf++) {
        int r0 = wm * 32 + mf * 16 + (lane >> 2);
        int r1 = r0 + 8;
#pragma unroll
        for (int nf = 0; nf < 8; nf++) {
            int c0 = wc * 64 + nf * 8 + (lane & 3) * 2;
            float v0 = silu_f(d[mf][nf][0]);
            float v1 = silu_f(d[mf][nf][1]);
            float v2 = silu_f(d[mf][nf][2]);
            float v3 = silu_f(d[mf][nf][3]);
            if (STAGE == 2) {
                float w0 = sBias[384 + c0], w1 = sBias[384 + c0 + 1];
                pw0[mf] += v0 * w0 + v1 * w1;
                pw1[mf] += v2 * w0 + v3 * w1;
            } else {
                if (STAGE == 1) {
                    redv2(&g_agg_msg[(size_t)sDst[r0] * H + c0], v0, v1);
                    redv2(&g_agg_msg[(size_t)sDst[r1] * H + c0], v2, v3);
                }
                int chunk = c0 >> 5;
                int wofs = (c0 & 31) >> 1;
                uint32_t* ph0 = (uint32_t*)(sb + AF_OFF + chunk * 20480 + r0 * 80) + wofs;
                uint32_t* ph1 = (uint32_t*)(sb + AF_OFF + chunk * 20480 + r1 * 80) + wofs;
                ph0[0]    = pack2bf(v0, v1);
                ph0[2560] = pack2bf(v0 - bf16rt(v0), v1 - bf16rt(v1));
                ph1[0]    = pack2bf(v2, v3);
                ph1[2560] = pack2bf(v2 - bf16rt(v2), v3 - bf16rt(v3));
            }
        }
    }
    if (STAGE == 2) {
#pragma unroll
        for (int o = 1; o < 4; o <<= 1) {
            pw0[0] += __shfl_xor_sync(0xffffffffu, pw0[0], o);
            pw0[1] += __shfl_xor_sync(0xffffffffu, pw0[1], o);
            pw1[0] += __shfl_xor_sync(0xffffffffu, pw1[0], o);
            pw1[1] += __shfl_xor_sync(0xffffffffu, pw1[1], o);
        }
        if ((lane & 3) == 0) {
            int r = wm * 32 + (lane >> 2);
            sPw[wc * 128 + r]      = pw0[0];
            sPw[wc * 128 + r + 8]  = pw1[0];
            sPw[wc * 128 + r + 16] = pw0[1];
            sPw[wc * 128 + r + 24] = pw1[1];
        }
        __syncthreads();
        if (tid < 128) {
            float w = sPw[tid] + sPw[128 + tid] + bc2[0];
            int dd = sDst[tid];
            redv4(&g_agg_coord4[(size_t)dd * 4],
                  sRel[tid * 3 + 0] * w, sRel[tid * 3 + 1] * w, sRel[tid * 3 + 2] * w, 1.0f);
        }
    }
}

__global__ __launch_bounds__(256, 1) void edge_kernel(
    const float* __restrict__ h,  const float* __restrict__ x,
    const int*   __restrict__ ei, const float* __restrict__ ea,
    const float* __restrict__ b1, const float* __restrict__ b2,
    const float* __restrict__ bc1, const float* __restrict__ Wc2,
    const float* __restrict__ bc2)
{
    extern __shared__ char sb[];
    uint32_t sbase = smem_u32(sb);
    int tid = threadIdx.x, lane = tid & 31, wid = tid >> 5;
    int wm = wid & 3, wc = wid >> 2;
    int ebase = blockIdx.x * 128;

    float* sBias = (float*)(sb + BIAS_OFF);
    float* sRel  = (float*)(sb + REL_OFF);
    float* sEa   = (float*)(sb + EA_OFF);
    float* sDsq  = (float*)(sb + DSQ_OFF);
    int*   sSrc  = (int*)(sb + SRC_OFF);
    int*   sDst  = (int*)(sb + DST_OFF);
    float* sPw   = (float*)(sb + PW_OFF);

    if (tid < 128) {
        sBias[tid]       = b1[tid];
        sBias[128 + tid] = b2[tid];
        sBias[256 + tid] = bc1[tid];
        sBias[384 + tid] = Wc2[tid];
        int e = ebase + tid;
        int s = ei[e];
        int dd = ei[N_EDGES + e];
        sSrc[tid] = s; sDst[tid] = dd;
        float rx = x[s * 3 + 0] - x[dd * 3 + 0];
        float ry = x[s * 3 + 1] - x[dd * 3 + 1];
        float rz = x[s * 3 + 2] - x[dd * 3 + 2];
        sRel[tid * 3 + 0] = rx; sRel[tid * 3 + 1] = ry; sRel[tid * 3 + 2] = rz;
        sDsq[tid] = rx * rx + ry * ry + rz * rz;
        sEa[tid * 3 + 0] = ea[e * 3 + 0];
        sEa[tid * 3 + 1] = ea[e * 3 + 1];
        sEa[tid * 3 + 2] = ea[e * 3 + 2];
    }
    __syncthreads();

    const float4* hv = (const float4*)h;
    float d[2][8][4];
    int row = tid >> 1, halfq = tid & 1;

    // ================= STAGE 0 : 9 chunks, pipelined =================
    init_d(d, sBias, 0, lane, wc);
    issueB(sbase, 0, tid);
    {   // build A(0) directly
        int node = sSrc[row];
        uint32_t* ph = (uint32_t*)(sb + AF_OFF + row * 80);
        uint32_t* pl = ph + 2560;
#pragma unroll
        for (int j = 0; j < 4; j++) {
            float4 v = hv[(size_t)node * 32 + halfq * 4 + j];
            int w0 = halfq * 8 + j * 2;
            ph[w0]     = pack2bf(v.x, v.y);
            ph[w0 + 1] = pack2bf(v.z, v.w);
            pl[w0]     = pack2bf(v.x - bf16rt(v.x), v.y - bf16rt(v.y));
            pl[w0 + 1] = pack2bf(v.z - bf16rt(v.z), v.w - bf16rt(v.w));
        }
    }
#pragma unroll 1
    for (int c = 0; c < 9; c++) {
        issueB(sbase, c + 1, tid);   // c+1 in [1,9]
        CP_WAIT_1;
        __syncthreads();
        // prefetch A gather for chunk c+1 (chunks 1..7)
        float4 av[4];
        bool pf = (c < 7);
        if (pf) {
            int cn = c + 1;
            int node = ((cn < 4) ? sSrc : sDst)[row];
            int cb = cn & 3;
#pragma unroll
            for (int j = 0; j < 4; j++)
                av[j] = hv[(size_t)node * 32 + cb * 8 + halfq * 4 + j];
        }
        do_mma(sbase, (const uint32_t*)(sb + BB_OFF + (c & 1) * 16384),
               c & 3, lane, wm, wc, d, (c == 8) ? 1 : 2);
        if (pf) {
            int cn = c + 1;
            uint32_t* ph = (uint32_t*)(sb + AF_OFF + (cn & 3) * 20480 + row * 80);
            uint32_t* pl = ph + 2560;
#pragma unroll
            for (int j = 0; j < 4; j++) {
                int w0 = halfq * 8 + j * 2;
                ph[w0]     = pack2bf(av[j].x, av[j].y);
                ph[w0 + 1] = pack2bf(av[j].z, av[j].w);
                pl[w0]     = pack2bf(av[j].x - bf16rt(av[j].x), av[j].y - bf16rt(av[j].y));
                pl[w0 + 1] = pack2bf(av[j].z - bf16rt(av[j].z), av[j].w - bf16rt(av[j].w));
            }
        } else if (c == 7) {
            // build tail chunk 8 (slot 0): [ea0,ea1,ea2,dsq, zeros] (only ks=0 used)
            uint32_t* ph = (uint32_t*)(sb + AF_OFF + row * 80);
            uint32_t* pl = ph + 2560;
            uint32_t* p = halfq ? pl : ph;
            if (halfq == 0) {
                p[0] = pack2bf(sEa[row * 3 + 0], sEa[row * 3 + 1]);
                p[1] = pack2bf(sEa[row * 3 + 2], sDsq[row]);
            } else {
                float e0 = sEa[row * 3 + 0], e1 = sEa[row * 3 + 1];
                float e2 = sEa[row * 3 + 2], dq = sDsq[row];
                p[0] = pack2bf(e0 - bf16rt(e0), e1 - bf16rt(e1));
                p[1] = pack2bf(e2 - bf16rt(e2), dq - bf16rt(dq));
            }
#pragma unroll
            for (int w = 2; w < 8; w++) p[w] = 0u;
        }
    }
    epilogue<0>(sb, d, sDst, sRel, bc2, sPw, tid, lane, wm, wc);

    // ================= STAGE 1 : chunks 9..12 (B(9) already in flight) =================
    init_d(d, sBias, 1, lane, wc);
#pragma unroll 1
    for (int c = 0; c < 4; c++) {
        int cg = 9 + c;
        issueB(sbase, cg + 1, tid);  // 10..13
        CP_WAIT_1;
        __syncthreads();
        do_mma(sbase, (const uint32_t*)(sb + BB_OFF + (cg & 1) * 16384),
               c, lane, wm, wc, d, 2);
    }
    epilogue<1>(sb, d, sDst, sRel, bc2, sPw, tid, lane, wm, wc);

    // ================= STAGE 2 : chunks 13..16 (B(13) already in flight) =================
    init_d(d, sBias, 2, lane, wc);
#pragma unroll 1
    for (int c = 0; c < 4; c++) {
        int cg = 13 + c;
        if (cg < 16) { issueB(sbase, cg + 1, tid); CP_WAIT_1; }
        else         { CP_WAIT_0; }
        __syncthreads();
        do_mma(sbase, (const uint32_t*)(sb + BB_OFF + (cg & 1) * 16384),
               c, lane, wm, wc, d, 2);
    }
    epilogue<2>(sb, d, sDst, sRel, bc2, sPw, tid, lane, wm, wc);
}

// ---------------- SIMT node kernel (64 nodes / block) ----------------
__device__ __forceinline__ void gemm128(const float* __restrict__ As,
                                        const float* __restrict__ Wg,
                                        float* sW, float acc[4][8],
                                        int tm, int tn, int tid)
{
    for (int kt = 0; kt < 128; kt += 16) {
        __syncthreads();
        const float4* Wv = (const float4*)(Wg + (size_t)kt * H);
        float4* sWv = (float4*)sW;
        sWv[tid]       = Wv[tid];
        sWv[tid + 256] = Wv[tid + 256];
        __syncthreads();
#pragma unroll
        for (int kk = 0; kk < 16; kk++) {
            float a[4];
#pragma unroll
            for (int m = 0; m < 4; m++) a[m] = As[(tm * 4 + m) * H + kt + kk];
            float4 w0 = *(const float4*)&sW[kk * H + tn * 8];
            float4 w1 = *(const float4*)&sW[kk * H + tn * 8 + 4];
#pragma unroll
            for (int m = 0; m < 4; m++) {
                acc[m][0] += a[m] * w0.x; acc[m][1] += a[m] * w0.y;
                acc[m][2] += a[m] * w0.z; acc[m][3] += a[m] * w0.w;
                acc[m][4] += a[m] * w1.x; acc[m][5] += a[m] * w1.y;
                acc[m][6] += a[m] * w1.z; acc[m][7] += a[m] * w1.w;
            }
        }
    }
}

__global__ __launch_bounds__(256, 2) void node_kernel(
    const float* __restrict__ h,   const float* __restrict__ x,
    const float* __restrict__ Wn1, const float* __restrict__ bn1,
    const float* __restrict__ Wn2, const float* __restrict__ bn2,
    const float* __restrict__ gamma, const float* __restrict__ beta,
    float* __restrict__ out_h, float* __restrict__ out_x)
{
    extern __shared__ float smem[];
    float* sA = smem;
    float* sB = sA + 64 * H;
    float* sW = sB + 64 * H;

    int tid = threadIdx.x;
    int tn = tid & 15;
    int tm = tid >> 4;
    int nbase = blockIdx.x * 64;

    {
        const float4* hv = (const float4*)h;
        const float4* av = (const float4*)g_agg_msg;
        float4* sA4 = (float4*)sA;
        float4* sB4 = (float4*)sB;
        float4 z = make_float4(0.f, 0.f, 0.f, 0.f);
#pragma unroll
        for (int j = 0; j < 8; j++) {
            int idx = tid + j * 256;
            int row = idx >> 5;
            int c4 = idx & 31;
            int node = nbase + row;
            if (node < N_NODES) {
                sA4[idx] = hv[(size_t)node * 32 + c4];
                sB4[idx] = av[(size_t)node * 32 + c4];
            } else { sA4[idx] = z; sB4[idx] = z; }
        }
    }

    float acc[4][8];
    {
        float4 b0 = *(const float4*)(bn1 + tn * 8);
        float4 b1v = *(const float4*)(bn1 + tn * 8 + 4);
#pragma unroll
        for (int m = 0; m < 4; m++) {
            acc[m][0] = b0.x; acc[m][1] = b0.y; acc[m][2] = b0.z; acc[m][3] = b0.w;
            acc[m][4] = b1v.x; acc[m][5] = b1v.y; acc[m][6] = b1v.z; acc[m][7] = b1v.w;
        }
    }
    gemm128(sA, Wn1, sW, acc, tm, tn, tid);
    gemm128(sB, Wn1 + 128 * H, sW, acc, tm, tn, tid);
#pragma unroll
    for (int m = 0; m < 4; m++)
#pragma unroll
        for (int n = 0; n < 8; n++)
            acc[m][n] = silu_f(acc[m][n]);
    __syncthreads();
#pragma unroll
    for (int m = 0; m < 4; m++) {
        int row = tm * 4 + m;
        *(float4*)&sB[row * H + tn * 8]     = make_float4(acc[m][0], acc[m][1], acc[m][2], acc[m][3]);
        *(float4*)&sB[row * H + tn * 8 + 4] = make_float4(acc[m][4], acc[m][5], acc[m][6], acc[m][7]);
    }

    {
        float4 b0 = *(const float4*)(bn2 + tn * 8);
        float4 b1v = *(const float4*)(bn2 + tn * 8 + 4);
#pragma unroll
        for (int m = 0; m < 4; m++) {
            acc[m][0] = b0.x; acc[m][1] = b0.y; acc[m][2] = b0.z; acc[m][3] = b0.w;
            acc[m][4] = b1v.x; acc[m][5] = b1v.y; acc[m][6] = b1v.z; acc[m][7] = b1v.w;
        }
    }
    gemm128(sB, Wn2, sW, acc, tm, tn, tid);

    __syncthreads();
#pragma unroll
    for (int m = 0; m < 4; m++) {
        int row = tm * 4 + m;
        float4 h0 = *(const float4*)&sA[row * H + tn * 8];
        float4 h1 = *(const float4*)&sA[row * H + tn * 8 + 4];
        *(float4*)&sB[row * H + tn * 8]     = make_float4(h0.x + acc[m][0], h0.y + acc[m][1], h0.z + acc[m][2], h0.w + acc[m][3]);
        *(float4*)&sB[row * H + tn * 8 + 4] = make_float4(h1.x + acc[m][4], h1.y + acc[m][5], h1.z + acc[m][6], h1.w + acc[m][7]);
    }
    __syncthreads();

    {
        int row = tid >> 2;
        int part = tid & 3;
        int node = nbase + row;
        const float4* yv = (const float4*)sB;
        float s = 0.f, sq = 0.f;
        float4 vals[8];
#pragma unroll
        for (int j = 0; j < 8; j++) {
            float4 v = yv[row * 32 + part * 8 + j];
            vals[j] = v;
            s  += v.x + v.y + v.z + v.w;
            sq += v.x * v.x + v.y * v.y + v.z * v.z + v.w * v.w;
        }
        s  += __shfl_xor_sync(0xffffffffu, s, 1);
        sq += __shfl_xor_sync(0xffffffffu, sq, 1);
        s  += __shfl_xor_sync(0xffffffffu, s, 2);
        sq += __shfl_xor_sync(0xffffffffu, sq, 2);
        float mu  = s * (1.0f / 128.0f);
        float var = sq * (1.0f / 128.0f) - mu * mu;
        float inv = rsqrtf(var + 1e-5f);
        if (node < N_NODES) {
            float4* ov = (float4*)(out_h + (size_t)node * H);
#pragma unroll
            for (int j = 0; j < 8; j++) {
                int c4 = part * 8 + j;
                float4 g = *(const float4*)(gamma + c4 * 4);
                float4 b = *(const float4*)(beta + c4 * 4);
                float4 v = vals[j];
                ov[c4] = make_float4((v.x - mu) * inv * g.x + b.x,
                                     (v.y - mu) * inv * g.y + b.y,
                                     (v.z - mu) * inv * g.z + b.z,
                                     (v.w - mu) * inv * g.w + b.w);
            }
        }
    }

    if (tid < 192) {
        int r = tid / 3, c = tid % 3;
        int node = nbase + r;
        if (node < N_NODES) {
            float cnt = fmaxf(g_agg_coord4[(size_t)node * 4 + 3], 1.0f);
            out_x[(size_t)node * 3 + c] = x[(size_t)node * 3 + c]
                                        + g_agg_coord4[(size_t)node * 4 + c] / cnt;
        }
    }
}

// ---------------------------------------------------------------------------
extern "C" void kernel_launch(void* const* d_in, const int* in_sizes, int n_in,
                              void* d_out, int out_size)
{
    const float* h    = (const float*)d_in[0];
    const float* x    = (const float*)d_in[1];
    const int*   eidx = (const int*)  d_in[2];
    const float* ea   = (const float*)d_in[3];
    const float* W1   = (const float*)d_in[4];
    const float* b1   = (const float*)d_in[5];
    const float* W2   = (const float*)d_in[6];
    const float* b2   = (const float*)d_in[7];
    const float* Wc1  = (const float*)d_in[8];
    const float* bc1  = (const float*)d_in[9];
    const float* Wc2  = (const float*)d_in[10];
    const float* bc2  = (const float*)d_in[11];
    const float* Wn1  = (const float*)d_in[12];
    const float* bn1  = (const float*)d_in[13];
    const float* Wn2  = (const float*)d_in[14];
    const float* bn2  = (const float*)d_in[15];
    const float* gamma = (const float*)d_in[16];
    const float* beta  = (const float*)d_in[17];

    float* out_h = (float*)d_out;
    float* out_x = out_h + (size_t)N_NODES * H;

    const int NODE_SMEM = (64 * H + 64 * H + 16 * H) * 4;
    cudaFuncSetAttribute(edge_kernel, cudaFuncAttributeMaxDynamicSharedMemorySize, EDGE_SMEM);
    cudaFuncSetAttribute(node_kernel, cudaFuncAttributeMaxDynamicSharedMemorySize, NODE_SMEM);

    zero_kernel<<<(N_NODES * H + 255) / 256, 256>>>();
    prep_kernel<<<(128 * 288 + 255) / 256, 256>>>(W1, 0, 260, 288);
    prep_kernel<<<(128 * 128 + 255) / 256, 256>>>(W2, 1, 128, 128);
    prep_kernel<<<(128 * 128 + 255) / 256, 256>>>(Wc1, 2, 128, 128);
    edge_kernel<<<N_EDGES / 128, 256, EDGE_SMEM>>>(h, x, eidx, ea, b1, b2, bc1, Wc2, bc2);
    node_kernel<<<(N_NODES + 63) / 64, 256, NODE_SMEM>>>(h, x, Wn1, bn1, Wn2, bn2,
                                                         gamma, beta, out_h, out_x);
}

// round 7
// speedup vs baseline: 3.2113x; 1.3758x over previous
#include <cuda_runtime.h>
#include <cuda_bf16.h>
#include <cstdint>

#define N_NODES 50000
#define N_EDGES 800000
#define H 128

// ---------------- device scratch ----------------
__device__ __align__(16) float g_agg_msg[(size_t)N_NODES * H];
__device__ __align__(16) float g_agg_coord4[(size_t)N_NODES * 4];  // x,y,z,count
// Weights in B-fragment layout, bf16 hi/lo planes, chunked by k32.
__device__ __align__(16) unsigned short g_W1b[9 * 4096 * 2];
__device__ __align__(16) unsigned short g_W2b[4 * 4096 * 2];
__device__ __align__(16) unsigned short g_Wc1b[4 * 4096 * 2];

// ---------------- helpers ----------------
__device__ __forceinline__ uint32_t smem_u32(const void* p) {
    uint32_t a;
    asm("{ .reg .u64 t; cvta.to.shared.u64 t, %1; cvt.u32.u64 %0, t; }" : "=r"(a) : "l"(p));
    return a;
}
__device__ __forceinline__ float bf16rt(float v) {
    return __bfloat162float(__float2bfloat16(v));
}
__device__ __forceinline__ uint32_t pack2bf(float a, float b) {
    unsigned short ua = __bfloat16_as_ushort(__float2bfloat16(a));
    unsigned short ub = __bfloat16_as_ushort(__float2bfloat16(b));
    return (uint32_t)ua | ((uint32_t)ub << 16);
}
__device__ __forceinline__ float silu_f(float v) {
    return v * (1.0f / (1.0f + __expf(-v)));
}
__device__ __forceinline__ void redv2(float* p, float a, float b) {
    asm volatile("red.global.add.v2.f32 [%0], {%1, %2};" :: "l"(p), "f"(a), "f"(b) : "memory");
}
__device__ __forceinline__ void redv4(float* p, float a, float b, float c, float d) {
    asm volatile("red.global.add.v4.f32 [%0], {%1, %2, %3, %4};"
                 :: "l"(p), "f"(a), "f"(b), "f"(c), "f"(d) : "memory");
}
__device__ __forceinline__ void ldm4(uint32_t* r, uint32_t addr) {
    asm volatile("ldmatrix.sync.aligned.m8n8.x4.shared.b16 {%0,%1,%2,%3}, [%4];"
                 : "=r"(r[0]), "=r"(r[1]), "=r"(r[2]), "=r"(r[3]) : "r"(addr));
}
__device__ __forceinline__ void mma_bf16(float* d, const uint32_t* a, uint32_t b0, uint32_t b1) {
    asm volatile("mma.sync.aligned.m16n8k16.row.col.f32.bf16.bf16.f32 "
                 "{%0,%1,%2,%3}, {%4,%5,%6,%7}, {%8,%9}, {%0,%1,%2,%3};"
                 : "+f"(d[0]), "+f"(d[1]), "+f"(d[2]), "+f"(d[3])
                 : "r"(a[0]), "r"(a[1]), "r"(a[2]), "r"(a[3]), "r"(b0), "r"(b1));
}
__device__ __forceinline__ void cp_async16(uint32_t dst, const void* src) {
    asm volatile("cp.async.cg.shared.global [%0], [%1], 16;" :: "r"(dst), "l"(src) : "memory");
}
#define CP_COMMIT  asm volatile("cp.async.commit_group;" ::: "memory")
#define CP_WAIT_0  asm volatile("cp.async.wait_group 0;" ::: "memory")

// A-plane XOR swizzle: 64B row stride, 16B groups permuted by g ^= (row>>1)&3.
__device__ __forceinline__ uint32_t aswz(int row, int byteInRow) {
    int g = byteInRow >> 4;
    int inner = byteInRow & 15;
    return (uint32_t)(row * 64 + (((g ^ ((row >> 1) & 3)) << 4) | inner));
}

// ---------------- smem layout (edge kernel) ----------------
// A-full: 4 chunks(k32) x [hi plane 8192 | lo plane 8192] = 65536
#define AF_OFF   0
#define BB_OFF   65536     // B double buffer: 2 x 16384
#define BIAS_OFF 98304     // b1,b2,bc1,Wc2 : 4*512
#define REL_OFF  100352
#define EA_OFF   101888
#define DSQ_OFF  103424
#define SRC_OFF  103936
#define DST_OFF  104448
#define PW_OFF   104960    // 2*128 floats
#define EDGE_SMEM 105984   // ~103.5 KB -> 2 CTAs/SM

// ---------------- zero / prep ----------------
__global__ void zero_kernel()
{
    int i = blockIdx.x * blockDim.x + threadIdx.x;
    if (i < N_NODES * H) g_agg_msg[i] = 0.0f;
    if (i < N_NODES * 4) g_agg_coord4[i] = 0.0f;
}

// W[K,128] -> bf16 hi/lo in exact mma B-fragment layout.
__global__ void prep_kernel(const float* __restrict__ W, int which, int Kact, int Kpad)
{
    int idx = blockIdx.x * blockDim.x + threadIdx.x;
    if (idx >= 128 * Kpad) return;
    int k = idx >> 7;
    int n = idx & 127;
    float v = (k < Kact) ? W[k * 128 + n] : 0.0f;
    float fhi = bf16rt(v);
    float flo = v - fhi;
    int chunk = k >> 5, ks = (k >> 4) & 1, reg = (k >> 3) & 1;
    int kr = k & 7, nf = n >> 3, lanep = ((n & 7) << 2) | (kr >> 1), half = k & 1;
    unsigned short* dst = (which == 0) ? g_W1b : (which == 1) ? g_W2b : g_Wc1b;
    int wi_hi = chunk * 4096 + ((ks * 2 + 0) * 16 + nf) * 64 + reg * 32 + lanep;
    int wi_lo = wi_hi + 1024;  // plane 1
    dst[wi_hi * 2 + half] = __bfloat16_as_ushort(__float2bfloat16(fhi));
    dst[wi_lo * 2 + half] = __bfloat16_as_ushort(__float2bfloat16(flo));
}

// ---------------- edge kernel pieces ----------------
__device__ __forceinline__ void init_d(float d[2][8][4], const float* sBias,
                                       int stage, int lane, int wc)
{
#pragma unroll
    for (int nf = 0; nf < 8; nf++) {
        int c0 = wc * 64 + nf * 8 + (lane & 3) * 2;
        float b0v = sBias[stage * 128 + c0];
        float b1v = sBias[stage * 128 + c0 + 1];
#pragma unroll
        for (int mf = 0; mf < 2; mf++) {
            d[mf][nf][0] = b0v; d[mf][nf][1] = b1v;
            d[mf][nf][2] = b0v; d[mf][nf][3] = b1v;
        }
    }
}

// prefetch B chunk cg (global schedule) into buf cg&1 via cp.async + commit
__device__ __forceinline__ void issueB(uint32_t sbase, int cg, int tid)
{
    int stage = (cg < 9) ? 0 : ((cg < 13) ? 1 : 2);
    int cin = cg - ((stage == 0) ? 0 : (stage == 1) ? 9 : 13);
    const unsigned short* gW = (stage == 0) ? g_W1b : (stage == 1) ? g_W2b : g_Wc1b;
    const uint4* bsrc = (const uint4*)gW + (size_t)cin * 1024;
    uint32_t bdst = sbase + BB_OFF + (uint32_t)(cg & 1) * 16384;
    int niter = (cg == 8) ? 2 : 4;  // tail chunk: only ks=0 planes (8KB)
#pragma unroll
    for (int i = 0; i < 4; i++) {
        if (i < niter)
            cp_async16(bdst + (uint32_t)(tid + i * 256) * 16, bsrc + tid + i * 256);
    }
    CP_COMMIT;
}

__device__ __forceinline__ void do_mma(uint32_t sbase, const uint32_t* bw,
                                       int slot, int lane, int wm, int wc,
                                       float d[2][8][4], int nks)
{
    uint32_t chunkBase = sbase + AF_OFF + (uint32_t)slot * 16384;
#pragma unroll 2
    for (int ks = 0; ks < nks; ks++) {
        int kbyte = ks * 32 + ((lane & 16) ? 16 : 0);
        uint32_t aHi[2][4], aLo[2][4];
#pragma unroll
        for (int mf = 0; mf < 2; mf++) {
            int row = wm * 32 + mf * 16 + (lane & 15);
            uint32_t ad = chunkBase + aswz(row, kbyte);
            ldm4(aHi[mf], ad);
            ldm4(aLo[mf], ad + 8192);
        }
#pragma unroll
        for (int nf = 0; nf < 8; nf++) {
            int nfg = wc * 8 + nf;
            int bi_hi = ((ks * 2 + 0) * 16 + nfg) * 64 + lane;
            int bi_lo = ((ks * 2 + 1) * 16 + nfg) * 64 + lane;
            uint32_t bh0 = bw[bi_hi], bh1 = bw[bi_hi + 32];
            uint32_t bl0 = bw[bi_lo], bl1 = bw[bi_lo + 32];
#pragma unroll
            for (int mf = 0; mf < 2; mf++) {
                mma_bf16(d[mf][nf], aHi[mf], bh0, bh1);
                mma_bf16(d[mf][nf], aHi[mf], bl0, bl1);
                mma_bf16(d[mf][nf], aLo[mf], bh0, bh1);
            }
        }
    }
}

// write one k32 A-chunk row from 8 floats (two 16B halves per thread pair)
__device__ __forceinline__ void writeA(char* sb, int slot, int row, int halfq,
                                       const float4* v /*4 float4s*/)
{
    char* chunkBase = sb + AF_OFF + slot * 16384;
#pragma unroll
    for (int j = 0; j < 2; j++) {
        int byte0 = (halfq * 8 + j * 4) * 4;  // 16B group
        uint32_t off = aswz(row, byte0);
        uint32_t* ph = (uint32_t*)(chunkBase + off);
        uint32_t* pl = (uint32_t*)(chunkBase + 8192 + off);
        float4 a = v[j * 2], b = v[j * 2 + 1];
        ph[0] = pack2bf(a.x, a.y); ph[1] = pack2bf(a.z, a.w);
        pl[0] = pack2bf(a.x - bf16rt(a.x), a.y - bf16rt(a.y));
        pl[1] = pack2bf(a.z - bf16rt(a.z), a.w - bf16rt(a.w));
        ph[2] = pack2bf(b.x, b.y); ph[3] = pack2bf(b.z, b.w);
        pl[2] = pack2bf(b.x - bf16rt(b.x), b.y - bf16rt(b.y));
        pl[3] = pack2bf(b.z - bf16rt(b.z), b.w - bf16rt(b.w));
    }
}

// epilogue: silu(d) -> (STAGE 0/1: write A-full splits; STAGE 1: + red agg_msg;
//                       STAGE 2: dot Wc2 -> coord red)
template<int STAGE>
__device__ __forceinline__ void epilogue(char* sb, float d[2][8][4],
                                         const int* sDst, const float* sRel,
                                         const float* bc2, float* sPw,
                                         int tid, int lane, int wm, int wc)
{
    __syncthreads();  // all warps done reading A-full / B
    const float* sBias = (const float*)(sb + BIAS_OFF);
    float pw0[2] = {0.f, 0.f}, pw1[2] = {0.f, 0.f};
#pragma unroll
    for (int mf = 0; mf < 2; mf++) {
        int r0 = wm * 32 + mf * 16 + (lane >> 2);
        int r1 = r0 + 8;
#pragma unroll
        for (int nf = 0; nf < 8; nf++) {
            int c0 = wc * 64 + nf * 8 + (lane & 3) * 2;
            float v0 = silu_f(d[mf][nf][0]);
            float v1 = silu_f(d[mf][nf][1]);
            float v2 = silu_f(d[mf][nf][2]);
            float v3 = silu_f(d[mf][nf][3]);
            if (STAGE == 2) {
                float w0 = sBias[384 + c0], w1 = sBias[384 + c0 + 1];
                pw0[mf] += v0 * w0 + v1 * w1;
                pw1[mf] += v2 * w0 + v3 * w1;
            } else {
                if (STAGE == 1) {
                    redv2(&g_agg_msg[(size_t)sDst[r0] * H + c0], v0, v1);
                    redv2(&g_agg_msg[(size_t)sDst[r1] * H + c0], v2, v3);
                }
                int chunk = c0 >> 5;
                int byte0 = (c0 & 31) * 2;
                char* chunkBase = sb + AF_OFF + chunk * 16384;
                uint32_t o0 = aswz(r0, byte0);
                uint32_t o1 = aswz(r1, byte0);
                *(uint32_t*)(chunkBase + o0)        = pack2bf(v0, v1);
                *(uint32_t*)(chunkBase + 8192 + o0) = pack2bf(v0 - bf16rt(v0), v1 - bf16rt(v1));
                *(uint32_t*)(chunkBase + o1)        = pack2bf(v2, v3);
                *(uint32_t*)(chunkBase + 8192 + o1) = pack2bf(v2 - bf16rt(v2), v3 - bf16rt(v3));
            }
        }
    }
    if (STAGE == 2) {
#pragma unroll
        for (int o = 1; o < 4; o <<= 1) {
            pw0[0] += __shfl_xor_sync(0xffffffffu, pw0[0], o);
            pw0[1] += __shfl_xor_sync(0xffffffffu, pw0[1], o);
            pw1[0] += __shfl_xor_sync(0xffffffffu, pw1[0], o);
            pw1[1] += __shfl_xor_sync(0xffffffffu, pw1[1], o);
        }
        if ((lane & 3) == 0) {
            int r = wm * 32 + (lane >> 2);
            sPw[wc * 128 + r]      = pw0[0];
            sPw[wc * 128 + r + 8]  = pw1[0];
            sPw[wc * 128 + r + 16] = pw0[1];
            sPw[wc * 128 + r + 24] = pw1[1];
        }
        __syncthreads();
        if (tid < 128) {
            float w = sPw[tid] + sPw[128 + tid] + bc2[0];
            int dd = sDst[tid];
            redv4(&g_agg_coord4[(size_t)dd * 4],
                  sRel[tid * 3 + 0] * w, sRel[tid * 3 + 1] * w, sRel[tid * 3 + 2] * w, 1.0f);
        }
    }
}

__global__ __launch_bounds__(256, 2) void edge_kernel(
    const float* __restrict__ h,  const float* __restrict__ x,
    const int*   __restrict__ ei, const float* __restrict__ ea,
    const float* __restrict__ b1, const float* __restrict__ b2,
    const float* __restrict__ bc1, const float* __restrict__ Wc2,
    const float* __restrict__ bc2)
{
    extern __shared__ char sb[];
    uint32_t sbase = smem_u32(sb);
    int tid = threadIdx.x, lane = tid & 31, wid = tid >> 5;
    int wm = wid & 3, wc = wid >> 2;
    int ebase = blockIdx.x * 128;

    float* sBias = (float*)(sb + BIAS_OFF);
    float* sRel  = (float*)(sb + REL_OFF);
    float* sEa   = (float*)(sb + EA_OFF);
    float* sDsq  = (float*)(sb + DSQ_OFF);
    int*   sSrc  = (int*)(sb + SRC_OFF);
    int*   sDst  = (int*)(sb + DST_OFF);
    float* sPw   = (float*)(sb + PW_OFF);

    if (tid < 128) {
        sBias[tid]       = b1[tid];
        sBias[128 + tid] = b2[tid];
        sBias[256 + tid] = bc1[tid];
        sBias[384 + tid] = Wc2[tid];
        int e = ebase + tid;
        int s = ei[e];
        int dd = ei[N_EDGES + e];
        sSrc[tid] = s; sDst[tid] = dd;
        float rx = x[s * 3 + 0] - x[dd * 3 + 0];
        float ry = x[s * 3 + 1] - x[dd * 3 + 1];
        float rz = x[s * 3 + 2] - x[dd * 3 + 2];
        sRel[tid * 3 + 0] = rx; sRel[tid * 3 + 1] = ry; sRel[tid * 3 + 2] = rz;
        sDsq[tid] = rx * rx + ry * ry + rz * rz;
        sEa[tid * 3 + 0] = ea[e * 3 + 0];
        sEa[tid * 3 + 1] = ea[e * 3 + 1];
        sEa[tid * 3 + 2] = ea[e * 3 + 2];
    }
    __syncthreads();

    const float4* hv = (const float4*)h;
    float d[2][8][4];
    int row = tid >> 1, halfq = tid & 1;

    // ================= STAGE 0 : 9 chunks, race-free pipeline =================
    init_d(d, sBias, 0, lane, wc);
    issueB(sbase, 0, tid);
    {   // build A(0) directly
        int node = sSrc[row];
        float4 av[4];
#pragma unroll
        for (int j = 0; j < 4; j++) av[j] = hv[(size_t)node * 32 + halfq * 4 + j];
        writeA(sb, 0, row, halfq, av);
    }
#pragma unroll 1
    for (int c = 0; c < 9; c++) {
        CP_WAIT_0;            // own copies of chunk c complete
        __syncthreads();      // publish B(c)+A(c); prior readers of buf (c+1)&1 done
        // A gather prefetch for chunk c+1 (chunks 1..7)
        float4 av[4];
        bool pf = (c < 7);
        if (pf) {
            int cn = c + 1;
            int node = ((cn < 4) ? sSrc : sDst)[row];
            int cb = cn & 3;
#pragma unroll
            for (int j = 0; j < 4; j++)
                av[j] = hv[(size_t)node * 32 + cb * 8 + halfq * 4 + j];
        }
        issueB(sbase, c + 1, tid);   // safe: after barrier (c+1 in [1,9])
        do_mma(sbase, (const uint32_t*)(sb + BB_OFF + (c & 1) * 16384),
               c & 3, lane, wm, wc, d, (c == 8) ? 1 : 2);
        if (pf) {
            writeA(sb, (c + 1) & 3, row, halfq, av);
        } else if (c == 7) {
            // build tail chunk 8 (slot 0): [ea0,ea1,ea2,dsq, zeros] (only ks=0 used)
            char* chunkBase = sb + AF_OFF;
            char* base = chunkBase + (halfq ? 8192 : 0);   // halfq 0 -> hi, 1 -> lo
            uint32_t o0 = aswz(row, 0);
            uint32_t* p0 = (uint32_t*)(base + o0);
            if (halfq == 0) {
                p0[0] = pack2bf(sEa[row * 3 + 0], sEa[row * 3 + 1]);
                p0[1] = pack2bf(sEa[row * 3 + 2], sDsq[row]);
            } else {
                float e0 = sEa[row * 3 + 0], e1 = sEa[row * 3 + 1];
                float e2 = sEa[row * 3 + 2], dq = sDsq[row];
                p0[0] = pack2bf(e0 - bf16rt(e0), e1 - bf16rt(e1));
                p0[1] = pack2bf(e2 - bf16rt(e2), dq - bf16rt(dq));
            }
            p0[2] = 0u; p0[3] = 0u;
            uint32_t* p1 = (uint32_t*)(base + aswz(row, 16));
            p1[0] = 0u; p1[1] = 0u; p1[2] = 0u; p1[3] = 0u;
        }
    }
    epilogue<0>(sb, d, sDst, sRel, bc2, sPw, tid, lane, wm, wc);

    // ================= STAGE 1 : chunks 9..12 (B(9) already in flight) =================
    init_d(d, sBias, 1, lane, wc);
#pragma unroll 1
    for (int c = 0; c < 4; c++) {
        int cg = 9 + c;
        CP_WAIT_0;
        __syncthreads();
        issueB(sbase, cg + 1, tid);  // 10..13
        do_mma(sbase, (const uint32_t*)(sb + BB_OFF + (cg & 1) * 16384),
               c, lane, wm, wc, d, 2);
    }
    epilogue<1>(sb, d, sDst, sRel, bc2, sPw, tid, lane, wm, wc);

    // ================= STAGE 2 : chunks 13..16 (B(13) already in flight) =================
    init_d(d, sBias, 2, lane, wc);
#pragma unroll 1
    for (int c = 0; c < 4; c++) {
        int cg = 13 + c;
        CP_WAIT_0;
        __syncthreads();
        if (cg < 16) issueB(sbase, cg + 1, tid);
        do_mma(sbase, (const uint32_t*)(sb + BB_OFF + (cg & 1) * 16384),
               c, lane, wm, wc, d, 2);
    }
    epilogue<2>(sb, d, sDst, sRel, bc2, sPw, tid, lane, wm, wc);
}

// ---------------- SIMT node kernel (64 nodes / block) ----------------
__device__ __forceinline__ void gemm128(const float* __restrict__ As,
                                        const float* __restrict__ Wg,
                                        float* sW, float acc[4][8],
                                        int tm, int tn, int tid)
{
    for (int kt = 0; kt < 128; kt += 16) {
        __syncthreads();
        const float4* Wv = (const float4*)(Wg + (size_t)kt * H);
        float4* sWv = (float4*)sW;
        sWv[tid]       = Wv[tid];
        sWv[tid + 256] = Wv[tid + 256];
        __syncthreads();
#pragma unroll
        for (int kk = 0; kk < 16; kk++) {
            float a[4];
#pragma unroll
            for (int m = 0; m < 4; m++) a[m] = As[(tm * 4 + m) * H + kt + kk];
            float4 w0 = *(const float4*)&sW[kk * H + tn * 8];
            float4 w1 = *(const float4*)&sW[kk * H + tn * 8 + 4];
#pragma unroll
            for (int m = 0; m < 4; m++) {
                acc[m][0] += a[m] * w0.x; acc[m][1] += a[m] * w0.y;
                acc[m][2] += a[m] * w0.z; acc[m][3] += a[m] * w0.w;
                acc[m][4] += a[m] * w1.x; acc[m][5] += a[m] * w1.y;
                acc[m][6] += a[m] * w1.z; acc[m][7] += a[m] * w1.w;
            }
        }
    }
}

__global__ __launch_bounds__(256, 2) void node_kernel(
    const float* __restrict__ h,   const float* __restrict__ x,
    const float* __restrict__ Wn1, const float* __restrict__ bn1,
    const float* __restrict__ Wn2, const float* __restrict__ bn2,
    const float* __restrict__ gamma, const float* __restrict__ beta,
    float* __restrict__ out_h, float* __restrict__ out_x)
{
    extern __shared__ float smem[];
    float* sA = smem;
    float* sB = sA + 64 * H;
    float* sW = sB + 64 * H;

    int tid = threadIdx.x;
    int tn = tid & 15;
    int tm = tid >> 4;
    int nbase = blockIdx.x * 64;

    {
        const float4* hv = (const float4*)h;
        const float4* av = (const float4*)g_agg_msg;
        float4* sA4 = (float4*)sA;
        float4* sB4 = (float4*)sB;
        float4 z = make_float4(0.f, 0.f, 0.f, 0.f);
#pragma unroll
        for (int j = 0; j < 8; j++) {
            int idx = tid + j * 256;
            int row = idx >> 5;
            int c4 = idx & 31;
            int node = nbase + row;
            if (node < N_NODES) {
                sA4[idx] = hv[(size_t)node * 32 + c4];
                sB4[idx] = av[(size_t)node * 32 + c4];
            } else { sA4[idx] = z; sB4[idx] = z; }
        }
    }

    float acc[4][8];
    {
        float4 b0 = *(const float4*)(bn1 + tn * 8);
        float4 b1v = *(const float4*)(bn1 + tn * 8 + 4);
#pragma unroll
        for (int m = 0; m < 4; m++) {
            acc[m][0] = b0.x; acc[m][1] = b0.y; acc[m][2] = b0.z; acc[m][3] = b0.w;
            acc[m][4] = b1v.x; acc[m][5] = b1v.y; acc[m][6] = b1v.z; acc[m][7] = b1v.w;
        }
    }
    gemm128(sA, Wn1, sW, acc, tm, tn, tid);
    gemm128(sB, Wn1 + 128 * H, sW, acc, tm, tn, tid);
#pragma unroll
    for (int m = 0; m < 4; m++)
#pragma unroll
        for (int n = 0; n < 8; n++)
            acc[m][n] = silu_f(acc[m][n]);
    __syncthreads();
#pragma unroll
    for (int m = 0; m < 4; m++) {
        int row = tm * 4 + m;
        *(float4*)&sB[row * H + tn * 8]     = make_float4(acc[m][0], acc[m][1], acc[m][2], acc[m][3]);
        *(float4*)&sB[row * H + tn * 8 + 4] = make_float4(acc[m][4], acc[m][5], acc[m][6], acc[m][7]);
    }

    {
        float4 b0 = *(const float4*)(bn2 + tn * 8);
        float4 b1v = *(const float4*)(bn2 + tn * 8 + 4);
#pragma unroll
        for (int m = 0; m < 4; m++) {
            acc[m][0] = b0.x; acc[m][1] = b0.y; acc[m][2] = b0.z; acc[m][3] = b0.w;
            acc[m][4] = b1v.x; acc[m][5] = b1v.y; acc[m][6] = b1v.z; acc[m][7] = b1v.w;
        }
    }
    gemm128(sB, Wn2, sW, acc, tm, tn, tid);

    __syncthreads();
#pragma unroll
    for (int m = 0; m < 4; m++) {
        int row = tm * 4 + m;
        float4 h0 = *(const float4*)&sA[row * H + tn * 8];
        float4 h1 = *(const float4*)&sA[row * H + tn * 8 + 4];
        *(float4*)&sB[row * H + tn * 8]     = make_float4(h0.x + acc[m][0], h0.y + acc[m][1], h0.z + acc[m][2], h0.w + acc[m][3]);
        *(float4*)&sB[row * H + tn * 8 + 4] = make_float4(h1.x + acc[m][4], h1.y + acc[m][5], h1.z + acc[m][6], h1.w + acc[m][7]);
    }
    __syncthreads();

    {
        int row = tid >> 2;
        int part = tid & 3;
        int node = nbase + row;
        const float4* yv = (const float4*)sB;
        float s = 0.f, sq = 0.f;
        float4 vals[8];
#pragma unroll
        for (int j = 0; j < 8; j++) {
            float4 v = yv[row * 32 + part * 8 + j];
            vals[j] = v;
            s  += v.x + v.y + v.z + v.w;
            sq += v.x * v.x + v.y * v.y + v.z * v.z + v.w * v.w;
        }
        s  += __shfl_xor_sync(0xffffffffu, s, 1);
        sq += __shfl_xor_sync(0xffffffffu, sq, 1);
        s  += __shfl_xor_sync(0xffffffffu, s, 2);
        sq += __shfl_xor_sync(0xffffffffu, sq, 2);
        float mu  = s * (1.0f / 128.0f);
        float var = sq * (1.0f / 128.0f) - mu * mu;
        float inv = rsqrtf(var + 1e-5f);
        if (node < N_NODES) {
            float4* ov = (float4*)(out_h + (size_t)node * H);
#pragma unroll
            for (int j = 0; j < 8; j++) {
                int c4 = part * 8 + j;
                float4 g = *(const float4*)(gamma + c4 * 4);
                float4 b = *(const float4*)(beta + c4 * 4);
                float4 v = vals[j];
                ov[c4] = make_float4((v.x - mu) * inv * g.x + b.x,
                                     (v.y - mu) * inv * g.y + b.y,
                                     (v.z - mu) * inv * g.z + b.z,
                                     (v.w - mu) * inv * g.w + b.w);
            }
        }
    }

    if (tid < 192) {
        int r = tid / 3, c = tid % 3;
        int node = nbase + r;
        if (node < N_NODES) {
            float cnt = fmaxf(g_agg_coord4[(size_t)node * 4 + 3], 1.0f);
            out_x[(size_t)node * 3 + c] = x[(size_t)node * 3 + c]
                                        + g_agg_coord4[(size_t)node * 4 + c] / cnt;
        }
    }
}

// ---------------------------------------------------------------------------
extern "C" void kernel_launch(void* const* d_in, const int* in_sizes, int n_in,
                              void* d_out, int out_size)
{
    const float* h    = (const float*)d_in[0];
    const float* x    = (const float*)d_in[1];
    const int*   eidx = (const int*)  d_in[2];
    const float* ea   = (const float*)d_in[3];
    const float* W1   = (const float*)d_in[4];
    const float* b1   = (const float*)d_in[5];
    const float* W2   = (const float*)d_in[6];
    const float* b2   = (const float*)d_in[7];
    const float* Wc1  = (const float*)d_in[8];
    const float* bc1  = (const float*)d_in[9];
    const float* Wc2  = (const float*)d_in[10];
    const float* bc2  = (const float*)d_in[11];
    const float* Wn1  = (const float*)d_in[12];
    const float* bn1  = (const float*)d_in[13];
    const float* Wn2  = (const float*)d_in[14];
    const float* bn2  = (const float*)d_in[15];
    const float* gamma = (const float*)d_in[16];
    const float* beta  = (const float*)d_in[17];

    float* out_h = (float*)d_out;
    float* out_x = out_h + (size_t)N_NODES * H;

    const int NODE_SMEM = (64 * H + 64 * H + 16 * H) * 4;
    cudaFuncSetAttribute(edge_kernel, cudaFuncAttributeMaxDynamicSharedMemorySize, EDGE_SMEM);
    cudaFuncSetAttribute(node_kernel, cudaFuncAttributeMaxDynamicSharedMemorySize, NODE_SMEM);

    zero_kernel<<<(N_NODES * H + 255) / 256, 256>>>();
    prep_kernel<<<(128 * 288 + 255) / 256, 256>>>(W1, 0, 260, 288);
    prep_kernel<<<(128 * 128 + 255) / 256, 256>>>(W2, 1, 128, 128);
    prep_kernel<<<(128 * 128 + 255) / 256, 256>>>(Wc1, 2, 128, 128);
    edge_kernel<<<N_EDGES / 128, 256, EDGE_SMEM>>>(h, x, eidx, ea, b1, b2, bc1, Wc2, bc2);
    node_kernel<<<(N_NODES + 63) / 64, 256, NODE_SMEM>>>(h, x, Wn1, bn1, Wn2, bn2,
                                                         gamma, beta, out_h, out_x);
}

// round 8
// speedup vs baseline: 3.2373x; 1.0081x over previous
#include <cuda_runtime.h>
#include <cuda_bf16.h>
#include <cstdint>

#define N_NODES 50000
#define N_EDGES 800000
#define H 128

// ---------------- device scratch ----------------
__device__ __align__(16) float g_agg_msg[(size_t)N_NODES * H];
__device__ __align__(16) float g_agg_coord4[(size_t)N_NODES * 4];  // x,y,z,count
// Weights as 8x8 b16 ldmatrix tiles, hi/lo planes, chunked by k32 (8192 ushorts/chunk).
__device__ __align__(16) unsigned short g_W1b[9 * 8192];
__device__ __align__(16) unsigned short g_W2b[4 * 8192];
__device__ __align__(16) unsigned short g_Wc1b[4 * 8192];
// h pre-split into bf16 hi/lo 16B groups: [node][chunk(4)][plane(2)][group(4)] uint4
__device__ __align__(16) uint4 g_hbf[(size_t)N_NODES * 32];

// ---------------- helpers ----------------
__device__ __forceinline__ uint32_t smem_u32(const void* p) {
    uint32_t a;
    asm("{ .reg .u64 t; cvta.to.shared.u64 t, %1; cvt.u32.u64 %0, t; }" : "=r"(a) : "l"(p));
    return a;
}
__device__ __forceinline__ float bf16rt(float v) {
    return __bfloat162float(__float2bfloat16(v));
}
__device__ __forceinline__ uint32_t pack2bf(float a, float b) {
    unsigned short ua = __bfloat16_as_ushort(__float2bfloat16(a));
    unsigned short ub = __bfloat16_as_ushort(__float2bfloat16(b));
    return (uint32_t)ua | ((uint32_t)ub << 16);
}
__device__ __forceinline__ float silu_f(float v) {
    return v * (1.0f / (1.0f + __expf(-v)));
}
__device__ __forceinline__ void redv2(float* p, float a, float b) {
    asm volatile("red.global.add.v2.f32 [%0], {%1, %2};" :: "l"(p), "f"(a), "f"(b) : "memory");
}
__device__ __forceinline__ void redv4(float* p, float a, float b, float c, float d) {
    asm volatile("red.global.add.v4.f32 [%0], {%1, %2, %3, %4};"
                 :: "l"(p), "f"(a), "f"(b), "f"(c), "f"(d) : "memory");
}
__device__ __forceinline__ void ldm4(uint32_t* r, uint32_t addr) {
    asm volatile("ldmatrix.sync.aligned.m8n8.x4.shared.b16 {%0,%1,%2,%3}, [%4];"
                 : "=r"(r[0]), "=r"(r[1]), "=r"(r[2]), "=r"(r[3]) : "r"(addr));
}
__device__ __forceinline__ void mma_bf16(float* d, const uint32_t* a, uint32_t b0, uint32_t b1) {
    asm volatile("mma.sync.aligned.m16n8k16.row.col.f32.bf16.bf16.f32 "
                 "{%0,%1,%2,%3}, {%4,%5,%6,%7}, {%8,%9}, {%0,%1,%2,%3};"
                 : "+f"(d[0]), "+f"(d[1]), "+f"(d[2]), "+f"(d[3])
                 : "r"(a[0]), "r"(a[1]), "r"(a[2]), "r"(a[3]), "r"(b0), "r"(b1));
}
__device__ __forceinline__ void cp_async16(uint32_t dst, const void* src) {
    asm volatile("cp.async.cg.shared.global [%0], [%1], 16;" :: "r"(dst), "l"(src) : "memory");
}
#define CP_COMMIT  asm volatile("cp.async.commit_group;" ::: "memory")
#define CP_WAIT_0  asm volatile("cp.async.wait_group 0;" ::: "memory")

// A-plane XOR swizzle: 64B row stride, 16B groups permuted by g ^= (row>>1)&3.
__device__ __forceinline__ uint32_t aswz(int row, int byteInRow) {
    int g = byteInRow >> 4;
    int inner = byteInRow & 15;
    return (uint32_t)(row * 64 + (((g ^ ((row >> 1) & 3)) << 4) | inner));
}

// ---------------- smem layout (edge kernel) ----------------
#define AF_OFF   0         // 4 chunks x [hi 8192 | lo 8192] = 65536
#define BB_OFF   65536     // B double buffer: 2 x 16384
#define BIAS_OFF 98304     // b1,b2,bc1,Wc2 : 4*512
#define REL_OFF  100352
#define EA_OFF   101888
#define DSQ_OFF  103424
#define SRC_OFF  103936
#define DST_OFF  104448
#define PW_OFF   104960    // 2*128 floats
#define EDGE_SMEM 105984   // ~103.5 KB -> 2 CTAs/SM

// ---------------- zero / prep ----------------
__global__ void zero_kernel()
{
    int i = blockIdx.x * blockDim.x + threadIdx.x;
    if (i < N_NODES * H) g_agg_msg[i] = 0.0f;
    if (i < N_NODES * 4) g_agg_coord4[i] = 0.0f;
}

// h[N,128] -> bf16 hi/lo plane groups. One thread per (node, 8-col group).
__global__ void hbf_kernel(const float* __restrict__ h)
{
    int idx = blockIdx.x * blockDim.x + threadIdx.x;
    if (idx >= N_NODES * 16) return;
    int node = idx >> 4;
    int gg = idx & 15;            // chunk*4 + g
    const float* src = h + (size_t)node * H + gg * 8;
    uint32_t hi[4], lo[4];
#pragma unroll
    for (int i = 0; i < 4; i++) {
        float a = src[i * 2], b = src[i * 2 + 1];
        hi[i] = pack2bf(a, b);
        lo[i] = pack2bf(a - bf16rt(a), b - bf16rt(b));
    }
    size_t base = (size_t)node * 32 + (gg >> 2) * 8 + (gg & 3);
    g_hbf[base]     = make_uint4(hi[0], hi[1], hi[2], hi[3]);
    g_hbf[base + 4] = make_uint4(lo[0], lo[1], lo[2], lo[3]);
}

// W[K,128] -> bf16 hi/lo as 8x8 b16 ldmatrix tiles.
// chunk(k32) image = 8192 ushorts; tile idx = (ks*2+plane)*32 + nf*2 + khalf (nf 0..15)
__global__ void prep_kernel(const float* __restrict__ W, int which, int Kact, int Kpad)
{
    int idx = blockIdx.x * blockDim.x + threadIdx.x;
    if (idx >= 128 * Kpad) return;
    int k = idx >> 7;
    int n = idx & 127;
    float v = (k < Kact) ? W[k * 128 + n] : 0.0f;
    float fhi = bf16rt(v);
    float flo = v - fhi;
    int chunk = k >> 5, ks = (k >> 4) & 1, khalf = (k >> 3) & 1, kin = k & 7;
    int nf = n >> 3, nin = n & 7;
    unsigned short* dst = (which == 0) ? g_W1b : (which == 1) ? g_W2b : g_Wc1b;
    int base = chunk * 8192;
    int tile_hi = ((ks * 2 + 0) * 16 + nf) * 2 + khalf;
    int tile_lo = ((ks * 2 + 1) * 16 + nf) * 2 + khalf;
    dst[base + tile_hi * 64 + nin * 8 + kin] = __bfloat16_as_ushort(__float2bfloat16(fhi));
    dst[base + tile_lo * 64 + nin * 8 + kin] = __bfloat16_as_ushort(__float2bfloat16(flo));
}

// ---------------- edge kernel pieces ----------------
__device__ __forceinline__ void init_d(float d[2][8][4], const float* sBias,
                                       int stage, int lane, int wc)
{
#pragma unroll
    for (int nf = 0; nf < 8; nf++) {
        int c0 = wc * 64 + nf * 8 + (lane & 3) * 2;
        float b0v = sBias[stage * 128 + c0];
        float b1v = sBias[stage * 128 + c0 + 1];
#pragma unroll
        for (int mf = 0; mf < 2; mf++) {
            d[mf][nf][0] = b0v; d[mf][nf][1] = b1v;
            d[mf][nf][2] = b0v; d[mf][nf][3] = b1v;
        }
    }
}

// prefetch B chunk cg into buf cg&1 via cp.async; caller commits the group.
__device__ __forceinline__ void issueB(uint32_t sbase, int cg, int tid)
{
    int stage = (cg < 9) ? 0 : ((cg < 13) ? 1 : 2);
    int cin = cg - ((stage == 0) ? 0 : (stage == 1) ? 9 : 13);
    const unsigned short* gW = (stage == 0) ? g_W1b : (stage == 1) ? g_W2b : g_Wc1b;
    const uint4* bsrc = (const uint4*)(gW + (size_t)cin * 8192);
    uint32_t bdst = sbase + BB_OFF + (uint32_t)(cg & 1) * 16384;
    int niter = (cg == 8) ? 2 : 4;  // tail chunk: only ks=0 tiles (first 8KB)
#pragma unroll
    for (int i = 0; i < 4; i++) {
        if (i < niter)
            cp_async16(bdst + (uint32_t)(tid + i * 256) * 16, bsrc + tid + i * 256);
    }
    CP_COMMIT;
}

// issue A-gather for chunk cn (0..7) from precomputed g_hbf, into slot cn&3.
__device__ __forceinline__ void issueA(uint32_t sbase, int cn, const int* sSrc,
                                       const int* sDst, int row, int halfq)
{
    int node = ((cn < 4) ? sSrc : sDst)[row];
    int cb = cn & 3;
    const uint4* src = g_hbf + (size_t)node * 32 + cb * 8;
    uint32_t dstBase = sbase + AF_OFF + (uint32_t)(cn & 3) * 16384;
#pragma unroll
    for (int j = 0; j < 2; j++) {
        int g = halfq * 2 + j;
        uint32_t off = aswz(row, g * 16);
        cp_async16(dstBase + off, src + g);            // hi plane
        cp_async16(dstBase + 8192 + off, src + 4 + g); // lo plane
    }
}

__device__ __forceinline__ void do_mma(uint32_t sbase, uint32_t bBuf,
                                       int slot, int lane, int wm, int wc,
                                       float d[2][8][4], int nks)
{
    uint32_t chunkBase = sbase + AF_OFF + (uint32_t)slot * 16384;
    uint32_t bRow = (uint32_t)(((lane >> 3) << 7) + ((lane & 7) << 4));
#pragma unroll 2
    for (int ks = 0; ks < nks; ks++) {
        int kbyte = ks * 32 + ((lane & 16) ? 16 : 0);
        uint32_t aHi[2][4], aLo[2][4];
#pragma unroll
        for (int mf = 0; mf < 2; mf++) {
            int row = wm * 32 + mf * 16 + (lane & 15);
            uint32_t ad = chunkBase + aswz(row, kbyte);
            ldm4(aHi[mf], ad);
            ldm4(aLo[mf], ad + 8192);
        }
        // B tiles: tile idx (ks*2+plane)*32 + wc*16 + 4q .. +3 ; 512B per ldmatrix.x4
        uint32_t tHi = bBuf + (uint32_t)((ks * 2 + 0) * 32 + wc * 16) * 128 + bRow;
        uint32_t tLo = bBuf + (uint32_t)((ks * 2 + 1) * 32 + wc * 16) * 128 + bRow;
#pragma unroll
        for (int q = 0; q < 4; q++) {
            uint32_t bh[4], bl[4];
            ldm4(bh, tHi + q * 512);
            ldm4(bl, tLo + q * 512);
#pragma unroll
            for (int j = 0; j < 2; j++) {
                int nf = q * 2 + j;
#pragma unroll
                for (int mf = 0; mf < 2; mf++) {
                    mma_bf16(d[mf][nf], aHi[mf], bh[j * 2], bh[j * 2 + 1]);
                    mma_bf16(d[mf][nf], aHi[mf], bl[j * 2], bl[j * 2 + 1]);
                    mma_bf16(d[mf][nf], aLo[mf], bh[j * 2], bh[j * 2 + 1]);
                }
            }
        }
    }
}

// epilogue: silu(d) -> (STAGE 0/1: write A-full splits; STAGE 1: + red agg_msg;
//                       STAGE 2: dot Wc2 -> coord red)
template<int STAGE>
__device__ __forceinline__ void epilogue(char* sb, float d[2][8][4],
                                         const int* sDst, const float* sRel,
                                         const float* bc2, float* sPw,
                                         int tid, int lane, int wm, int wc)
{
    __syncthreads();  // all warps done reading A-full / B
    const float* sBias = (const float*)(sb + BIAS_OFF);
    float pw0[2] = {0.f, 0.f}, pw1[2] = {0.f, 0.f};
#pragma unroll
    for (int mf = 0; mf < 2; mf++) {
        int r0 = wm * 32 + mf * 16 + (lane >> 2);
        int r1 = r0 + 8;
#pragma unroll
        for (int nf = 0; nf < 8; nf++) {
            int c0 = wc * 64 + nf * 8 + (lane & 3) * 2;
            float v0 = silu_f(d[mf][nf][0]);
            float v1 = silu_f(d[mf][nf][1]);
            float v2 = silu_f(d[mf][nf][2]);
            float v3 = silu_f(d[mf][nf][3]);
            if (STAGE == 2) {
                float w0 = sBias[384 + c0], w1 = sBias[384 + c0 + 1];
                pw0[mf] += v0 * w0 + v1 * w1;
                pw1[mf] += v2 * w0 + v3 * w1;
            } else {
                if (STAGE == 1) {
                    redv2(&g_agg_msg[(size_t)sDst[r0] * H + c0], v0, v1);
                    redv2(&g_agg_msg[(size_t)sDst[r1] * H + c0], v2, v3);
                }
                int chunk = c0 >> 5;
                int byte0 = (c0 & 31) * 2;
                char* chunkBase = sb + AF_OFF + chunk * 16384;
                uint32_t o0 = aswz(r0, byte0);
                uint32_t o1 = aswz(r1, byte0);
                *(uint32_t*)(chunkBase + o0)        = pack2bf(v0, v1);
                *(uint32_t*)(chunkBase + 8192 + o0) = pack2bf(v0 - bf16rt(v0), v1 - bf16rt(v1));
                *(uint32_t*)(chunkBase + o1)        = pack2bf(v2, v3);
                *(uint32_t*)(chunkBase + 8192 + o1) = pack2bf(v2 - bf16rt(v2), v3 - bf16rt(v3));
            }
        }
    }
    if (STAGE == 2) {
#pragma unroll
        for (int o = 1; o < 4; o <<= 1) {
            pw0[0] += __shfl_xor_sync(0xffffffffu, pw0[0], o);
            pw0[1] += __shfl_xor_sync(0xffffffffu, pw0[1], o);
            pw1[0] += __shfl_xor_sync(0xffffffffu, pw1[0], o);
            pw1[1] += __shfl_xor_sync(0xffffffffu, pw1[1], o);
        }
        if ((lane & 3) == 0) {
            int r = wm * 32 + (lane >> 2);
            sPw[wc * 128 + r]      = pw0[0];
            sPw[wc * 128 + r + 8]  = pw1[0];
            sPw[wc * 128 + r + 16] = pw0[1];
            sPw[wc * 128 + r + 24] = pw1[1];
        }
        __syncthreads();
        if (tid < 128) {
            float w = sPw[tid] + sPw[128 + tid] + bc2[0];
            int dd = sDst[tid];
            redv4(&g_agg_coord4[(size_t)dd * 4],
                  sRel[tid * 3 + 0] * w, sRel[tid * 3 + 1] * w, sRel[tid * 3 + 2] * w, 1.0f);
        }
    }
}

__global__ __launch_bounds__(256, 2) void edge_kernel(
    const float* __restrict__ x,
    const int*   __restrict__ ei, const float* __restrict__ ea,
    const float* __restrict__ b1, const float* __restrict__ b2,
    const float* __restrict__ bc1, const float* __restrict__ Wc2,
    const float* __restrict__ bc2)
{
    extern __shared__ char sb[];
    uint32_t sbase = smem_u32(sb);
    int tid = threadIdx.x, lane = tid & 31, wid = tid >> 5;
    int wm = wid & 3, wc = wid >> 2;
    int ebase = blockIdx.x * 128;

    float* sBias = (float*)(sb + BIAS_OFF);
    float* sRel  = (float*)(sb + REL_OFF);
    float* sEa   = (float*)(sb + EA_OFF);
    float* sDsq  = (float*)(sb + DSQ_OFF);
    int*   sSrc  = (int*)(sb + SRC_OFF);
    int*   sDst  = (int*)(sb + DST_OFF);
    float* sPw   = (float*)(sb + PW_OFF);

    if (tid < 128) {
        sBias[tid]       = b1[tid];
        sBias[128 + tid] = b2[tid];
        sBias[256 + tid] = bc1[tid];
        sBias[384 + tid] = Wc2[tid];
        int e = ebase + tid;
        int s = ei[e];
        int dd = ei[N_EDGES + e];
        sSrc[tid] = s; sDst[tid] = dd;
        float rx = x[s * 3 + 0] - x[dd * 3 + 0];
        float ry = x[s * 3 + 1] - x[dd * 3 + 1];
        float rz = x[s * 3 + 2] - x[dd * 3 + 2];
        sRel[tid * 3 + 0] = rx; sRel[tid * 3 + 1] = ry; sRel[tid * 3 + 2] = rz;
        sDsq[tid] = rx * rx + ry * ry + rz * rz;
        sEa[tid * 3 + 0] = ea[e * 3 + 0];
        sEa[tid * 3 + 1] = ea[e * 3 + 1];
        sEa[tid * 3 + 2] = ea[e * 3 + 2];
    }
    __syncthreads();

    float d[2][8][4];
    int row = tid >> 1, halfq = tid & 1;

    // ================= STAGE 0 : 9 chunks, race-free pipeline =================
    init_d(d, sBias, 0, lane, wc);
    issueA(sbase, 0, sSrc, sDst, row, halfq);
    issueB(sbase, 0, tid);   // commits group (A(0)+B(0))
#pragma unroll 1
    for (int c = 0; c < 9; c++) {
        CP_WAIT_0;            // A(c)+B(c) complete
        __syncthreads();      // publish; prior readers of reused buffers done
        bool pf = (c < 7);
        if (pf) issueA(sbase, c + 1, sSrc, sDst, row, halfq);
        issueB(sbase, c + 1, tid);   // commits group (c+1 in [1,9])
        do_mma(sbase, sbase + BB_OFF + (uint32_t)(c & 1) * 16384,
               c & 3, lane, wm, wc, d, (c == 8) ? 1 : 2);
        if (c == 7) {
            // build tail chunk 8 (slot 0): [ea0,ea1,ea2,dsq, zeros] (only ks=0 used)
            char* base = sb + AF_OFF + (halfq ? 8192 : 0);   // 0 -> hi, 1 -> lo
            uint32_t o0 = aswz(row, 0);
            uint32_t* p0 = (uint32_t*)(base + o0);
            if (halfq == 0) {
                p0[0] = pack2bf(sEa[row * 3 + 0], sEa[row * 3 + 1]);
                p0[1] = pack2bf(sEa[row * 3 + 2], sDsq[row]);
            } else {
                float e0 = sEa[row * 3 + 0], e1 = sEa[row * 3 + 1];
                float e2 = sEa[row * 3 + 2], dq = sDsq[row];
                p0[0] = pack2bf(e0 - bf16rt(e0), e1 - bf16rt(e1));
                p0[1] = pack2bf(e2 - bf16rt(e2), dq - bf16rt(dq));
            }
            p0[2] = 0u; p0[3] = 0u;
            uint32_t* p1 = (uint32_t*)(base + aswz(row, 16));
            p1[0] = 0u; p1[1] = 0u; p1[2] = 0u; p1[3] = 0u;
        }
    }
    epilogue<0>(sb, d, sDst, sRel, bc2, sPw, tid, lane, wm, wc);

    // ================= STAGE 1 : chunks 9..12 (B(9) already in flight) =================
    init_d(d, sBias, 1, lane, wc);
#pragma unroll 1
    for (int c = 0; c < 4; c++) {
        int cg = 9 + c;
        CP_WAIT_0;
        __syncthreads();
        issueB(sbase, cg + 1, tid);  // 10..13
        do_mma(sbase, sbase + BB_OFF + (uint32_t)(cg & 1) * 16384,
               c, lane, wm, wc, d, 2);
    }
    epilogue<1>(sb, d, sDst, sRel, bc2, sPw, tid, lane, wm, wc);

    // ================= STAGE 2 : chunks 13..16 (B(13) already in flight) =================
    init_d(d, sBias, 2, lane, wc);
#pragma unroll 1
    for (int c = 0; c < 4; c++) {
        int cg = 13 + c;
        CP_WAIT_0;
        __syncthreads();
        if (cg < 16) issueB(sbase, cg + 1, tid);
        do_mma(sbase, sbase + BB_OFF + (uint32_t)(cg & 1) * 16384,
               c, lane, wm, wc, d, 2);
    }
    epilogue<2>(sb, d, sDst, sRel, bc2, sPw, tid, lane, wm, wc);
}

// ---------------- SIMT node kernel (64 nodes / block) ----------------
__device__ __forceinline__ void gemm128(const float* __restrict__ As,
                                        const float* __restrict__ Wg,
                                        float* sW, float acc[4][8],
                                        int tm, int tn, int tid)
{
    for (int kt = 0; kt < 128; kt += 16) {
        __syncthreads();
        const float4* Wv = (const float4*)(Wg + (size_t)kt * H);
        float4* sWv = (float4*)sW;
        sWv[tid]       = Wv[tid];
        sWv[tid + 256] = Wv[tid + 256];
        __syncthreads();
#pragma unroll
        for (int kk = 0; kk < 16; kk++) {
            float a[4];
#pragma unroll
            for (int m = 0; m < 4; m++) a[m] = As[(tm * 4 + m) * H + kt + kk];
            float4 w0 = *(const float4*)&sW[kk * H + tn * 8];
            float4 w1 = *(const float4*)&sW[kk * H + tn * 8 + 4];
#pragma unroll
            for (int m = 0; m < 4; m++) {
                acc[m][0] += a[m] * w0.x; acc[m][1] += a[m] * w0.y;
                acc[m][2] += a[m] * w0.z; acc[m][3] += a[m] * w0.w;
                acc[m][4] += a[m] * w1.x; acc[m][5] += a[m] * w1.y;
                acc[m][6] += a[m] * w1.z; acc[m][7] += a[m] * w1.w;
            }
        }
    }
}

__global__ __launch_bounds__(256, 2) void node_kernel(
    const float* __restrict__ h,   const float* __restrict__ x,
    const float* __restrict__ Wn1, const float* __restrict__ bn1,
    const float* __restrict__ Wn2, const float* __restrict__ bn2,
    const float* __restrict__ gamma, const float* __restrict__ beta,
    float* __restrict__ out_h, float* __restrict__ out_x)
{
    extern __shared__ float smem[];
    float* sA = smem;
    float* sB = sA + 64 * H;
    float* sW = sB + 64 * H;

    int tid = threadIdx.x;
    int tn = tid & 15;
    int tm = tid >> 4;
    int nbase = blockIdx.x * 64;

    {
        const float4* hv = (const float4*)h;
        const float4* av = (const float4*)g_agg_msg;
        float4* sA4 = (float4*)sA;
        float4* sB4 = (float4*)sB;
        float4 z = make_float4(0.f, 0.f, 0.f, 0.f);
#pragma unroll
        for (int j = 0; j < 8; j++) {
            int idx = tid + j * 256;
            int row = idx >> 5;
            int c4 = idx & 31;
            int node = nbase + row;
            if (node < N_NODES) {
                sA4[idx] = hv[(size_t)node * 32 + c4];
                sB4[idx] = av[(size_t)node * 32 + c4];
            } else { sA4[idx] = z; sB4[idx] = z; }
        }
    }

    float acc[4][8];
    {
        float4 b0 = *(const float4*)(bn1 + tn * 8);
        float4 b1v = *(const float4*)(bn1 + tn * 8 + 4);
#pragma unroll
        for (int m = 0; m < 4; m++) {
            acc[m][0] = b0.x; acc[m][1] = b0.y; acc[m][2] = b0.z; acc[m][3] = b0.w;
            acc[m][4] = b1v.x; acc[m][5] = b1v.y; acc[m][6] = b1v.z; acc[m][7] = b1v.w;
        }
    }
    gemm128(sA, Wn1, sW, acc, tm, tn, tid);
    gemm128(sB, Wn1 + 128 * H, sW, acc, tm, tn, tid);
#pragma unroll
    for (int m = 0; m < 4; m++)
#pragma unroll
        for (int n = 0; n < 8; n++)
            acc[m][n] = silu_f(acc[m][n]);
    __syncthreads();
#pragma unroll
    for (int m = 0; m < 4; m++) {
        int row = tm * 4 + m;
        *(float4*)&sB[row * H + tn * 8]     = make_float4(acc[m][0], acc[m][1], acc[m][2], acc[m][3]);
        *(float4*)&sB[row * H + tn * 8 + 4] = make_float4(acc[m][4], acc[m][5], acc[m][6], acc[m][7]);
    }

    {
        float4 b0 = *(const float4*)(bn2 + tn * 8);
        float4 b1v = *(const float4*)(bn2 + tn * 8 + 4);
#pragma unroll
        for (int m = 0; m < 4; m++) {
            acc[m][0] = b0.x; acc[m][1] = b0.y; acc[m][2] = b0.z; acc[m][3] = b0.w;
            acc[m][4] = b1v.x; acc[m][5] = b1v.y; acc[m][6] = b1v.z; acc[m][7] = b1v.w;
        }
    }
    gemm128(sB, Wn2, sW, acc, tm, tn, tid);

    __syncthreads();
#pragma unroll
    for (int m = 0; m < 4; m++) {
        int row = tm * 4 + m;
        float4 h0 = *(const float4*)&sA[row * H + tn * 8];
        float4 h1 = *(const float4*)&sA[row * H + tn * 8 + 4];
        *(float4*)&sB[row * H + tn * 8]     = make_float4(h0.x + acc[m][0], h0.y + acc[m][1], h0.z + acc[m][2], h0.w + acc[m][3]);
        *(float4*)&sB[row * H + tn * 8 + 4] = make_float4(h1.x + acc[m][4], h1.y + acc[m][5], h1.z + acc[m][6], h1.w + acc[m][7]);
    }
    __syncthreads();

    {
        int row = tid >> 2;
        int part = tid & 3;
        int node = nbase + row;
        const float4* yv = (const float4*)sB;
        float s = 0.f, sq = 0.f;
        float4 vals[8];
#pragma unroll
        for (int j = 0; j < 8; j++) {
            float4 v = yv[row * 32 + part * 8 + j];
            vals[j] = v;
            s  += v.x + v.y + v.z + v.w;
            sq += v.x * v.x + v.y * v.y + v.z * v.z + v.w * v.w;
        }
        s  += __shfl_xor_sync(0xffffffffu, s, 1);
        sq += __shfl_xor_sync(0xffffffffu, sq, 1);
        s  += __shfl_xor_sync(0xffffffffu, s, 2);
        sq += __shfl_xor_sync(0xffffffffu, sq, 2);
        float mu  = s * (1.0f / 128.0f);
        float var = sq * (1.0f / 128.0f) - mu * mu;
        float inv = rsqrtf(var + 1e-5f);
        if (node < N_NODES) {
            float4* ov = (float4*)(out_h + (size_t)node * H);
#pragma unroll
            for (int j = 0; j < 8; j++) {
                int c4 = part * 8 + j;
                float4 g = *(const float4*)(gamma + c4 * 4);
                float4 b = *(const float4*)(beta + c4 * 4);
                float4 v = vals[j];
                ov[c4] = make_float4((v.x - mu) * inv * g.x + b.x,
                                     (v.y - mu) * inv * g.y + b.y,
                                     (v.z - mu) * inv * g.z + b.z,
                                     (v.w - mu) * inv * g.w + b.w);
            }
        }
    }

    if (tid < 192) {
        int r = tid / 3, c = tid % 3;
        int node = nbase + r;
        if (node < N_NODES) {
            float cnt = fmaxf(g_agg_coord4[(size_t)node * 4 + 3], 1.0f);
            out_x[(size_t)node * 3 + c] = x[(size_t)node * 3 + c]
                                        + g_agg_coord4[(size_t)node * 4 + c] / cnt;
        }
    }
}

// ---------------------------------------------------------------------------
extern "C" void kernel_launch(void* const* d_in, const int* in_sizes, int n_in,
                              void* d_out, int out_size)
{
    const float* h    = (const float*)d_in[0];
    const float* x    = (const float*)d_in[1];
    const int*   eidx = (const int*)  d_in[2];
    const float* ea   = (const float*)d_in[3];
    const float* W1   = (const float*)d_in[4];
    const float* b1   = (const float*)d_in[5];
    const float* W2   = (const float*)d_in[6];
    const float* b2   = (const float*)d_in[7];
    const float* Wc1  = (const float*)d_in[8];
    const float* bc1  = (const float*)d_in[9];
    const float* Wc2  = (const float*)d_in[10];
    const float* bc2  = (const float*)d_in[11];
    const float* Wn1  = (const float*)d_in[12];
    const float* bn1  = (const float*)d_in[13];
    const float* Wn2  = (const float*)d_in[14];
    const float* bn2  = (const float*)d_in[15];
    const float* gamma = (const float*)d_in[16];
    const float* beta  = (const float*)d_in[17];

    float* out_h = (float*)d_out;
    float* out_x = out_h + (size_t)N_NODES * H;

    const int NODE_SMEM = (64 * H + 64 * H + 16 * H) * 4;
    cudaFuncSetAttribute(edge_kernel, cudaFuncAttributeMaxDynamicSharedMemorySize, EDGE_SMEM);
    cudaFuncSetAttribute(node_kernel, cudaFuncAttributeMaxDynamicSharedMemorySize, NODE_SMEM);

    zero_kernel<<<(N_NODES * H + 255) / 256, 256>>>();
    hbf_kernel<<<(N_NODES * 16 + 255) / 256, 256>>>(h);
    prep_kernel<<<(128 * 288 + 255) / 256, 256>>>(W1, 0, 260, 288);
    prep_kernel<<<(128 * 128 + 255) / 256, 256>>>(W2, 1, 128, 128);
    prep_kernel<<<(128 * 128 + 255) / 256, 256>>>(Wc1, 2, 128, 128);
    edge_kernel<<<N_EDGES / 128, 256, EDGE_SMEM>>>(x, eidx, ea, b1, b2, bc1, Wc2, bc2);
    node_kernel<<<(N_NODES + 63) / 64, 256, NODE_SMEM>>>(h, x, Wn1, bn1, Wn2, bn2,
                                                         gamma, beta, out_h, out_x);
}

// round 9
// speedup vs baseline: 4.0612x; 1.2545x over previous
#include <cuda_runtime.h>
#include <cuda_fp16.h>
#include <cstdint>

#define N_NODES 50000
#define N_EDGES 800000
#define H 128

// ---------------- device scratch ----------------
__device__ __align__(16) float g_agg_msg[(size_t)N_NODES * H];
__device__ __align__(16) float g_agg_coord4[(size_t)N_NODES * 4];  // x,y,z,count
// Weights as 8x8 b16 ldmatrix tiles, fp16 hi/lo planes, chunked by k32 (8192 ushorts/chunk).
__device__ __align__(16) unsigned short g_W1b[9 * 8192];
__device__ __align__(16) unsigned short g_W2b[4 * 8192];
__device__ __align__(16) unsigned short g_Wc1b[4 * 8192];
// h pre-converted to fp16 16B groups: [node][chunk(4)][group(4)] uint4
__device__ __align__(16) uint4 g_hbf[(size_t)N_NODES * 16];

// ---------------- helpers ----------------
__device__ __forceinline__ uint32_t smem_u32(const void* p) {
    uint32_t a;
    asm("{ .reg .u64 t; cvta.to.shared.u64 t, %1; cvt.u32.u64 %0, t; }" : "=r"(a) : "l"(p));
    return a;
}
__device__ __forceinline__ float h16rt(float v) {
    return __half2float(__float2half_rn(v));
}
__device__ __forceinline__ uint32_t pack2h(float a, float b) {
    __half2 hh = __floats2half2_rn(a, b);
    return *(uint32_t*)&hh;
}
__device__ __forceinline__ float silu_f(float v) {
    return v * (1.0f / (1.0f + __expf(-v)));
}
__device__ __forceinline__ void redv2(float* p, float a, float b) {
    asm volatile("red.global.add.v2.f32 [%0], {%1, %2};" :: "l"(p), "f"(a), "f"(b) : "memory");
}
__device__ __forceinline__ void redv4(float* p, float a, float b, float c, float d) {
    asm volatile("red.global.add.v4.f32 [%0], {%1, %2, %3, %4};"
                 :: "l"(p), "f"(a), "f"(b), "f"(c), "f"(d) : "memory");
}
__device__ __forceinline__ void ldm4(uint32_t* r, uint32_t addr) {
    asm volatile("ldmatrix.sync.aligned.m8n8.x4.shared.b16 {%0,%1,%2,%3}, [%4];"
                 : "=r"(r[0]), "=r"(r[1]), "=r"(r[2]), "=r"(r[3]) : "r"(addr));
}
__device__ __forceinline__ void mma_f16(float* d, const uint32_t* a, uint32_t b0, uint32_t b1) {
    asm volatile("mma.sync.aligned.m16n8k16.row.col.f32.f16.f16.f32 "
                 "{%0,%1,%2,%3}, {%4,%5,%6,%7}, {%8,%9}, {%0,%1,%2,%3};"
                 : "+f"(d[0]), "+f"(d[1]), "+f"(d[2]), "+f"(d[3])
                 : "r"(a[0]), "r"(a[1]), "r"(a[2]), "r"(a[3]), "r"(b0), "r"(b1));
}
__device__ __forceinline__ void cp_async16(uint32_t dst, const void* src) {
    asm volatile("cp.async.cg.shared.global [%0], [%1], 16;" :: "r"(dst), "l"(src) : "memory");
}
#define CP_COMMIT  asm volatile("cp.async.commit_group;" ::: "memory")
#define CP_WAIT_0  asm volatile("cp.async.wait_group 0;" ::: "memory")

// A-plane XOR swizzle: 64B row stride, 16B groups permuted by g ^= (row>>1)&3.
__device__ __forceinline__ uint32_t aswz(int row, int byteInRow) {
    int g = byteInRow >> 4;
    int inner = byteInRow & 15;
    return (uint32_t)(row * 64 + (((g ^ ((row >> 1) & 3)) << 4) | inner));
}

// ---------------- smem layout (edge kernel) ----------------
#define AF_OFF   0         // 4 slots x 8192 (single fp16 plane each) = 32768
#define BB_OFF   32768     // B double buffer: 2 x 16384
#define BIAS_OFF 65536     // b1,b2,bc1,Wc2 : 4*512
#define REL_OFF  67584
#define EA_OFF   69120
#define DSQ_OFF  70656
#define SRC_OFF  71168
#define DST_OFF  71680
#define PW_OFF   72192     // 2*128 floats
#define EDGE_SMEM 73216    // ~71.5 KB

// ---------------- zero / prep ----------------
__global__ void zero_kernel()
{
    int i = blockIdx.x * blockDim.x + threadIdx.x;
    if (i < N_NODES * H) g_agg_msg[i] = 0.0f;
    if (i < N_NODES * 4) g_agg_coord4[i] = 0.0f;
}

// h[N,128] -> fp16 groups. One thread per (node, 8-col group).
__global__ void hbf_kernel(const float* __restrict__ h)
{
    int idx = blockIdx.x * blockDim.x + threadIdx.x;
    if (idx >= N_NODES * 16) return;
    int node = idx >> 4;
    int gg = idx & 15;            // chunk*4 + g
    const float* src = h + (size_t)node * H + gg * 8;
    uint32_t w[4];
#pragma unroll
    for (int i = 0; i < 4; i++)
        w[i] = pack2h(src[i * 2], src[i * 2 + 1]);
    g_hbf[(size_t)node * 16 + gg] = make_uint4(w[0], w[1], w[2], w[3]);
}

// W[K,128] -> fp16 hi/lo as 8x8 b16 ldmatrix tiles.
// chunk(k32) image = 8192 ushorts; tile idx = (ks*2+plane)*32 + nf*2 + khalf (nf 0..15)
__global__ void prep_kernel(const float* __restrict__ W, int which, int Kact, int Kpad)
{
    int idx = blockIdx.x * blockDim.x + threadIdx.x;
    if (idx >= 128 * Kpad) return;
    int k = idx >> 7;
    int n = idx & 127;
    float v = (k < Kact) ? W[k * 128 + n] : 0.0f;
    float fhi = h16rt(v);
    float flo = v - fhi;
    int chunk = k >> 5, ks = (k >> 4) & 1, khalf = (k >> 3) & 1, kin = k & 7;
    int nf = n >> 3, nin = n & 7;
    unsigned short* dst = (which == 0) ? g_W1b : (which == 1) ? g_W2b : g_Wc1b;
    int base = chunk * 8192;
    int tile_hi = ((ks * 2 + 0) * 16 + nf) * 2 + khalf;
    int tile_lo = ((ks * 2 + 1) * 16 + nf) * 2 + khalf;
    __half hh = __float2half_rn(fhi);
    __half hl = __float2half_rn(flo);
    dst[base + tile_hi * 64 + nin * 8 + kin] = *(unsigned short*)&hh;
    dst[base + tile_lo * 64 + nin * 8 + kin] = *(unsigned short*)&hl;
}

// ---------------- edge kernel pieces ----------------
__device__ __forceinline__ void init_d(float d[2][8][4], const float* sBias,
                                       int stage, int lane, int wc)
{
#pragma unroll
    for (int nf = 0; nf < 8; nf++) {
        int c0 = wc * 64 + nf * 8 + (lane & 3) * 2;
        float b0v = sBias[stage * 128 + c0];
        float b1v = sBias[stage * 128 + c0 + 1];
#pragma unroll
        for (int mf = 0; mf < 2; mf++) {
            d[mf][nf][0] = b0v; d[mf][nf][1] = b1v;
            d[mf][nf][2] = b0v; d[mf][nf][3] = b1v;
        }
    }
}

// prefetch B chunk cg into buf cg&1 via cp.async; commits the group.
__device__ __forceinline__ void issueB(uint32_t sbase, int cg, int tid)
{
    int stage = (cg < 9) ? 0 : ((cg < 13) ? 1 : 2);
    int cin = cg - ((stage == 0) ? 0 : (stage == 1) ? 9 : 13);
    const unsigned short* gW = (stage == 0) ? g_W1b : (stage == 1) ? g_W2b : g_Wc1b;
    const uint4* bsrc = (const uint4*)(gW + (size_t)cin * 8192);
    uint32_t bdst = sbase + BB_OFF + (uint32_t)(cg & 1) * 16384;
    int niter = (cg == 8) ? 2 : 4;  // tail chunk: only ks=0 tiles (first 8KB)
#pragma unroll
    for (int i = 0; i < 4; i++) {
        if (i < niter)
            cp_async16(bdst + (uint32_t)(tid + i * 256) * 16, bsrc + tid + i * 256);
    }
    CP_COMMIT;
}

// issue A-gather for chunk cn (0..7) from precomputed g_hbf, into slot cn&3.
__device__ __forceinline__ void issueA(uint32_t sbase, int cn, const int* sSrc,
                                       const int* sDst, int row, int halfq)
{
    int node = ((cn < 4) ? sSrc : sDst)[row];
    int cb = cn & 3;
    const uint4* src = g_hbf + (size_t)node * 16 + cb * 4;
    uint32_t dstBase = sbase + AF_OFF + (uint32_t)(cn & 3) * 8192;
#pragma unroll
    for (int j = 0; j < 2; j++) {
        int g = halfq * 2 + j;
        cp_async16(dstBase + aswz(row, g * 16), src + g);
    }
}

// TAIL=false: 2-product (A fp16, B hi/lo). TAIL=true: 1 k-step, 3-product
// (A hi in slot, A lo in slot+1 plane).
template<int NKS, bool TAIL>
__device__ __forceinline__ void do_mma(uint32_t sbase, uint32_t bBuf,
                                       int slot, int lane, int wm, int wc,
                                       float d[2][8][4])
{
    uint32_t chunkBase = sbase + AF_OFF + (uint32_t)slot * 8192;
    uint32_t bRow = (uint32_t)(((lane >> 3) << 7) + ((lane & 7) << 4));
#pragma unroll
    for (int ks = 0; ks < NKS; ks++) {
        int kbyte = ks * 32 + ((lane & 16) ? 16 : 0);
        uint32_t aHi[2][4], aLo[2][4];
#pragma unroll
        for (int mf = 0; mf < 2; mf++) {
            int row = wm * 32 + mf * 16 + (lane & 15);
            uint32_t ad = chunkBase + aswz(row, kbyte);
            ldm4(aHi[mf], ad);
            if (TAIL) ldm4(aLo[mf], ad + 8192);  // next slot's plane holds A-lo
        }
        uint32_t tHi = bBuf + (uint32_t)((ks * 2 + 0) * 32 + wc * 16) * 128 + bRow;
        uint32_t tLo = bBuf + (uint32_t)((ks * 2 + 1) * 32 + wc * 16) * 128 + bRow;
#pragma unroll
        for (int q = 0; q < 4; q++) {
            uint32_t bh[4], bl[4];
            ldm4(bh, tHi + q * 512);
            ldm4(bl, tLo + q * 512);
#pragma unroll
            for (int j = 0; j < 2; j++) {
                int nf = q * 2 + j;
#pragma unroll
                for (int mf = 0; mf < 2; mf++) {
                    mma_f16(d[mf][nf], aHi[mf], bh[j * 2], bh[j * 2 + 1]);
                    mma_f16(d[mf][nf], aHi[mf], bl[j * 2], bl[j * 2 + 1]);
                    if (TAIL) mma_f16(d[mf][nf], aLo[mf], bh[j * 2], bh[j * 2 + 1]);
                }
            }
        }
    }
}

// epilogue: silu(d) -> (STAGE 0/1: write fp16 A plane; STAGE 1: + red agg_msg;
//                       STAGE 2: dot Wc2 -> coord red)
template<int STAGE>
__device__ __forceinline__ void epilogue(char* sb, float d[2][8][4],
                                         const int* sDst, const float* sRel,
                                         const float* bc2, float* sPw,
                                         int tid, int lane, int wm, int wc)
{
    __syncthreads();  // all warps done reading A / B
    const float* sBias = (const float*)(sb + BIAS_OFF);
    float pw0[2] = {0.f, 0.f}, pw1[2] = {0.f, 0.f};
#pragma unroll
    for (int mf = 0; mf < 2; mf++) {
        int r0 = wm * 32 + mf * 16 + (lane >> 2);
        int r1 = r0 + 8;
#pragma unroll
        for (int nf = 0; nf < 8; nf++) {
            int c0 = wc * 64 + nf * 8 + (lane & 3) * 2;
            float v0 = silu_f(d[mf][nf][0]);
            float v1 = silu_f(d[mf][nf][1]);
            float v2 = silu_f(d[mf][nf][2]);
            float v3 = silu_f(d[mf][nf][3]);
            if (STAGE == 2) {
                float w0 = sBias[384 + c0], w1 = sBias[384 + c0 + 1];
                pw0[mf] += v0 * w0 + v1 * w1;
                pw1[mf] += v2 * w0 + v3 * w1;
            } else {
                if (STAGE == 1) {
                    redv2(&g_agg_msg[(size_t)sDst[r0] * H + c0], v0, v1);
                    redv2(&g_agg_msg[(size_t)sDst[r1] * H + c0], v2, v3);
                }
                int chunk = c0 >> 5;
                int byte0 = (c0 & 31) * 2;
                char* chunkBase = sb + AF_OFF + chunk * 8192;
                *(uint32_t*)(chunkBase + aswz(r0, byte0)) = pack2h(v0, v1);
                *(uint32_t*)(chunkBase + aswz(r1, byte0)) = pack2h(v2, v3);
            }
        }
    }
    if (STAGE == 2) {
#pragma unroll
        for (int o = 1; o < 4; o <<= 1) {
            pw0[0] += __shfl_xor_sync(0xffffffffu, pw0[0], o);
            pw0[1] += __shfl_xor_sync(0xffffffffu, pw0[1], o);
            pw1[0] += __shfl_xor_sync(0xffffffffu, pw1[0], o);
            pw1[1] += __shfl_xor_sync(0xffffffffu, pw1[1], o);
        }
        if ((lane & 3) == 0) {
            int r = wm * 32 + (lane >> 2);
            sPw[wc * 128 + r]      = pw0[0];
            sPw[wc * 128 + r + 8]  = pw1[0];
            sPw[wc * 128 + r + 16] = pw0[1];
            sPw[wc * 128 + r + 24] = pw1[1];
        }
        __syncthreads();
        if (tid < 128) {
            float w = sPw[tid] + sPw[128 + tid] + bc2[0];
            int dd = sDst[tid];
            redv4(&g_agg_coord4[(size_t)dd * 4],
                  sRel[tid * 3 + 0] * w, sRel[tid * 3 + 1] * w, sRel[tid * 3 + 2] * w, 1.0f);
        }
    }
}

__global__ __launch_bounds__(256, 2) void edge_kernel(
    const float* __restrict__ x,
    const int*   __restrict__ ei, const float* __restrict__ ea,
    const float* __restrict__ b1, const float* __restrict__ b2,
    const float* __restrict__ bc1, const float* __restrict__ Wc2,
    const float* __restrict__ bc2)
{
    extern __shared__ char sb[];
    uint32_t sbase = smem_u32(sb);
    int tid = threadIdx.x, lane = tid & 31, wid = tid >> 5;
    int wm = wid & 3, wc = wid >> 2;
    int ebase = blockIdx.x * 128;

    float* sBias = (float*)(sb + BIAS_OFF);
    float* sRel  = (float*)(sb + REL_OFF);
    float* sEa   = (float*)(sb + EA_OFF);
    float* sDsq  = (float*)(sb + DSQ_OFF);
    int*   sSrc  = (int*)(sb + SRC_OFF);
    int*   sDst  = (int*)(sb + DST_OFF);
    float* sPw   = (float*)(sb + PW_OFF);

    if (tid < 128) {
        sBias[tid]       = b1[tid];
        sBias[128 + tid] = b2[tid];
        sBias[256 + tid] = bc1[tid];
        sBias[384 + tid] = Wc2[tid];
        int e = ebase + tid;
        int s = ei[e];
        int dd = ei[N_EDGES + e];
        sSrc[tid] = s; sDst[tid] = dd;
        float rx = x[s * 3 + 0] - x[dd * 3 + 0];
        float ry = x[s * 3 + 1] - x[dd * 3 + 1];
        float rz = x[s * 3 + 2] - x[dd * 3 + 2];
        sRel[tid * 3 + 0] = rx; sRel[tid * 3 + 1] = ry; sRel[tid * 3 + 2] = rz;
        sDsq[tid] = rx * rx + ry * ry + rz * rz;
        sEa[tid * 3 + 0] = ea[e * 3 + 0];
        sEa[tid * 3 + 1] = ea[e * 3 + 1];
        sEa[tid * 3 + 2] = ea[e * 3 + 2];
    }
    __syncthreads();

    float d[2][8][4];
    int row = tid >> 1, halfq = tid & 1;

    // ================= STAGE 0 : 9 chunks, race-free pipeline =================
    init_d(d, sBias, 0, lane, wc);
    issueA(sbase, 0, sSrc, sDst, row, halfq);
    issueB(sbase, 0, tid);   // commits group (A(0)+B(0))
#pragma unroll 1
    for (int c = 0; c < 9; c++) {
        CP_WAIT_0;            // A(c)+B(c) complete
        __syncthreads();      // publish; prior readers of reused buffers done
        bool pf = (c < 7);
        if (pf) issueA(sbase, c + 1, sSrc, sDst, row, halfq);
        issueB(sbase, c + 1, tid);   // commits group (c+1 in [1,9])
        uint32_t bBuf = sbase + BB_OFF + (uint32_t)(c & 1) * 16384;
        if (c == 8) do_mma<1, true>(sbase, bBuf, 0, lane, wm, wc, d);
        else        do_mma<2, false>(sbase, bBuf, c & 3, lane, wm, wc, d);
        if (c == 7) {
            // build tail chunk 8: A-hi in slot0 plane, A-lo in slot1 plane.
            // (slots 0/1 last read at c=4/5; safe to overwrite, published by c=8 barrier)
            char* base = sb + AF_OFF + (halfq ? 8192 : 0);
            uint32_t* p0 = (uint32_t*)(base + aswz(row, 0));
            if (halfq == 0) {
                p0[0] = pack2h(sEa[row * 3 + 0], sEa[row * 3 + 1]);
                p0[1] = pack2h(sEa[row * 3 + 2], sDsq[row]);
            } else {
                float e0 = sEa[row * 3 + 0], e1 = sEa[row * 3 + 1];
                float e2 = sEa[row * 3 + 2], dq = sDsq[row];
                p0[0] = pack2h(e0 - h16rt(e0), e1 - h16rt(e1));
                p0[1] = pack2h(e2 - h16rt(e2), dq - h16rt(dq));
            }
            p0[2] = 0u; p0[3] = 0u;
            uint32_t* p1 = (uint32_t*)(base + aswz(row, 16));
            p1[0] = 0u; p1[1] = 0u; p1[2] = 0u; p1[3] = 0u;
        }
    }
    epilogue<0>(sb, d, sDst, sRel, bc2, sPw, tid, lane, wm, wc);

    // ================= STAGE 1 : chunks 9..12 (B(9) already in flight) =================
    init_d(d, sBias, 1, lane, wc);
#pragma unroll 1
    for (int c = 0; c < 4; c++) {
        int cg = 9 + c;
        CP_WAIT_0;
        __syncthreads();
        issueB(sbase, cg + 1, tid);  // 10..13
        do_mma<2, false>(sbase, sbase + BB_OFF + (uint32_t)(cg & 1) * 16384,
                         c, lane, wm, wc, d);
    }
    epilogue<1>(sb, d, sDst, sRel, bc2, sPw, tid, lane, wm, wc);

    // ================= STAGE 2 : chunks 13..16 (B(13) already in flight) =================
    init_d(d, sBias, 2, lane, wc);
#pragma unroll 1
    for (int c = 0; c < 4; c++) {
        int cg = 13 + c;
        CP_WAIT_0;
        __syncthreads();
        if (cg < 16) issueB(sbase, cg + 1, tid);
        do_mma<2, false>(sbase, sbase + BB_OFF + (uint32_t)(cg & 1) * 16384,
                         c, lane, wm, wc, d);
    }
    epilogue<2>(sb, d, sDst, sRel, bc2, sPw, tid, lane, wm, wc);
}

// ---------------- SIMT node kernel (64 nodes / block) ----------------
__device__ __forceinline__ void gemm128(const float* __restrict__ As,
                                        const float* __restrict__ Wg,
                                        float* sW, float acc[4][8],
                                        int tm, int tn, int tid)
{
    for (int kt = 0; kt < 128; kt += 16) {
        __syncthreads();
        const float4* Wv = (const float4*)(Wg + (size_t)kt * H);
        float4* sWv = (float4*)sW;
        sWv[tid]       = Wv[tid];
        sWv[tid + 256] = Wv[tid + 256];
        __syncthreads();
#pragma unroll
        for (int kk = 0; kk < 16; kk++) {
            float a[4];
#pragma unroll
            for (int m = 0; m < 4; m++) a[m] = As[(tm * 4 + m) * H + kt + kk];
            float4 w0 = *(const float4*)&sW[kk * H + tn * 8];
            float4 w1 = *(const float4*)&sW[kk * H + tn * 8 + 4];
#pragma unroll
            for (int m = 0; m < 4; m++) {
                acc[m][0] += a[m] * w0.x; acc[m][1] += a[m] * w0.y;
                acc[m][2] += a[m] * w0.z; acc[m][3] += a[m] * w0.w;
                acc[m][4] += a[m] * w1.x; acc[m][5] += a[m] * w1.y;
                acc[m][6] += a[m] * w1.z; acc[m][7] += a[m] * w1.w;
            }
        }
    }
}

__global__ __launch_bounds__(256, 2) void node_kernel(
    const float* __restrict__ h,   const float* __restrict__ x,
    const float* __restrict__ Wn1, const float* __restrict__ bn1,
    const float* __restrict__ Wn2, const float* __restrict__ bn2,
    const float* __restrict__ gamma, const float* __restrict__ beta,
    float* __restrict__ out_h, float* __restrict__ out_x)
{
    extern __shared__ float smem[];
    float* sA = smem;
    float* sB = sA + 64 * H;
    float* sW = sB + 64 * H;

    int tid = threadIdx.x;
    int tn = tid & 15;
    int tm = tid >> 4;
    int nbase = blockIdx.x * 64;

    {
        const float4* hv = (const float4*)h;
        const float4* av = (const float4*)g_agg_msg;
        float4* sA4 = (float4*)sA;
        float4* sB4 = (float4*)sB;
        float4 z = make_float4(0.f, 0.f, 0.f, 0.f);
#pragma unroll
        for (int j = 0; j < 8; j++) {
            int idx = tid + j * 256;
            int row = idx >> 5;
            int c4 = idx & 31;
            int node = nbase + row;
            if (node < N_NODES) {
                sA4[idx] = hv[(size_t)node * 32 + c4];
                sB4[idx] = av[(size_t)node * 32 + c4];
            } else { sA4[idx] = z; sB4[idx] = z; }
        }
    }

    float acc[4][8];
    {
        float4 b0 = *(const float4*)(bn1 + tn * 8);
        float4 b1v = *(const float4*)(bn1 + tn * 8 + 4);
#pragma unroll
        for (int m = 0; m < 4; m++) {
            acc[m][0] = b0.x; acc[m][1] = b0.y; acc[m][2] = b0.z; acc[m][3] = b0.w;
            acc[m][4] = b1v.x; acc[m][5] = b1v.y; acc[m][6] = b1v.z; acc[m][7] = b1v.w;
        }
    }
    gemm128(sA, Wn1, sW, acc, tm, tn, tid);
    gemm128(sB, Wn1 + 128 * H, sW, acc, tm, tn, tid);
#pragma unroll
    for (int m = 0; m < 4; m++)
#pragma unroll
        for (int n = 0; n < 8; n++)
            acc[m][n] = silu_f(acc[m][n]);
    __syncthreads();
#pragma unroll
    for (int m = 0; m < 4; m++) {
        int row = tm * 4 + m;
        *(float4*)&sB[row * H + tn * 8]     = make_float4(acc[m][0], acc[m][1], acc[m][2], acc[m][3]);
        *(float4*)&sB[row * H + tn * 8 + 4] = make_float4(acc[m][4], acc[m][5], acc[m][6], acc[m][7]);
    }

    {
        float4 b0 = *(const float4*)(bn2 + tn * 8);
        float4 b1v = *(const float4*)(bn2 + tn * 8 + 4);
#pragma unroll
        for (int m = 0; m < 4; m++) {
            acc[m][0] = b0.x; acc[m][1] = b0.y; acc[m][2] = b0.z; acc[m][3] = b0.w;
            acc[m][4] = b1v.x; acc[m][5] = b1v.y; acc[m][6] = b1v.z; acc[m][7] = b1v.w;
        }
    }
    gemm128(sB, Wn2, sW, acc, tm, tn, tid);

    __syncthreads();
#pragma unroll
    for (int m = 0; m < 4; m++) {
        int row = tm * 4 + m;
        float4 h0 = *(const float4*)&sA[row * H + tn * 8];
        float4 h1 = *(const float4*)&sA[row * H + tn * 8 + 4];
        *(float4*)&sB[row * H + tn * 8]     = make_float4(h0.x + acc[m][0], h0.y + acc[m][1], h0.z + acc[m][2], h0.w + acc[m][3]);
        *(float4*)&sB[row * H + tn * 8 + 4] = make_float4(h1.x + acc[m][4], h1.y + acc[m][5], h1.z + acc[m][6], h1.w + acc[m][7]);
    }
    __syncthreads();

    {
        int row = tid >> 2;
        int part = tid & 3;
        int node = nbase + row;
        const float4* yv = (const float4*)sB;
        float s = 0.f, sq = 0.f;
        float4 vals[8];
#pragma unroll
        for (int j = 0; j < 8; j++) {
            float4 v = yv[row * 32 + part * 8 + j];
            vals[j] = v;
            s  += v.x + v.y + v.z + v.w;
            sq += v.x * v.x + v.y * v.y + v.z * v.z + v.w * v.w;
        }
        s  += __shfl_xor_sync(0xffffffffu, s, 1);
        sq += __shfl_xor_sync(0xffffffffu, sq, 1);
        s  += __shfl_xor_sync(0xffffffffu, s, 2);
        sq += __shfl_xor_sync(0xffffffffu, sq, 2);
        float mu  = s * (1.0f / 128.0f);
        float var = sq * (1.0f / 128.0f) - mu * mu;
        float inv = rsqrtf(var + 1e-5f);
        if (node < N_NODES) {
            float4* ov = (float4*)(out_h + (size_t)node * H);
#pragma unroll
            for (int j = 0; j < 8; j++) {
                int c4 = part * 8 + j;
                float4 g = *(const float4*)(gamma + c4 * 4);
                float4 b = *(const float4*)(beta + c4 * 4);
                float4 v = vals[j];
                ov[c4] = make_float4((v.x - mu) * inv * g.x + b.x,
                                     (v.y - mu) * inv * g.y + b.y,
                                     (v.z - mu) * inv * g.z + b.z,
                                     (v.w - mu) * inv * g.w + b.w);
            }
        }
    }

    if (tid < 192) {
        int r = tid / 3, c = tid % 3;
        int node = nbase + r;
        if (node < N_NODES) {
            float cnt = fmaxf(g_agg_coord4[(size_t)node * 4 + 3], 1.0f);
            out_x[(size_t)node * 3 + c] = x[(size_t)node * 3 + c]
                                        + g_agg_coord4[(size_t)node * 4 + c] / cnt;
        }
    }
}

// ---------------------------------------------------------------------------
extern "C" void kernel_launch(void* const* d_in, const int* in_sizes, int n_in,
                              void* d_out, int out_size)
{
    const float* h    = (const float*)d_in[0];
    const float* x    = (const float*)d_in[1];
    const int*   eidx = (const int*)  d_in[2];
    const float* ea   = (const float*)d_in[3];
    const float* W1   = (const float*)d_in[4];
    const float* b1   = (const float*)d_in[5];
    const float* W2   = (const float*)d_in[6];
    const float* b2   = (const float*)d_in[7];
    const float* Wc1  = (const float*)d_in[8];
    const float* bc1  = (const float*)d_in[9];
    const float* Wc2  = (const float*)d_in[10];
    const float* bc2  = (const float*)d_in[11];
    const float* Wn1  = (const float*)d_in[12];
    const float* bn1  = (const float*)d_in[13];
    const float* Wn2  = (const float*)d_in[14];
    const float* bn2  = (const float*)d_in[15];
    const float* gamma = (const float*)d_in[16];
    const float* beta  = (const float*)d_in[17];

    float* out_h = (float*)d_out;
    float* out_x = out_h + (size_t)N_NODES * H;

    const int NODE_SMEM = (64 * H + 64 * H + 16 * H) * 4;
    cudaFuncSetAttribute(edge_kernel, cudaFuncAttributeMaxDynamicSharedMemorySize, EDGE_SMEM);
    cudaFuncSetAttribute(node_kernel, cudaFuncAttributeMaxDynamicSharedMemorySize, NODE_SMEM);

    zero_kernel<<<(N_NODES * H + 255) / 256, 256>>>();
    hbf_kernel<<<(N_NODES * 16 + 255) / 256, 256>>>(h);
    prep_kernel<<<(128 * 288 + 255) / 256, 256>>>(W1, 0, 260, 288);
    prep_kernel<<<(128 * 128 + 255) / 256, 256>>>(W2, 1, 128, 128);
    prep_kernel<<<(128 * 128 + 255) / 256, 256>>>(Wc1, 2, 128, 128);
    edge_kernel<<<N_EDGES / 128, 256, EDGE_SMEM>>>(x, eidx, ea, b1, b2, bc1, Wc2, bc2);
    node_kernel<<<(N_NODES + 63) / 64, 256, NODE_SMEM>>>(h, x, Wn1, bn1, Wn2, bn2,
                                                         gamma, beta, out_h, out_x);
}

// round 10
// speedup vs baseline: 4.8536x; 1.1951x over previous
#include <cuda_runtime.h>
#include <cuda_fp16.h>
#include <cstdint>

#define N_NODES 50000
#define N_EDGES 800000
#define H 128

// ---------------- device scratch ----------------
__device__ __align__(16) float g_agg_msg[(size_t)N_NODES * H];
__device__ __align__(16) float g_agg_coord4[(size_t)N_NODES * 4];  // x,y,z,count
// Weights as 8x8 b16 ldmatrix tiles, single fp16 plane, chunked by k32 (4096 ushorts/chunk).
__device__ __align__(16) unsigned short g_W1b[9 * 4096];
__device__ __align__(16) unsigned short g_W2b[4 * 4096];
__device__ __align__(16) unsigned short g_Wc1b[4 * 4096];
// h pre-converted to fp16 16B groups: [node][chunk(4)][group(4)] uint4
__device__ __align__(16) uint4 g_hbf[(size_t)N_NODES * 16];

// ---------------- helpers ----------------
__device__ __forceinline__ uint32_t smem_u32(const void* p) {
    uint32_t a;
    asm("{ .reg .u64 t; cvta.to.shared.u64 t, %1; cvt.u32.u64 %0, t; }" : "=r"(a) : "l"(p));
    return a;
}
__device__ __forceinline__ float h16rt(float v) {
    return __half2float(__float2half_rn(v));
}
__device__ __forceinline__ uint32_t pack2h(float a, float b) {
    __half2 hh = __floats2half2_rn(a, b);
    return *(uint32_t*)&hh;
}
__device__ __forceinline__ float silu_f(float v) {
    return v * (1.0f / (1.0f + __expf(-v)));
}
__device__ __forceinline__ void redv2(float* p, float a, float b) {
    asm volatile("red.global.add.v2.f32 [%0], {%1, %2};" :: "l"(p), "f"(a), "f"(b) : "memory");
}
__device__ __forceinline__ void redv4(float* p, float a, float b, float c, float d) {
    asm volatile("red.global.add.v4.f32 [%0], {%1, %2, %3, %4};"
                 :: "l"(p), "f"(a), "f"(b), "f"(c), "f"(d) : "memory");
}
__device__ __forceinline__ void ldm4(uint32_t* r, uint32_t addr) {
    asm volatile("ldmatrix.sync.aligned.m8n8.x4.shared.b16 {%0,%1,%2,%3}, [%4];"
                 : "=r"(r[0]), "=r"(r[1]), "=r"(r[2]), "=r"(r[3]) : "r"(addr));
}
__device__ __forceinline__ void mma_f16(float* d, const uint32_t* a, uint32_t b0, uint32_t b1) {
    asm volatile("mma.sync.aligned.m16n8k16.row.col.f32.f16.f16.f32 "
                 "{%0,%1,%2,%3}, {%4,%5,%6,%7}, {%8,%9}, {%0,%1,%2,%3};"
                 : "+f"(d[0]), "+f"(d[1]), "+f"(d[2]), "+f"(d[3])
                 : "r"(a[0]), "r"(a[1]), "r"(a[2]), "r"(a[3]), "r"(b0), "r"(b1));
}
__device__ __forceinline__ void cp_async16(uint32_t dst, const void* src) {
    asm volatile("cp.async.cg.shared.global [%0], [%1], 16;" :: "r"(dst), "l"(src) : "memory");
}
#define CP_COMMIT  asm volatile("cp.async.commit_group;" ::: "memory")
#define CP_WAIT_0  asm volatile("cp.async.wait_group 0;" ::: "memory")

// A-plane XOR swizzle: 64B row stride, 16B groups permuted by g ^= (row>>1)&3.
__device__ __forceinline__ uint32_t aswz(int row, int byteInRow) {
    int g = byteInRow >> 4;
    int inner = byteInRow & 15;
    return (uint32_t)(row * 64 + (((g ^ ((row >> 1) & 3)) << 4) | inner));
}

// ---------------- smem layout (edge kernel) ----------------
#define AF_OFF   0         // 4 slots x 8192 (single fp16 plane each) = 32768
#define BB_OFF   32768     // B double buffer: 2 x 8192
#define BIAS_OFF 49152     // b1,b2,bc1,Wc2 : 4*512
#define REL_OFF  51200
#define EA_OFF   52736
#define DSQ_OFF  54272
#define SRC_OFF  54784
#define DST_OFF  55296
#define PW_OFF   55808     // 2*128 floats
#define EDGE_SMEM 56832    // ~55.5 KB -> 2 CTAs/SM easily

// ---------------- zero / prep ----------------
__global__ void zero_kernel()
{
    int i = blockIdx.x * blockDim.x + threadIdx.x;
    if (i < N_NODES * H) g_agg_msg[i] = 0.0f;
    if (i < N_NODES * 4) g_agg_coord4[i] = 0.0f;
}

// h[N,128] -> fp16 groups. One thread per (node, 8-col group).
__global__ void hbf_kernel(const float* __restrict__ h)
{
    int idx = blockIdx.x * blockDim.x + threadIdx.x;
    if (idx >= N_NODES * 16) return;
    int node = idx >> 4;
    int gg = idx & 15;            // chunk*4 + g
    const float* src = h + (size_t)node * H + gg * 8;
    uint32_t w[4];
#pragma unroll
    for (int i = 0; i < 4; i++)
        w[i] = pack2h(src[i * 2], src[i * 2 + 1]);
    g_hbf[(size_t)node * 16 + gg] = make_uint4(w[0], w[1], w[2], w[3]);
}

// W[K,128] -> single fp16 plane as 8x8 b16 ldmatrix tiles.
// chunk(k32) image = 4096 ushorts; tile idx = ks*32 + nf*2 + khalf (nf 0..15)
__global__ void prep_kernel(const float* __restrict__ W, int which, int Kact, int Kpad)
{
    int idx = blockIdx.x * blockDim.x + threadIdx.x;
    if (idx >= 128 * Kpad) return;
    int k = idx >> 7;
    int n = idx & 127;
    float v = (k < Kact) ? W[k * 128 + n] : 0.0f;
    int chunk = k >> 5, ks = (k >> 4) & 1, khalf = (k >> 3) & 1, kin = k & 7;
    int nf = n >> 3, nin = n & 7;
    unsigned short* dst = (which == 0) ? g_W1b : (which == 1) ? g_W2b : g_Wc1b;
    int tile = ks * 32 + nf * 2 + khalf;
    __half hh = __float2half_rn(v);
    dst[chunk * 4096 + tile * 64 + nin * 8 + kin] = *(unsigned short*)&hh;
}

// ---------------- edge kernel pieces ----------------
__device__ __forceinline__ void init_d(float d[2][8][4], const float* sBias,
                                       int stage, int lane, int wc)
{
#pragma unroll
    for (int nf = 0; nf < 8; nf++) {
        int c0 = wc * 64 + nf * 8 + (lane & 3) * 2;
        float b0v = sBias[stage * 128 + c0];
        float b1v = sBias[stage * 128 + c0 + 1];
#pragma unroll
        for (int mf = 0; mf < 2; mf++) {
            d[mf][nf][0] = b0v; d[mf][nf][1] = b1v;
            d[mf][nf][2] = b0v; d[mf][nf][3] = b1v;
        }
    }
}

// prefetch B chunk cg into buf cg&1 via cp.async; commits the group.
__device__ __forceinline__ void issueB(uint32_t sbase, int cg, int tid)
{
    int stage = (cg < 9) ? 0 : ((cg < 13) ? 1 : 2);
    int cin = cg - ((stage == 0) ? 0 : (stage == 1) ? 9 : 13);
    const unsigned short* gW = (stage == 0) ? g_W1b : (stage == 1) ? g_W2b : g_Wc1b;
    const uint4* bsrc = (const uint4*)(gW + (size_t)cin * 4096);
    uint32_t bdst = sbase + BB_OFF + (uint32_t)(cg & 1) * 8192;
    int niter = (cg == 8) ? 1 : 2;  // tail chunk: only ks=0 tiles (first 4KB)
#pragma unroll
    for (int i = 0; i < 2; i++) {
        if (i < niter)
            cp_async16(bdst + (uint32_t)(tid + i * 256) * 16, bsrc + tid + i * 256);
    }
    CP_COMMIT;
}

// issue A-gather for chunk cn (0..7) from precomputed g_hbf, into slot cn&3.
__device__ __forceinline__ void issueA(uint32_t sbase, int cn, const int* sSrc,
                                       const int* sDst, int row, int halfq)
{
    int node = ((cn < 4) ? sSrc : sDst)[row];
    int cb = cn & 3;
    const uint4* src = g_hbf + (size_t)node * 16 + cb * 4;
    uint32_t dstBase = sbase + AF_OFF + (uint32_t)(cn & 3) * 8192;
#pragma unroll
    for (int j = 0; j < 2; j++) {
        int g = halfq * 2 + j;
        cp_async16(dstBase + aswz(row, g * 16), src + g);
    }
}

// TAIL=false: 1-product (A fp16, B fp16). TAIL=true: 1 k-step, 2-product
// (A hi in slot0 plane, A lo in slot1 plane; B single).
template<int NKS, bool TAIL>
__device__ __forceinline__ void do_mma(uint32_t sbase, uint32_t bBuf,
                                       int slot, int lane, int wm, int wc,
                                       float d[2][8][4])
{
    uint32_t chunkBase = sbase + AF_OFF + (uint32_t)slot * 8192;
    uint32_t bRow = (uint32_t)(((lane >> 3) << 7) + ((lane & 7) << 4));
#pragma unroll
    for (int ks = 0; ks < NKS; ks++) {
        int kbyte = ks * 32 + ((lane & 16) ? 16 : 0);
        uint32_t aHi[2][4], aLo[2][4];
#pragma unroll
        for (int mf = 0; mf < 2; mf++) {
            int row = wm * 32 + mf * 16 + (lane & 15);
            uint32_t ad = chunkBase + aswz(row, kbyte);
            ldm4(aHi[mf], ad);
            if (TAIL) ldm4(aLo[mf], ad + 8192);  // next slot's plane holds A-lo
        }
        uint32_t tB = bBuf + (uint32_t)(ks * 32 + wc * 16) * 128 + bRow;
#pragma unroll
        for (int q = 0; q < 4; q++) {
            uint32_t bh[4];
            ldm4(bh, tB + q * 512);
#pragma unroll
            for (int j = 0; j < 2; j++) {
                int nf = q * 2 + j;
#pragma unroll
                for (int mf = 0; mf < 2; mf++) {
                    mma_f16(d[mf][nf], aHi[mf], bh[j * 2], bh[j * 2 + 1]);
                    if (TAIL) mma_f16(d[mf][nf], aLo[mf], bh[j * 2], bh[j * 2 + 1]);
                }
            }
        }
    }
}

// epilogue: silu(d) -> (STAGE 0/1: write fp16 A plane; STAGE 1: + red agg_msg;
//                       STAGE 2: dot Wc2 -> coord red)
template<int STAGE>
__device__ __forceinline__ void epilogue(char* sb, float d[2][8][4],
                                         const int* sDst, const float* sRel,
                                         const float* bc2, float* sPw,
                                         int tid, int lane, int wm, int wc)
{
    __syncthreads();  // all warps done reading A / B
    const float* sBias = (const float*)(sb + BIAS_OFF);
    float pw0[2] = {0.f, 0.f}, pw1[2] = {0.f, 0.f};
#pragma unroll
    for (int mf = 0; mf < 2; mf++) {
        int r0 = wm * 32 + mf * 16 + (lane >> 2);
        int r1 = r0 + 8;
#pragma unroll
        for (int nf = 0; nf < 8; nf++) {
            int c0 = wc * 64 + nf * 8 + (lane & 3) * 2;
            float v0 = silu_f(d[mf][nf][0]);
            float v1 = silu_f(d[mf][nf][1]);
            float v2 = silu_f(d[mf][nf][2]);
            float v3 = silu_f(d[mf][nf][3]);
            if (STAGE == 2) {
                float w0 = sBias[384 + c0], w1 = sBias[384 + c0 + 1];
                pw0[mf] += v0 * w0 + v1 * w1;
                pw1[mf] += v2 * w0 + v3 * w1;
            } else {
                if (STAGE == 1) {
                    redv2(&g_agg_msg[(size_t)sDst[r0] * H + c0], v0, v1);
                    redv2(&g_agg_msg[(size_t)sDst[r1] * H + c0], v2, v3);
                }
                int chunk = c0 >> 5;
                int byte0 = (c0 & 31) * 2;
                char* chunkBase = sb + AF_OFF + chunk * 8192;
                *(uint32_t*)(chunkBase + aswz(r0, byte0)) = pack2h(v0, v1);
                *(uint32_t*)(chunkBase + aswz(r1, byte0)) = pack2h(v2, v3);
            }
        }
    }
    if (STAGE == 2) {
#pragma unroll
        for (int o = 1; o < 4; o <<= 1) {
            pw0[0] += __shfl_xor_sync(0xffffffffu, pw0[0], o);
            pw0[1] += __shfl_xor_sync(0xffffffffu, pw0[1], o);
            pw1[0] += __shfl_xor_sync(0xffffffffu, pw1[0], o);
            pw1[1] += __shfl_xor_sync(0xffffffffu, pw1[1], o);
        }
        if ((lane & 3) == 0) {
            int r = wm * 32 + (lane >> 2);
            sPw[wc * 128 + r]      = pw0[0];
            sPw[wc * 128 + r + 8]  = pw1[0];
            sPw[wc * 128 + r + 16] = pw0[1];
            sPw[wc * 128 + r + 24] = pw1[1];
        }
        __syncthreads();
        if (tid < 128) {
            float w = sPw[tid] + sPw[128 + tid] + bc2[0];
            int dd = sDst[tid];
            redv4(&g_agg_coord4[(size_t)dd * 4],
                  sRel[tid * 3 + 0] * w, sRel[tid * 3 + 1] * w, sRel[tid * 3 + 2] * w, 1.0f);
        }
    }
}

__global__ __launch_bounds__(256, 2) void edge_kernel(
    const float* __restrict__ x,
    const int*   __restrict__ ei, const float* __restrict__ ea,
    const float* __restrict__ b1, const float* __restrict__ b2,
    const float* __restrict__ bc1, const float* __restrict__ Wc2,
    const float* __restrict__ bc2)
{
    extern __shared__ char sb[];
    uint32_t sbase = smem_u32(sb);
    int tid = threadIdx.x, lane = tid & 31, wid = tid >> 5;
    int wm = wid & 3, wc = wid >> 2;
    int ebase = blockIdx.x * 128;

    float* sBias = (float*)(sb + BIAS_OFF);
    float* sRel  = (float*)(sb + REL_OFF);
    float* sEa   = (float*)(sb + EA_OFF);
    float* sDsq  = (float*)(sb + DSQ_OFF);
    int*   sSrc  = (int*)(sb + SRC_OFF);
    int*   sDst  = (int*)(sb + DST_OFF);
    float* sPw   = (float*)(sb + PW_OFF);

    if (tid < 128) {
        sBias[tid]       = b1[tid];
        sBias[128 + tid] = b2[tid];
        sBias[256 + tid] = bc1[tid];
        sBias[384 + tid] = Wc2[tid];
        int e = ebase + tid;
        int s = ei[e];
        int dd = ei[N_EDGES + e];
        sSrc[tid] = s; sDst[tid] = dd;
        float rx = x[s * 3 + 0] - x[dd * 3 + 0];
        float ry = x[s * 3 + 1] - x[dd * 3 + 1];
        float rz = x[s * 3 + 2] - x[dd * 3 + 2];
        sRel[tid * 3 + 0] = rx; sRel[tid * 3 + 1] = ry; sRel[tid * 3 + 2] = rz;
        sDsq[tid] = rx * rx + ry * ry + rz * rz;
        sEa[tid * 3 + 0] = ea[e * 3 + 0];
        sEa[tid * 3 + 1] = ea[e * 3 + 1];
        sEa[tid * 3 + 2] = ea[e * 3 + 2];
    }
    __syncthreads();

    float d[2][8][4];
    int row = tid >> 1, halfq = tid & 1;

    // ================= STAGE 0 : 9 chunks, race-free pipeline =================
    init_d(d, sBias, 0, lane, wc);
    issueA(sbase, 0, sSrc, sDst, row, halfq);
    issueB(sbase, 0, tid);   // commits group (A(0)+B(0))
#pragma unroll 1
    for (int c = 0; c < 9; c++) {
        CP_WAIT_0;            // A(c)+B(c) complete
        __syncthreads();      // publish; prior readers of reused buffers done
        bool pf = (c < 7);
        if (pf) issueA(sbase, c + 1, sSrc, sDst, row, halfq);
        issueB(sbase, c + 1, tid);   // commits group (c+1 in [1,9])
        uint32_t bBuf = sbase + BB_OFF + (uint32_t)(c & 1) * 8192;
        if (c == 8) do_mma<1, true>(sbase, bBuf, 0, lane, wm, wc, d);
        else        do_mma<2, false>(sbase, bBuf, c & 3, lane, wm, wc, d);
        if (c == 7) {
            // build tail chunk 8: A-hi in slot0 plane, A-lo in slot1 plane.
            // (slots 0/1 last read at c=4/5; safe to overwrite, published by c=8 barrier)
            char* base = sb + AF_OFF + (halfq ? 8192 : 0);
            uint32_t* p0 = (uint32_t*)(base + aswz(row, 0));
            if (halfq == 0) {
                p0[0] = pack2h(sEa[row * 3 + 0], sEa[row * 3 + 1]);
                p0[1] = pack2h(sEa[row * 3 + 2], sDsq[row]);
            } else {
                float e0 = sEa[row * 3 + 0], e1 = sEa[row * 3 + 1];
                float e2 = sEa[row * 3 + 2], dq = sDsq[row];
                p0[0] = pack2h(e0 - h16rt(e0), e1 - h16rt(e1));
                p0[1] = pack2h(e2 - h16rt(e2), dq - h16rt(dq));
            }
            p0[2] = 0u; p0[3] = 0u;
            uint32_t* p1 = (uint32_t*)(base + aswz(row, 16));
            p1[0] = 0u; p1[1] = 0u; p1[2] = 0u; p1[3] = 0u;
        }
    }
    epilogue<0>(sb, d, sDst, sRel, bc2, sPw, tid, lane, wm, wc);

    // ================= STAGE 1 : chunks 9..12 (B(9) already in flight) =================
    init_d(d, sBias, 1, lane, wc);
#pragma unroll 1
    for (int c = 0; c < 4; c++) {
        int cg = 9 + c;
        CP_WAIT_0;
        __syncthreads();
        issueB(sbase, cg + 1, tid);  // 10..13
        do_mma<2, false>(sbase, sbase + BB_OFF + (uint32_t)(cg & 1) * 8192,
                         c, lane, wm, wc, d);
    }
    epilogue<1>(sb, d, sDst, sRel, bc2, sPw, tid, lane, wm, wc);

    // ================= STAGE 2 : chunks 13..16 (B(13) already in flight) =================
    init_d(d, sBias, 2, lane, wc);
#pragma unroll 1
    for (int c = 0; c < 4; c++) {
        int cg = 13 + c;
        CP_WAIT_0;
        __syncthreads();
        if (cg < 16) issueB(sbase, cg + 1, tid);
        do_mma<2, false>(sbase, sbase + BB_OFF + (uint32_t)(cg & 1) * 8192,
                         c, lane, wm, wc, d);
    }
    epilogue<2>(sb, d, sDst, sRel, bc2, sPw, tid, lane, wm, wc);
}

// ---------------- SIMT node kernel (64 nodes / block) ----------------
__device__ __forceinline__ void gemm128(const float* __restrict__ As,
                                        const float* __restrict__ Wg,
                                        float* sW, float acc[4][8],
                                        int tm, int tn, int tid)
{
    for (int kt = 0; kt < 128; kt += 16) {
        __syncthreads();
        const float4* Wv = (const float4*)(Wg + (size_t)kt * H);
        float4* sWv = (float4*)sW;
        sWv[tid]       = Wv[tid];
        sWv[tid + 256] = Wv[tid + 256];
        __syncthreads();
#pragma unroll
        for (int kk = 0; kk < 16; kk++) {
            float a[4];
#pragma unroll
            for (int m = 0; m < 4; m++) a[m] = As[(tm * 4 + m) * H + kt + kk];
            float4 w0 = *(const float4*)&sW[kk * H + tn * 8];
            float4 w1 = *(const float4*)&sW[kk * H + tn * 8 + 4];
#pragma unroll
            for (int m = 0; m < 4; m++) {
                acc[m][0] += a[m] * w0.x; acc[m][1] += a[m] * w0.y;
                acc[m][2] += a[m] * w0.z; acc[m][3] += a[m] * w0.w;
                acc[m][4] += a[m] * w1.x; acc[m][5] += a[m] * w1.y;
                acc[m][6] += a[m] * w1.z; acc[m][7] += a[m] * w1.w;
            }
        }
    }
}

__global__ __launch_bounds__(256, 2) void node_kernel(
    const float* __restrict__ h,   const float* __restrict__ x,
    const float* __restrict__ Wn1, const float* __restrict__ bn1,
    const float* __restrict__ Wn2, const float* __restrict__ bn2,
    const float* __restrict__ gamma, const float* __restrict__ beta,
    float* __restrict__ out_h, float* __restrict__ out_x)
{
    extern __shared__ float smem[];
    float* sA = smem;
    float* sB = sA + 64 * H;
    float* sW = sB + 64 * H;

    int tid = threadIdx.x;
    int tn = tid & 15;
    int tm = tid >> 4;
    int nbase = blockIdx.x * 64;

    {
        const float4* hv = (const float4*)h;
        const float4* av = (const float4*)g_agg_msg;
        float4* sA4 = (float4*)sA;
        float4* sB4 = (float4*)sB;
        float4 z = make_float4(0.f, 0.f, 0.f, 0.f);
#pragma unroll
        for (int j = 0; j < 8; j++) {
            int idx = tid + j * 256;
            int row = idx >> 5;
            int c4 = idx & 31;
            int node = nbase + row;
            if (node < N_NODES) {
                sA4[idx] = hv[(size_t)node * 32 + c4];
                sB4[idx] = av[(size_t)node * 32 + c4];
            } else { sA4[idx] = z; sB4[idx] = z; }
        }
    }

    float acc[4][8];
    {
        float4 b0 = *(const float4*)(bn1 + tn * 8);
        float4 b1v = *(const float4*)(bn1 + tn * 8 + 4);
#pragma unroll
        for (int m = 0; m < 4; m++) {
            acc[m][0] = b0.x; acc[m][1] = b0.y; acc[m][2] = b0.z; acc[m][3] = b0.w;
            acc[m][4] = b1v.x; acc[m][5] = b1v.y; acc[m][6] = b1v.z; acc[m][7] = b1v.w;
        }
    }
    gemm128(sA, Wn1, sW, acc, tm, tn, tid);
    gemm128(sB, Wn1 + 128 * H, sW, acc, tm, tn, tid);
#pragma unroll
    for (int m = 0; m < 4; m++)
#pragma unroll
        for (int n = 0; n < 8; n++)
            acc[m][n] = silu_f(acc[m][n]);
    __syncthreads();
#pragma unroll
    for (int m = 0; m < 4; m++) {
        int row = tm * 4 + m;
        *(float4*)&sB[row * H + tn * 8]     = make_float4(acc[m][0], acc[m][1], acc[m][2], acc[m][3]);
        *(float4*)&sB[row * H + tn * 8 + 4] = make_float4(acc[m][4], acc[m][5], acc[m][6], acc[m][7]);
    }

    {
        float4 b0 = *(const float4*)(bn2 + tn * 8);
        float4 b1v = *(const float4*)(bn2 + tn * 8 + 4);
#pragma unroll
        for (int m = 0; m < 4; m++) {
            acc[m][0] = b0.x; acc[m][1] = b0.y; acc[m][2] = b0.z; acc[m][3] = b0.w;
            acc[m][4] = b1v.x; acc[m][5] = b1v.y; acc[m][6] = b1v.z; acc[m][7] = b1v.w;
        }
    }
    gemm128(sB, Wn2, sW, acc, tm, tn, tid);

    __syncthreads();
#pragma unroll
    for (int m = 0; m < 4; m++) {
        int row = tm * 4 + m;
        float4 h0 = *(const float4*)&sA[row * H + tn * 8];
        float4 h1 = *(const float4*)&sA[row * H + tn * 8 + 4];
        *(float4*)&sB[row * H + tn * 8]     = make_float4(h0.x + acc[m][0], h0.y + acc[m][1], h0.z + acc[m][2], h0.w + acc[m][3]);
        *(float4*)&sB[row * H + tn * 8 + 4] = make_float4(h1.x + acc[m][4], h1.y + acc[m][5], h1.z + acc[m][6], h1.w + acc[m][7]);
    }
    __syncthreads();

    {
        int row = tid >> 2;
        int part = tid & 3;
        int node = nbase + row;
        const float4* yv = (const float4*)sB;
        float s = 0.f, sq = 0.f;
        float4 vals[8];
#pragma unroll
        for (int j = 0; j < 8; j++) {
            float4 v = yv[row * 32 + part * 8 + j];
            vals[j] = v;
            s  += v.x + v.y + v.z + v.w;
            sq += v.x * v.x + v.y * v.y + v.z * v.z + v.w * v.w;
        }
        s  += __shfl_xor_sync(0xffffffffu, s, 1);
        sq += __shfl_xor_sync(0xffffffffu, sq, 1);
        s  += __shfl_xor_sync(0xffffffffu, s, 2);
        sq += __shfl_xor_sync(0xffffffffu, sq, 2);
        float mu  = s * (1.0f / 128.0f);
        float var = sq * (1.0f / 128.0f) - mu * mu;
        float inv = rsqrtf(var + 1e-5f);
        if (node < N_NODES) {
            float4* ov = (float4*)(out_h + (size_t)node * H);
#pragma unroll
            for (int j = 0; j < 8; j++) {
                int c4 = part * 8 + j;
                float4 g = *(const float4*)(gamma + c4 * 4);
                float4 b = *(const float4*)(beta + c4 * 4);
                float4 v = vals[j];
                ov[c4] = make_float4((v.x - mu) * inv * g.x + b.x,
                                     (v.y - mu) * inv * g.y + b.y,
                                     (v.z - mu) * inv * g.z + b.z,
                                     (v.w - mu) * inv * g.w + b.w);
            }
        }
    }

    if (tid < 192) {
        int r = tid / 3, c = tid % 3;
        int node = nbase + r;
        if (node < N_NODES) {
            float cnt = fmaxf(g_agg_coord4[(size_t)node * 4 + 3], 1.0f);
            out_x[(size_t)node * 3 + c] = x[(size_t)node * 3 + c]
                                        + g_agg_coord4[(size_t)node * 4 + c] / cnt;
        }
    }
}

// ---------------------------------------------------------------------------
extern "C" void kernel_launch(void* const* d_in, const int* in_sizes, int n_in,
                              void* d_out, int out_size)
{
    const float* h    = (const float*)d_in[0];
    const float* x    = (const float*)d_in[1];
    const int*   eidx = (const int*)  d_in[2];
    const float* ea   = (const float*)d_in[3];
    const float* W1   = (const float*)d_in[4];
    const float* b1   = (const float*)d_in[5];
    const float* W2   = (const float*)d_in[6];
    const float* b2   = (const float*)d_in[7];
    const float* Wc1  = (const float*)d_in[8];
    const float* bc1  = (const float*)d_in[9];
    const float* Wc2  = (const float*)d_in[10];
    const float* bc2  = (const float*)d_in[11];
    const float* Wn1  = (const float*)d_in[12];
    const float* bn1  = (const float*)d_in[13];
    const float* Wn2  = (const float*)d_in[14];
    const float* bn2  = (const float*)d_in[15];
    const float* gamma = (const float*)d_in[16];
    const float* beta  = (const float*)d_in[17];

    float* out_h = (float*)d_out;
    float* out_x = out_h + (size_t)N_NODES * H;

    const int NODE_SMEM = (64 * H + 64 * H + 16 * H) * 4;
    cudaFuncSetAttribute(edge_kernel, cudaFuncAttributeMaxDynamicSharedMemorySize, EDGE_SMEM);
    cudaFuncSetAttribute(node_kernel, cudaFuncAttributeMaxDynamicSharedMemorySize, NODE_SMEM);

    zero_kernel<<<(N_NODES * H + 255) / 256, 256>>>();
    hbf_kernel<<<(N_NODES * 16 + 255) / 256, 256>>>(h);
    prep_kernel<<<(128 * 288 + 255) / 256, 256>>>(W1, 0, 260, 288);
    prep_kernel<<<(128 * 128 + 255) / 256, 256>>>(W2, 1, 128, 128);
    prep_kernel<<<(128 * 128 + 255) / 256, 256>>>(Wc1, 2, 128, 128);
    edge_kernel<<<N_EDGES / 128, 256, EDGE_SMEM>>>(x, eidx, ea, b1, b2, bc1, Wc2, bc2);
    node_kernel<<<(N_NODES + 63) / 64, 256, NODE_SMEM>>>(h, x, Wn1, bn1, Wn2, bn2,
                                                         gamma, beta, out_h, out_x);
}

// round 11
// speedup vs baseline: 4.9889x; 1.0279x over previous
#include <cuda_runtime.h>
#include <cuda_fp16.h>
#include <cstdint>

#define N_NODES 50000
#define N_EDGES 800000
#define H 128

// ---------------- device scratch ----------------
__device__ __align__(16) float g_agg_msg[(size_t)N_NODES * H];
__device__ __align__(16) float g_agg_coord4[(size_t)N_NODES * 4];  // x,y,z,count
// Weights as 8x8 b16 ldmatrix tiles, fp16, k64 chunk images (8192 ushorts = 16KB each).
__device__ __align__(16) unsigned short g_W1b[5 * 8192];   // K=288 -> 4 full + tail
__device__ __align__(16) unsigned short g_W2b[2 * 8192];
__device__ __align__(16) unsigned short g_Wc1b[2 * 8192];
// h pre-converted to fp16 16B groups: [node][k32chunk(4)][group(4)] uint4
__device__ __align__(16) uint4 g_hbf[(size_t)N_NODES * 16];

// ---------------- helpers ----------------
__device__ __forceinline__ uint32_t smem_u32(const void* p) {
    uint32_t a;
    asm("{ .reg .u64 t; cvta.to.shared.u64 t, %1; cvt.u32.u64 %0, t; }" : "=r"(a) : "l"(p));
    return a;
}
__device__ __forceinline__ float h16rt(float v) {
    return __half2float(__float2half_rn(v));
}
__device__ __forceinline__ uint32_t pack2h(float a, float b) {
    __half2 hh = __floats2half2_rn(a, b);
    return *(uint32_t*)&hh;
}
__device__ __forceinline__ float silu_f(float v) {
    return v * (1.0f / (1.0f + __expf(-v)));
}
__device__ __forceinline__ void redv2(float* p, float a, float b) {
    asm volatile("red.global.add.v2.f32 [%0], {%1, %2};" :: "l"(p), "f"(a), "f"(b) : "memory");
}
__device__ __forceinline__ void redv4(float* p, float a, float b, float c, float d) {
    asm volatile("red.global.add.v4.f32 [%0], {%1, %2, %3, %4};"
                 :: "l"(p), "f"(a), "f"(b), "f"(c), "f"(d) : "memory");
}
__device__ __forceinline__ void ldm4(uint32_t* r, uint32_t addr) {
    asm volatile("ldmatrix.sync.aligned.m8n8.x4.shared.b16 {%0,%1,%2,%3}, [%4];"
                 : "=r"(r[0]), "=r"(r[1]), "=r"(r[2]), "=r"(r[3]) : "r"(addr));
}
__device__ __forceinline__ void mma_f16(float* d, const uint32_t* a, uint32_t b0, uint32_t b1) {
    asm volatile("mma.sync.aligned.m16n8k16.row.col.f32.f16.f16.f32 "
                 "{%0,%1,%2,%3}, {%4,%5,%6,%7}, {%8,%9}, {%0,%1,%2,%3};"
                 : "+f"(d[0]), "+f"(d[1]), "+f"(d[2]), "+f"(d[3])
                 : "r"(a[0]), "r"(a[1]), "r"(a[2]), "r"(a[3]), "r"(b0), "r"(b1));
}
__device__ __forceinline__ void cp_async16(uint32_t dst, const void* src) {
    asm volatile("cp.async.cg.shared.global [%0], [%1], 16;" :: "r"(dst), "l"(src) : "memory");
}
#define CP_COMMIT  asm volatile("cp.async.commit_group;" ::: "memory")
#define CP_WAIT_0  asm volatile("cp.async.wait_group 0;" ::: "memory")

// A-plane XOR swizzle: 64B row stride, 16B groups permuted by g ^= (row>>1)&3.
__device__ __forceinline__ uint32_t aswz(int row, int byteInRow) {
    int g = byteInRow >> 4;
    int inner = byteInRow & 15;
    return (uint32_t)(row * 64 + (((g ^ ((row >> 1) & 3)) << 4) | inner));
}

// ---------------- smem layout (edge kernel) ----------------
#define AF_OFF   0         // 4 subslots x 8192 (each = 128 rows x 32 fp16 cols) = 32768
#define BB_OFF   32768     // B double buffer: 2 x 16384
#define BIAS_OFF 65536     // b1,b2,bc1,Wc2 : 4*512
#define REL_OFF  67584
#define EA_OFF   69120
#define DSQ_OFF  70656
#define SRC_OFF  71168
#define DST_OFF  71680
#define PW_OFF   72192     // 2*128 floats
#define EDGE_SMEM 73216    // ~71.5 KB -> 2 CTAs/SM

// ---------------- zero / prep ----------------
__global__ void zero_kernel()
{
    int i = blockIdx.x * blockDim.x + threadIdx.x;
    if (i < N_NODES * H) g_agg_msg[i] = 0.0f;
    if (i < N_NODES * 4) g_agg_coord4[i] = 0.0f;
}

// h[N,128] -> fp16 groups. One thread per (node, 8-col group).
__global__ void hbf_kernel(const float* __restrict__ h)
{
    int idx = blockIdx.x * blockDim.x + threadIdx.x;
    if (idx >= N_NODES * 16) return;
    int node = idx >> 4;
    int gg = idx & 15;            // k32chunk*4 + g
    const float* src = h + (size_t)node * H + gg * 8;
    uint32_t w[4];
#pragma unroll
    for (int i = 0; i < 4; i++)
        w[i] = pack2h(src[i * 2], src[i * 2 + 1]);
    g_hbf[(size_t)node * 16 + gg] = make_uint4(w[0], w[1], w[2], w[3]);
}

// W[K,128] -> fp16 as 8x8 b16 ldmatrix tiles, k64 chunk images.
// chunk(k64) image = 8192 ushorts; tile idx = ks*32 + nf*2 + khalf (ks 0..3, nf 0..15)
__global__ void prep_kernel(const float* __restrict__ W, int which, int Kact, int Kpad)
{
    int idx = blockIdx.x * blockDim.x + threadIdx.x;
    if (idx >= 128 * Kpad) return;
    int k = idx >> 7;
    int n = idx & 127;
    float v = (k < Kact) ? W[k * 128 + n] : 0.0f;
    int chunk = k >> 6, ks = (k >> 4) & 3, khalf = (k >> 3) & 1, kin = k & 7;
    int nf = n >> 3, nin = n & 7;
    unsigned short* dst = (which == 0) ? g_W1b : (which == 1) ? g_W2b : g_Wc1b;
    int tile = ks * 32 + nf * 2 + khalf;
    __half hh = __float2half_rn(v);
    dst[chunk * 8192 + tile * 64 + nin * 8 + kin] = *(unsigned short*)&hh;
}

// ---------------- edge kernel pieces ----------------
__device__ __forceinline__ void init_d(float d[2][8][4], const float* sBias,
                                       int stage, int lane, int wc)
{
#pragma unroll
    for (int nf = 0; nf < 8; nf++) {
        int c0 = wc * 64 + nf * 8 + (lane & 3) * 2;
        float b0v = sBias[stage * 128 + c0];
        float b1v = sBias[stage * 128 + c0 + 1];
#pragma unroll
        for (int mf = 0; mf < 2; mf++) {
            d[mf][nf][0] = b0v; d[mf][nf][1] = b1v;
            d[mf][nf][2] = b0v; d[mf][nf][3] = b1v;
        }
    }
}

// prefetch B chunk cg (global schedule 0..8) into buf cg&1; commits the group.
// cg 0..4 : W1 chunks 0..4 (4 = k32 tail, 4KB) ; cg 5,6 : W2 ; cg 7,8 : Wc1
__device__ __forceinline__ void issueB(uint32_t sbase, int cg, int tid)
{
    const unsigned short* gW;
    int cin;
    if (cg < 5)       { gW = g_W1b;  cin = cg; }
    else if (cg < 7)  { gW = g_W2b;  cin = cg - 5; }
    else              { gW = g_Wc1b; cin = cg - 7; }
    const uint4* bsrc = (const uint4*)(gW + (size_t)cin * 8192);
    uint32_t bdst = sbase + BB_OFF + (uint32_t)(cg & 1) * 16384;
    int niter = (cg == 4) ? 1 : 4;  // tail: only ks=0 tiles (first 4KB)
#pragma unroll
    for (int i = 0; i < 4; i++) {
        if (i < niter)
            cp_async16(bdst + (uint32_t)(tid + i * 256) * 16, bsrc + tid + i * 256);
    }
    CP_COMMIT;
}

// issue A-gather for k64 chunk cn (0..3) into subslot pair (cn&1)*2, (cn&1)*2+1.
__device__ __forceinline__ void issueA(uint32_t sbase, int cn, const int* sSrc,
                                       const int* sDst, int row, int halfq)
{
    int node = ((cn < 2) ? sSrc : sDst)[row];
    const uint4* hbase = g_hbf + (size_t)node * 16 + (cn & 1) * 8;
    uint32_t dstBase = sbase + AF_OFF + (uint32_t)((cn & 1) * 2) * 8192;
#pragma unroll
    for (int sub = 0; sub < 2; sub++) {
#pragma unroll
        for (int j = 0; j < 2; j++) {
            int g = halfq * 2 + j;
            cp_async16(dstBase + (uint32_t)sub * 8192 + aswz(row, g * 16),
                       hbase + sub * 4 + g);
        }
    }
}

// TAIL=false: NKS k16-steps, 1 product. TAIL=true: 1 k-step, 2 products
// (A hi in subslot 0, A lo in subslot 1).
template<int NKS, bool TAIL>
__device__ __forceinline__ void do_mma(uint32_t sbase, uint32_t bBuf, uint32_t aOff,
                                       int lane, int wm, int wc, float d[2][8][4])
{
    uint32_t aRegion = sbase + AF_OFF + aOff;
    uint32_t bRow = (uint32_t)(((lane >> 3) << 7) + ((lane & 7) << 4));
#pragma unroll
    for (int ks = 0; ks < NKS; ks++) {
        int kbyte = (ks & 1) * 32 + ((lane & 16) ? 16 : 0);
        uint32_t subOff = (uint32_t)(ks >> 1) * 8192;
        uint32_t aHi[2][4], aLo[2][4];
#pragma unroll
        for (int mf = 0; mf < 2; mf++) {
            int row = wm * 32 + mf * 16 + (lane & 15);
            uint32_t ad = aRegion + subOff + aswz(row, kbyte);
            ldm4(aHi[mf], ad);
            if (TAIL) ldm4(aLo[mf], ad + 8192);
        }
        uint32_t tB = bBuf + (uint32_t)(ks * 32 + wc * 16) * 128 + bRow;
#pragma unroll
        for (int q = 0; q < 4; q++) {
            uint32_t bh[4];
            ldm4(bh, tB + q * 512);
#pragma unroll
            for (int j = 0; j < 2; j++) {
                int nf = q * 2 + j;
#pragma unroll
                for (int mf = 0; mf < 2; mf++) {
                    mma_f16(d[mf][nf], aHi[mf], bh[j * 2], bh[j * 2 + 1]);
                    if (TAIL) mma_f16(d[mf][nf], aLo[mf], bh[j * 2], bh[j * 2 + 1]);
                }
            }
        }
    }
}

// epilogue: silu(d) -> (STAGE 0/1: write fp16 A subslots; STAGE 1: + red agg_msg;
//                       STAGE 2: dot Wc2 -> coord red)
template<int STAGE>
__device__ __forceinline__ void epilogue(char* sb, float d[2][8][4],
                                         const int* sDst, const float* sRel,
                                         const float* bc2, float* sPw,
                                         int tid, int lane, int wm, int wc)
{
    __syncthreads();  // all warps done reading A / B
    const float* sBias = (const float*)(sb + BIAS_OFF);
    float pw0[2] = {0.f, 0.f}, pw1[2] = {0.f, 0.f};
#pragma unroll
    for (int mf = 0; mf < 2; mf++) {
        int r0 = wm * 32 + mf * 16 + (lane >> 2);
        int r1 = r0 + 8;
#pragma unroll
        for (int nf = 0; nf < 8; nf++) {
            int c0 = wc * 64 + nf * 8 + (lane & 3) * 2;
            float v0 = silu_f(d[mf][nf][0]);
            float v1 = silu_f(d[mf][nf][1]);
            float v2 = silu_f(d[mf][nf][2]);
            float v3 = silu_f(d[mf][nf][3]);
            if (STAGE == 2) {
                float w0 = sBias[384 + c0], w1 = sBias[384 + c0 + 1];
                pw0[mf] += v0 * w0 + v1 * w1;
                pw1[mf] += v2 * w0 + v3 * w1;
            } else {
                if (STAGE == 1) {
                    redv2(&g_agg_msg[(size_t)sDst[r0] * H + c0], v0, v1);
                    redv2(&g_agg_msg[(size_t)sDst[r1] * H + c0], v2, v3);
                }
                int sub = c0 >> 5;
                int byte0 = (c0 & 31) * 2;
                char* subBase = sb + AF_OFF + sub * 8192;
                *(uint32_t*)(subBase + aswz(r0, byte0)) = pack2h(v0, v1);
                *(uint32_t*)(subBase + aswz(r1, byte0)) = pack2h(v2, v3);
            }
        }
    }
    if (STAGE == 2) {
#pragma unroll
        for (int o = 1; o < 4; o <<= 1) {
            pw0[0] += __shfl_xor_sync(0xffffffffu, pw0[0], o);
            pw0[1] += __shfl_xor_sync(0xffffffffu, pw0[1], o);
            pw1[0] += __shfl_xor_sync(0xffffffffu, pw1[0], o);
            pw1[1] += __shfl_xor_sync(0xffffffffu, pw1[1], o);
        }
        if ((lane & 3) == 0) {
            int r = wm * 32 + (lane >> 2);
            sPw[wc * 128 + r]      = pw0[0];
            sPw[wc * 128 + r + 8]  = pw1[0];
            sPw[wc * 128 + r + 16] = pw0[1];
            sPw[wc * 128 + r + 24] = pw1[1];
        }
        __syncthreads();
        if (tid < 128) {
            float w = sPw[tid] + sPw[128 + tid] + bc2[0];
            int dd = sDst[tid];
            redv4(&g_agg_coord4[(size_t)dd * 4],
                  sRel[tid * 3 + 0] * w, sRel[tid * 3 + 1] * w, sRel[tid * 3 + 2] * w, 1.0f);
        }
    }
}

__global__ __launch_bounds__(256, 2) void edge_kernel(
    const float* __restrict__ x,
    const int*   __restrict__ ei, const float* __restrict__ ea,
    const float* __restrict__ b1, const float* __restrict__ b2,
    const float* __restrict__ bc1, const float* __restrict__ Wc2,
    const float* __restrict__ bc2)
{
    extern __shared__ char sb[];
    uint32_t sbase = smem_u32(sb);
    int tid = threadIdx.x, lane = tid & 31, wid = tid >> 5;
    int wm = wid & 3, wc = wid >> 2;
    int ebase = blockIdx.x * 128;

    float* sBias = (float*)(sb + BIAS_OFF);
    float* sRel  = (float*)(sb + REL_OFF);
    float* sEa   = (float*)(sb + EA_OFF);
    float* sDsq  = (float*)(sb + DSQ_OFF);
    int*   sSrc  = (int*)(sb + SRC_OFF);
    int*   sDst  = (int*)(sb + DST_OFF);
    float* sPw   = (float*)(sb + PW_OFF);

    if (tid < 128) {
        sBias[tid]       = b1[tid];
        sBias[128 + tid] = b2[tid];
        sBias[256 + tid] = bc1[tid];
        sBias[384 + tid] = Wc2[tid];
        int e = ebase + tid;
        int s = ei[e];
        int dd = ei[N_EDGES + e];
        sSrc[tid] = s; sDst[tid] = dd;
        float rx = x[s * 3 + 0] - x[dd * 3 + 0];
        float ry = x[s * 3 + 1] - x[dd * 3 + 1];
        float rz = x[s * 3 + 2] - x[dd * 3 + 2];
        sRel[tid * 3 + 0] = rx; sRel[tid * 3 + 1] = ry; sRel[tid * 3 + 2] = rz;
        sDsq[tid] = rx * rx + ry * ry + rz * rz;
        sEa[tid * 3 + 0] = ea[e * 3 + 0];
        sEa[tid * 3 + 1] = ea[e * 3 + 1];
        sEa[tid * 3 + 2] = ea[e * 3 + 2];
    }
    __syncthreads();

    float d[2][8][4];
    int row = tid >> 1, halfq = tid & 1;

    // ================= STAGE 0 : 5 chunks (4x k64 + k32 tail) =================
    init_d(d, sBias, 0, lane, wc);
    issueA(sbase, 0, sSrc, sDst, row, halfq);
    issueB(sbase, 0, tid);   // commits group (A(0)+B(0))
#pragma unroll 1
    for (int c = 0; c < 5; c++) {
        CP_WAIT_0;            // A(c)+B(c) complete
        __syncthreads();      // publish; prior readers of reused buffers done
        bool pf = (c < 3);
        if (pf) issueA(sbase, c + 1, sSrc, sDst, row, halfq);
        issueB(sbase, c + 1, tid);   // c+1 in [1,5]
        uint32_t bBuf = sbase + BB_OFF + (uint32_t)(c & 1) * 16384;
        if (c == 4) do_mma<1, true>(sbase, bBuf, 0, lane, wm, wc, d);
        else        do_mma<4, false>(sbase, bBuf, (uint32_t)(c & 1) * 16384, lane, wm, wc, d);
        if (c == 3) {
            // build tail: A-hi in subslot 0, A-lo in subslot 1 (k16 used).
            // Subslots 0,1 last read at c=2; published by c=4's barrier.
            char* base = sb + AF_OFF + (halfq ? 8192 : 0);
            uint32_t* p0 = (uint32_t*)(base + aswz(row, 0));
            if (halfq == 0) {
                p0[0] = pack2h(sEa[row * 3 + 0], sEa[row * 3 + 1]);
                p0[1] = pack2h(sEa[row * 3 + 2], sDsq[row]);
            } else {
                float e0 = sEa[row * 3 + 0], e1 = sEa[row * 3 + 1];
                float e2 = sEa[row * 3 + 2], dq = sDsq[row];
                p0[0] = pack2h(e0 - h16rt(e0), e1 - h16rt(e1));
                p0[1] = pack2h(e2 - h16rt(e2), dq - h16rt(dq));
            }
            p0[2] = 0u; p0[3] = 0u;
            uint32_t* p1 = (uint32_t*)(base + aswz(row, 16));
            p1[0] = 0u; p1[1] = 0u; p1[2] = 0u; p1[3] = 0u;
        }
    }
    epilogue<0>(sb, d, sDst, sRel, bc2, sPw, tid, lane, wm, wc);

    // ================= STAGE 1 : chunks 5,6 (B(5) already in flight) =================
    init_d(d, sBias, 1, lane, wc);
#pragma unroll 1
    for (int c = 0; c < 2; c++) {
        int cg = 5 + c;
        CP_WAIT_0;
        __syncthreads();
        issueB(sbase, cg + 1, tid);  // 6,7
        do_mma<4, false>(sbase, sbase + BB_OFF + (uint32_t)(cg & 1) * 16384,
                         (uint32_t)c * 16384, lane, wm, wc, d);
    }
    epilogue<1>(sb, d, sDst, sRel, bc2, sPw, tid, lane, wm, wc);

    // ================= STAGE 2 : chunks 7,8 (B(7) already in flight) =================
    init_d(d, sBias, 2, lane, wc);
#pragma unroll 1
    for (int c = 0; c < 2; c++) {
        int cg = 7 + c;
        CP_WAIT_0;
        __syncthreads();
        if (cg < 8) issueB(sbase, cg + 1, tid);
        do_mma<4, false>(sbase, sbase + BB_OFF + (uint32_t)(cg & 1) * 16384,
                         (uint32_t)c * 16384, lane, wm, wc, d);
    }
    epilogue<2>(sb, d, sDst, sRel, bc2, sPw, tid, lane, wm, wc);
}

// ---------------- SIMT node kernel (64 nodes / block) ----------------
__device__ __forceinline__ void gemm128(const float* __restrict__ As,
                                        const float* __restrict__ Wg,
                                        float* sW, float acc[4][8],
                                        int tm, int tn, int tid)
{
    for (int kt = 0; kt < 128; kt += 16) {
        __syncthreads();
        const float4* Wv = (const float4*)(Wg + (size_t)kt * H);
        float4* sWv = (float4*)sW;
        sWv[tid]       = Wv[tid];
        sWv[tid + 256] = Wv[tid + 256];
        __syncthreads();
#pragma unroll
        for (int kk = 0; kk < 16; kk++) {
            float a[4];
#pragma unroll
            for (int m = 0; m < 4; m++) a[m] = As[(tm * 4 + m) * H + kt + kk];
            float4 w0 = *(const float4*)&sW[kk * H + tn * 8];
            float4 w1 = *(const float4*)&sW[kk * H + tn * 8 + 4];
#pragma unroll
            for (int m = 0; m < 4; m++) {
                acc[m][0] += a[m] * w0.x; acc[m][1] += a[m] * w0.y;
                acc[m][2] += a[m] * w0.z; acc[m][3] += a[m] * w0.w;
                acc[m][4] += a[m] * w1.x; acc[m][5] += a[m] * w1.y;
                acc[m][6] += a[m] * w1.z; acc[m][7] += a[m] * w1.w;
            }
        }
    }
}

__global__ __launch_bounds__(256, 2) void node_kernel(
    const float* __restrict__ h,   const float* __restrict__ x,
    const float* __restrict__ Wn1, const float* __restrict__ bn1,
    const float* __restrict__ Wn2, const float* __restrict__ bn2,
    const float* __restrict__ gamma, const float* __restrict__ beta,
    float* __restrict__ out_h, float* __restrict__ out_x)
{
    extern __shared__ float smem[];
    float* sA = smem;
    float* sB = sA + 64 * H;
    float* sW = sB + 64 * H;

    int tid = threadIdx.x;
    int tn = tid & 15;
    int tm = tid >> 4;
    int nbase = blockIdx.x * 64;

    {
        const float4* hv = (const float4*)h;
        const float4* av = (const float4*)g_agg_msg;
        float4* sA4 = (float4*)sA;
        float4* sB4 = (float4*)sB;
        float4 z = make_float4(0.f, 0.f, 0.f, 0.f);
#pragma unroll
        for (int j = 0; j < 8; j++) {
            int idx = tid + j * 256;
            int row = idx >> 5;
            int c4 = idx & 31;
            int node = nbase + row;
            if (node < N_NODES) {
                sA4[idx] = hv[(size_t)node * 32 + c4];
                sB4[idx] = av[(size_t)node * 32 + c4];
            } else { sA4[idx] = z; sB4[idx] = z; }
        }
    }

    float acc[4][8];
    {
        float4 b0 = *(const float4*)(bn1 + tn * 8);
        float4 b1v = *(const float4*)(bn1 + tn * 8 + 4);
#pragma unroll
        for (int m = 0; m < 4; m++) {
            acc[m][0] = b0.x; acc[m][1] = b0.y; acc[m][2] = b0.z; acc[m][3] = b0.w;
            acc[m][4] = b1v.x; acc[m][5] = b1v.y; acc[m][6] = b1v.z; acc[m][7] = b1v.w;
        }
    }
    gemm128(sA, Wn1, sW, acc, tm, tn, tid);
    gemm128(sB, Wn1 + 128 * H, sW, acc, tm, tn, tid);
#pragma unroll
    for (int m = 0; m < 4; m++)
#pragma unroll
        for (int n = 0; n < 8; n++)
            acc[m][n] = silu_f(acc[m][n]);
    __syncthreads();
#pragma unroll
    for (int m = 0; m < 4; m++) {
        int row = tm * 4 + m;
        *(float4*)&sB[row * H + tn * 8]     = make_float4(acc[m][0], acc[m][1], acc[m][2], acc[m][3]);
        *(float4*)&sB[row * H + tn * 8 + 4] = make_float4(acc[m][4], acc[m][5], acc[m][6], acc[m][7]);
    }

    {
        float4 b0 = *(const float4*)(bn2 + tn * 8);
        float4 b1v = *(const float4*)(bn2 + tn * 8 + 4);
#pragma unroll
        for (int m = 0; m < 4; m++) {
            acc[m][0] = b0.x; acc[m][1] = b0.y; acc[m][2] = b0.z; acc[m][3] = b0.w;
            acc[m][4] = b1v.x; acc[m][5] = b1v.y; acc[m][6] = b1v.z; acc[m][7] = b1v.w;
        }
    }
    gemm128(sB, Wn2, sW, acc, tm, tn, tid);

    __syncthreads();
#pragma unroll
    for (int m = 0; m < 4; m++) {
        int row = tm * 4 + m;
        float4 h0 = *(const float4*)&sA[row * H + tn * 8];
        float4 h1 = *(const float4*)&sA[row * H + tn * 8 + 4];
        *(float4*)&sB[row * H + tn * 8]     = make_float4(h0.x + acc[m][0], h0.y + acc[m][1], h0.z + acc[m][2], h0.w + acc[m][3]);
        *(float4*)&sB[row * H + tn * 8 + 4] = make_float4(h1.x + acc[m][4], h1.y + acc[m][5], h1.z + acc[m][6], h1.w + acc[m][7]);
    }
    __syncthreads();

    {
        int row = tid >> 2;
        int part = tid & 3;
        int node = nbase + row;
        const float4* yv = (const float4*)sB;
        float s = 0.f, sq = 0.f;
        float4 vals[8];
#pragma unroll
        for (int j = 0; j < 8; j++) {
            float4 v = yv[row * 32 + part * 8 + j];
            vals[j] = v;
            s  += v.x + v.y + v.z + v.w;
            sq += v.x * v.x + v.y * v.y + v.z * v.z + v.w * v.w;
        }
        s  += __shfl_xor_sync(0xffffffffu, s, 1);
        sq += __shfl_xor_sync(0xffffffffu, sq, 1);
        s  += __shfl_xor_sync(0xffffffffu, s, 2);
        sq += __shfl_xor_sync(0xffffffffu, sq, 2);
        float mu  = s * (1.0f / 128.0f);
        float var = sq * (1.0f / 128.0f) - mu * mu;
        float inv = rsqrtf(var + 1e-5f);
        if (node < N_NODES) {
            float4* ov = (float4*)(out_h + (size_t)node * H);
#pragma unroll
            for (int j = 0; j < 8; j++) {
                int c4 = part * 8 + j;
                float4 g = *(const float4*)(gamma + c4 * 4);
                float4 b = *(const float4*)(beta + c4 * 4);
                float4 v = vals[j];
                ov[c4] = make_float4((v.x - mu) * inv * g.x + b.x,
                                     (v.y - mu) * inv * g.y + b.y,
                                     (v.z - mu) * inv * g.z + b.z,
                                     (v.w - mu) * inv * g.w + b.w);
            }
        }
    }

    if (tid < 192) {
        int r = tid / 3, c = tid % 3;
        int node = nbase + r;
        if (node < N_NODES) {
            float cnt = fmaxf(g_agg_coord4[(size_t)node * 4 + 3], 1.0f);
            out_x[(size_t)node * 3 + c] = x[(size_t)node * 3 + c]
                                        + g_agg_coord4[(size_t)node * 4 + c] / cnt;
        }
    }
}

// ---------------------------------------------------------------------------
extern "C" void kernel_launch(void* const* d_in, const int* in_sizes, int n_in,
                              void* d_out, int out_size)
{
    const float* h    = (const float*)d_in[0];
    const float* x    = (const float*)d_in[1];
    const int*   eidx = (const int*)  d_in[2];
    const float* ea   = (const float*)d_in[3];
    const float* W1   = (const float*)d_in[4];
    const float* b1   = (const float*)d_in[5];
    const float* W2   = (const float*)d_in[6];
    const float* b2   = (const float*)d_in[7];
    const float* Wc1  = (const float*)d_in[8];
    const float* bc1  = (const float*)d_in[9];
    const float* Wc2  = (const float*)d_in[10];
    const float* bc2  = (const float*)d_in[11];
    const float* Wn1  = (const float*)d_in[12];
    const float* bn1  = (const float*)d_in[13];
    const float* Wn2  = (const float*)d_in[14];
    const float* bn2  = (const float*)d_in[15];
    const float* gamma = (const float*)d_in[16];
    const float* beta  = (const float*)d_in[17];

    float* out_h = (float*)d_out;
    float* out_x = out_h + (size_t)N_NODES * H;

    const int NODE_SMEM = (64 * H + 64 * H + 16 * H) * 4;
    cudaFuncSetAttribute(edge_kernel, cudaFuncAttributeMaxDynamicSharedMemorySize, EDGE_SMEM);
    cudaFuncSetAttribute(node_kernel, cudaFuncAttributeMaxDynamicSharedMemorySize, NODE_SMEM);

    zero_kernel<<<(N_NODES * H + 255) / 256, 256>>>();
    hbf_kernel<<<(N_NODES * 16 + 255) / 256, 256>>>(h);
    prep_kernel<<<(128 * 288 + 255) / 256, 256>>>(W1, 0, 260, 288);
    prep_kernel<<<(128 * 128 + 255) / 256, 256>>>(W2, 1, 128, 128);
    prep_kernel<<<(128 * 128 + 255) / 256, 256>>>(Wc1, 2, 128, 128);
    edge_kernel<<<N_EDGES / 128, 256, EDGE_SMEM>>>(x, eidx, ea, b1, b2, bc1, Wc2, bc2);
    node_kernel<<<(N_NODES + 63) / 64, 256, NODE_SMEM>>>(h, x, Wn1, bn1, Wn2, bn2,
                                                         gamma, beta, out_h, out_x);
}

// round 12
// speedup vs baseline: 6.2251x; 1.2478x over previous
#include <cuda_runtime.h>
#include <cuda_fp16.h>
#include <cstdint>

#define N_NODES 50000
#define N_EDGES 800000
#define H 128

// ---------------- device scratch ----------------
__device__ __align__(16) float g_agg_msg[(size_t)N_NODES * H];
__device__ __align__(16) float g_agg_coord4[(size_t)N_NODES * 4];  // x,y,z,count
// Weights as 8x8 b16 ldmatrix tiles, fp16, k64 chunk images (8192 ushorts = 16KB each).
__device__ __align__(16) unsigned short g_W1b[5 * 8192];   // K=288 -> 4 full + tail
__device__ __align__(16) unsigned short g_W2b[2 * 8192];
__device__ __align__(16) unsigned short g_Wc1b[2 * 8192];
__device__ __align__(16) unsigned short g_Wn1b[4 * 8192];  // K=256
__device__ __align__(16) unsigned short g_Wn2b[2 * 8192];  // K=128
// h pre-converted to fp16 16B groups: [node][k32chunk(4)][group(4)] uint4
__device__ __align__(16) uint4 g_hbf[(size_t)N_NODES * 16];

// ---------------- helpers ----------------
__device__ __forceinline__ uint32_t smem_u32(const void* p) {
    uint32_t a;
    asm("{ .reg .u64 t; cvta.to.shared.u64 t, %1; cvt.u32.u64 %0, t; }" : "=r"(a) : "l"(p));
    return a;
}
__device__ __forceinline__ float h16rt(float v) {
    return __half2float(__float2half_rn(v));
}
__device__ __forceinline__ uint32_t pack2h(float a, float b) {
    __half2 hh = __floats2half2_rn(a, b);
    return *(uint32_t*)&hh;
}
__device__ __forceinline__ float silu_f(float v) {
    return v * (1.0f / (1.0f + __expf(-v)));
}
__device__ __forceinline__ void redv2(float* p, float a, float b) {
    asm volatile("red.global.add.v2.f32 [%0], {%1, %2};" :: "l"(p), "f"(a), "f"(b) : "memory");
}
__device__ __forceinline__ void redv4(float* p, float a, float b, float c, float d) {
    asm volatile("red.global.add.v4.f32 [%0], {%1, %2, %3, %4};"
                 :: "l"(p), "f"(a), "f"(b), "f"(c), "f"(d) : "memory");
}
__device__ __forceinline__ void ldm4(uint32_t* r, uint32_t addr) {
    asm volatile("ldmatrix.sync.aligned.m8n8.x4.shared.b16 {%0,%1,%2,%3}, [%4];"
                 : "=r"(r[0]), "=r"(r[1]), "=r"(r[2]), "=r"(r[3]) : "r"(addr));
}
__device__ __forceinline__ void mma_f16(float* d, const uint32_t* a, uint32_t b0, uint32_t b1) {
    asm volatile("mma.sync.aligned.m16n8k16.row.col.f32.f16.f16.f32 "
                 "{%0,%1,%2,%3}, {%4,%5,%6,%7}, {%8,%9}, {%0,%1,%2,%3};"
                 : "+f"(d[0]), "+f"(d[1]), "+f"(d[2]), "+f"(d[3])
                 : "r"(a[0]), "r"(a[1]), "r"(a[2]), "r"(a[3]), "r"(b0), "r"(b1));
}
__device__ __forceinline__ void cp_async16(uint32_t dst, const void* src) {
    asm volatile("cp.async.cg.shared.global [%0], [%1], 16;" :: "r"(dst), "l"(src) : "memory");
}
#define CP_COMMIT  asm volatile("cp.async.commit_group;" ::: "memory")
#define CP_WAIT_0  asm volatile("cp.async.wait_group 0;" ::: "memory")

// A-plane XOR swizzle: 64B row stride, 16B groups permuted by g ^= (row>>1)&3.
__device__ __forceinline__ uint32_t aswz(int row, int byteInRow) {
    int g = byteInRow >> 4;
    int inner = byteInRow & 15;
    return (uint32_t)(row * 64 + (((g ^ ((row >> 1) & 3)) << 4) | inner));
}

// ---------------- smem layout (edge kernel) ----------------
#define AF_OFF   0         // 4 subslots x 8192
#define BB_OFF   32768     // B double buffer: 2 x 16384
#define BIAS_OFF 65536     // b1,b2,bc1,Wc2 : 4*512
#define REL_OFF  67584
#define EA_OFF   69120
#define DSQ_OFF  70656
#define SRC_OFF  71168
#define DST_OFF  71680
#define PW_OFF   72192
#define EDGE_SMEM 73216

// ---------------- smem layout (node kernel) ----------------
// shares AF_OFF / BB_OFF; bias region: bn1,bn2,gamma,beta
#define NSS_OFF  67584     // LN sum partials  128*8 f
#define NSQ_OFF  71680     // LN sumsq partials
#define NMU_OFF  75776     // mu 128 f
#define NINV_OFF 76288     // inv 128 f
#define NODE_SMEM 76800

// ---------------- zero / prep ----------------
__global__ void zero_kernel()
{
    int i = blockIdx.x * blockDim.x + threadIdx.x;
    if (i < N_NODES * H) g_agg_msg[i] = 0.0f;
    if (i < N_NODES * 4) g_agg_coord4[i] = 0.0f;
}

__global__ void hbf_kernel(const float* __restrict__ h)
{
    int idx = blockIdx.x * blockDim.x + threadIdx.x;
    if (idx >= N_NODES * 16) return;
    int node = idx >> 4;
    int gg = idx & 15;
    const float* src = h + (size_t)node * H + gg * 8;
    uint32_t w[4];
#pragma unroll
    for (int i = 0; i < 4; i++)
        w[i] = pack2h(src[i * 2], src[i * 2 + 1]);
    g_hbf[(size_t)node * 16 + gg] = make_uint4(w[0], w[1], w[2], w[3]);
}

// W[K,128] -> fp16 as 8x8 b16 ldmatrix tiles, k64 chunk images.
__global__ void prep_kernel(const float* __restrict__ W, int which, int Kact, int Kpad)
{
    int idx = blockIdx.x * blockDim.x + threadIdx.x;
    if (idx >= 128 * Kpad) return;
    int k = idx >> 7;
    int n = idx & 127;
    float v = (k < Kact) ? W[k * 128 + n] : 0.0f;
    int chunk = k >> 6, ks = (k >> 4) & 3, khalf = (k >> 3) & 1, kin = k & 7;
    int nf = n >> 3, nin = n & 7;
    unsigned short* dst = (which == 0) ? g_W1b : (which == 1) ? g_W2b :
                          (which == 2) ? g_Wc1b : (which == 3) ? g_Wn1b : g_Wn2b;
    int tile = ks * 32 + nf * 2 + khalf;
    __half hh = __float2half_rn(v);
    dst[chunk * 8192 + tile * 64 + nin * 8 + kin] = *(unsigned short*)&hh;
}

// ---------------- shared mma pieces ----------------
__device__ __forceinline__ void init_d(float d[2][8][4], const float* sBias,
                                       int stage, int lane, int wc)
{
#pragma unroll
    for (int nf = 0; nf < 8; nf++) {
        int c0 = wc * 64 + nf * 8 + (lane & 3) * 2;
        float b0v = sBias[stage * 128 + c0];
        float b1v = sBias[stage * 128 + c0 + 1];
#pragma unroll
        for (int mf = 0; mf < 2; mf++) {
            d[mf][nf][0] = b0v; d[mf][nf][1] = b1v;
            d[mf][nf][2] = b0v; d[mf][nf][3] = b1v;
        }
    }
}

template<int NKS, bool TAIL>
__device__ __forceinline__ void do_mma(uint32_t sbase, uint32_t bBuf, uint32_t aOff,
                                       int lane, int wm, int wc, float d[2][8][4])
{
    uint32_t aRegion = sbase + AF_OFF + aOff;
    uint32_t bRow = (uint32_t)(((lane >> 3) << 7) + ((lane & 7) << 4));
#pragma unroll
    for (int ks = 0; ks < NKS; ks++) {
        int kbyte = (ks & 1) * 32 + ((lane & 16) ? 16 : 0);
        uint32_t subOff = (uint32_t)(ks >> 1) * 8192;
        uint32_t aHi[2][4], aLo[2][4];
#pragma unroll
        for (int mf = 0; mf < 2; mf++) {
            int row = wm * 32 + mf * 16 + (lane & 15);
            uint32_t ad = aRegion + subOff + aswz(row, kbyte);
            ldm4(aHi[mf], ad);
            if (TAIL) ldm4(aLo[mf], ad + 8192);
        }
        uint32_t tB = bBuf + (uint32_t)(ks * 32 + wc * 16) * 128 + bRow;
#pragma unroll
        for (int q = 0; q < 4; q++) {
            uint32_t bh[4];
            ldm4(bh, tB + q * 512);
#pragma unroll
            for (int j = 0; j < 2; j++) {
                int nf = q * 2 + j;
#pragma unroll
                for (int mf = 0; mf < 2; mf++) {
                    mma_f16(d[mf][nf], aHi[mf], bh[j * 2], bh[j * 2 + 1]);
                    if (TAIL) mma_f16(d[mf][nf], aLo[mf], bh[j * 2], bh[j * 2 + 1]);
                }
            }
        }
    }
}

// silu + write fp16 activations into A subslots (handoff between stages)
__device__ __forceinline__ void silu_store_act(char* sb, float d[2][8][4],
                                               int lane, int wm, int wc)
{
#pragma unroll
    for (int mf = 0; mf < 2; mf++) {
        int r0 = wm * 32 + mf * 16 + (lane >> 2);
        int r1 = r0 + 8;
#pragma unroll
        for (int nf = 0; nf < 8; nf++) {
            int c0 = wc * 64 + nf * 8 + (lane & 3) * 2;
            float v0 = silu_f(d[mf][nf][0]);
            float v1 = silu_f(d[mf][nf][1]);
            float v2 = silu_f(d[mf][nf][2]);
            float v3 = silu_f(d[mf][nf][3]);
            int sub = c0 >> 5;
            int byte0 = (c0 & 31) * 2;
            char* subBase = sb + AF_OFF + sub * 8192;
            *(uint32_t*)(subBase + aswz(r0, byte0)) = pack2h(v0, v1);
            *(uint32_t*)(subBase + aswz(r1, byte0)) = pack2h(v2, v3);
        }
    }
}

// ---------------- edge kernel (unchanged from R10-passing) ----------------
__device__ __forceinline__ void issueB(uint32_t sbase, int cg, int tid)
{
    const unsigned short* gW;
    int cin;
    if (cg < 5)       { gW = g_W1b;  cin = cg; }
    else if (cg < 7)  { gW = g_W2b;  cin = cg - 5; }
    else              { gW = g_Wc1b; cin = cg - 7; }
    const uint4* bsrc = (const uint4*)(gW + (size_t)cin * 8192);
    uint32_t bdst = sbase + BB_OFF + (uint32_t)(cg & 1) * 16384;
    int niter = (cg == 4) ? 1 : 4;
#pragma unroll
    for (int i = 0; i < 4; i++) {
        if (i < niter)
            cp_async16(bdst + (uint32_t)(tid + i * 256) * 16, bsrc + tid + i * 256);
    }
    CP_COMMIT;
}

__device__ __forceinline__ void issueA(uint32_t sbase, int cn, const int* sSrc,
                                       const int* sDst, int row, int halfq)
{
    int node = ((cn < 2) ? sSrc : sDst)[row];
    const uint4* hbase = g_hbf + (size_t)node * 16 + (cn & 1) * 8;
    uint32_t dstBase = sbase + AF_OFF + (uint32_t)((cn & 1) * 2) * 8192;
#pragma unroll
    for (int sub = 0; sub < 2; sub++) {
#pragma unroll
        for (int j = 0; j < 2; j++) {
            int g = halfq * 2 + j;
            cp_async16(dstBase + (uint32_t)sub * 8192 + aswz(row, g * 16),
                       hbase + sub * 4 + g);
        }
    }
}

template<int STAGE>
__device__ __forceinline__ void epilogue(char* sb, float d[2][8][4],
                                         const int* sDst, const float* sRel,
                                         const float* bc2, float* sPw,
                                         int tid, int lane, int wm, int wc)
{
    __syncthreads();
    const float* sBias = (const float*)(sb + BIAS_OFF);
    float pw0[2] = {0.f, 0.f}, pw1[2] = {0.f, 0.f};
#pragma unroll
    for (int mf = 0; mf < 2; mf++) {
        int r0 = wm * 32 + mf * 16 + (lane >> 2);
        int r1 = r0 + 8;
#pragma unroll
        for (int nf = 0; nf < 8; nf++) {
            int c0 = wc * 64 + nf * 8 + (lane & 3) * 2;
            float v0 = silu_f(d[mf][nf][0]);
            float v1 = silu_f(d[mf][nf][1]);
            float v2 = silu_f(d[mf][nf][2]);
            float v3 = silu_f(d[mf][nf][3]);
            if (STAGE == 2) {
                float w0 = sBias[384 + c0], w1 = sBias[384 + c0 + 1];
                pw0[mf] += v0 * w0 + v1 * w1;
                pw1[mf] += v2 * w0 + v3 * w1;
            } else {
                if (STAGE == 1) {
                    redv2(&g_agg_msg[(size_t)sDst[r0] * H + c0], v0, v1);
                    redv2(&g_agg_msg[(size_t)sDst[r1] * H + c0], v2, v3);
                }
                int sub = c0 >> 5;
                int byte0 = (c0 & 31) * 2;
                char* subBase = sb + AF_OFF + sub * 8192;
                *(uint32_t*)(subBase + aswz(r0, byte0)) = pack2h(v0, v1);
                *(uint32_t*)(subBase + aswz(r1, byte0)) = pack2h(v2, v3);
            }
        }
    }
    if (STAGE == 2) {
#pragma unroll
        for (int o = 1; o < 4; o <<= 1) {
            pw0[0] += __shfl_xor_sync(0xffffffffu, pw0[0], o);
            pw0[1] += __shfl_xor_sync(0xffffffffu, pw0[1], o);
            pw1[0] += __shfl_xor_sync(0xffffffffu, pw1[0], o);
            pw1[1] += __shfl_xor_sync(0xffffffffu, pw1[1], o);
        }
        if ((lane & 3) == 0) {
            int r = wm * 32 + (lane >> 2);
            sPw[wc * 128 + r]      = pw0[0];
            sPw[wc * 128 + r + 8]  = pw1[0];
            sPw[wc * 128 + r + 16] = pw0[1];
            sPw[wc * 128 + r + 24] = pw1[1];
        }
        __syncthreads();
        if (tid < 128) {
            float w = sPw[tid] + sPw[128 + tid] + bc2[0];
            int dd = sDst[tid];
            redv4(&g_agg_coord4[(size_t)dd * 4],
                  sRel[tid * 3 + 0] * w, sRel[tid * 3 + 1] * w, sRel[tid * 3 + 2] * w, 1.0f);
        }
    }
}

__global__ __launch_bounds__(256, 2) void edge_kernel(
    const float* __restrict__ x,
    const int*   __restrict__ ei, const float* __restrict__ ea,
    const float* __restrict__ b1, const float* __restrict__ b2,
    const float* __restrict__ bc1, const float* __restrict__ Wc2,
    const float* __restrict__ bc2)
{
    extern __shared__ char sb[];
    uint32_t sbase = smem_u32(sb);
    int tid = threadIdx.x, lane = tid & 31, wid = tid >> 5;
    int wm = wid & 3, wc = wid >> 2;
    int ebase = blockIdx.x * 128;

    float* sBias = (float*)(sb + BIAS_OFF);
    float* sRel  = (float*)(sb + REL_OFF);
    float* sEa   = (float*)(sb + EA_OFF);
    float* sDsq  = (float*)(sb + DSQ_OFF);
    int*   sSrc  = (int*)(sb + SRC_OFF);
    int*   sDst  = (int*)(sb + DST_OFF);
    float* sPw   = (float*)(sb + PW_OFF);

    if (tid < 128) {
        sBias[tid]       = b1[tid];
        sBias[128 + tid] = b2[tid];
        sBias[256 + tid] = bc1[tid];
        sBias[384 + tid] = Wc2[tid];
        int e = ebase + tid;
        int s = ei[e];
        int dd = ei[N_EDGES + e];
        sSrc[tid] = s; sDst[tid] = dd;
        float rx = x[s * 3 + 0] - x[dd * 3 + 0];
        float ry = x[s * 3 + 1] - x[dd * 3 + 1];
        float rz = x[s * 3 + 2] - x[dd * 3 + 2];
        sRel[tid * 3 + 0] = rx; sRel[tid * 3 + 1] = ry; sRel[tid * 3 + 2] = rz;
        sDsq[tid] = rx * rx + ry * ry + rz * rz;
        sEa[tid * 3 + 0] = ea[e * 3 + 0];
        sEa[tid * 3 + 1] = ea[e * 3 + 1];
        sEa[tid * 3 + 2] = ea[e * 3 + 2];
    }
    __syncthreads();

    float d[2][8][4];
    int row = tid >> 1, halfq = tid & 1;

    // STAGE 0 : 5 chunks (4x k64 + k32 tail)
    init_d(d, sBias, 0, lane, wc);
    issueA(sbase, 0, sSrc, sDst, row, halfq);
    issueB(sbase, 0, tid);
#pragma unroll 1
    for (int c = 0; c < 5; c++) {
        CP_WAIT_0;
        __syncthreads();
        bool pf = (c < 3);
        if (pf) issueA(sbase, c + 1, sSrc, sDst, row, halfq);
        issueB(sbase, c + 1, tid);
        uint32_t bBuf = sbase + BB_OFF + (uint32_t)(c & 1) * 16384;
        if (c == 4) do_mma<1, true>(sbase, bBuf, 0, lane, wm, wc, d);
        else        do_mma<4, false>(sbase, bBuf, (uint32_t)(c & 1) * 16384, lane, wm, wc, d);
        if (c == 3) {
            char* base = sb + AF_OFF + (halfq ? 8192 : 0);
            uint32_t* p0 = (uint32_t*)(base + aswz(row, 0));
            if (halfq == 0) {
                p0[0] = pack2h(sEa[row * 3 + 0], sEa[row * 3 + 1]);
                p0[1] = pack2h(sEa[row * 3 + 2], sDsq[row]);
            } else {
                float e0 = sEa[row * 3 + 0], e1 = sEa[row * 3 + 1];
                float e2 = sEa[row * 3 + 2], dq = sDsq[row];
                p0[0] = pack2h(e0 - h16rt(e0), e1 - h16rt(e1));
                p0[1] = pack2h(e2 - h16rt(e2), dq - h16rt(dq));
            }
            p0[2] = 0u; p0[3] = 0u;
            uint32_t* p1 = (uint32_t*)(base + aswz(row, 16));
            p1[0] = 0u; p1[1] = 0u; p1[2] = 0u; p1[3] = 0u;
        }
    }
    epilogue<0>(sb, d, sDst, sRel, bc2, sPw, tid, lane, wm, wc);

    // STAGE 1 : chunks 5,6
    init_d(d, sBias, 1, lane, wc);
#pragma unroll 1
    for (int c = 0; c < 2; c++) {
        int cg = 5 + c;
        CP_WAIT_0;
        __syncthreads();
        issueB(sbase, cg + 1, tid);
        do_mma<4, false>(sbase, sbase + BB_OFF + (uint32_t)(cg & 1) * 16384,
                         (uint32_t)c * 16384, lane, wm, wc, d);
    }
    epilogue<1>(sb, d, sDst, sRel, bc2, sPw, tid, lane, wm, wc);

    // STAGE 2 : chunks 7,8
    init_d(d, sBias, 2, lane, wc);
#pragma unroll 1
    for (int c = 0; c < 2; c++) {
        int cg = 7 + c;
        CP_WAIT_0;
        __syncthreads();
        if (cg < 8) issueB(sbase, cg + 1, tid);
        do_mma<4, false>(sbase, sbase + BB_OFF + (uint32_t)(cg & 1) * 16384,
                         (uint32_t)c * 16384, lane, wm, wc, d);
    }
    epilogue<2>(sb, d, sDst, sRel, bc2, sPw, tid, lane, wm, wc);
}

// ---------------- tensorized node kernel : 128 nodes / block ----------------
__device__ __forceinline__ void issueB_node(uint32_t sbase, int cg, int tid)
{
    const unsigned short* gW = (cg < 4) ? g_Wn1b : g_Wn2b;
    int cin = (cg < 4) ? cg : cg - 4;
    const uint4* bsrc = (const uint4*)(gW + (size_t)cin * 8192);
    uint32_t bdst = sbase + BB_OFF + (uint32_t)(cg & 1) * 16384;
#pragma unroll
    for (int i = 0; i < 4; i++)
        cp_async16(bdst + (uint32_t)(tid + i * 256) * 16, bsrc + tid + i * 256);
    CP_COMMIT;
}

// A chunk cn (0,1) : h fp16 via cp.async from g_hbf (contiguous nodes)
__device__ __forceinline__ void issueA_node_h(uint32_t sbase, int cn, int nbase,
                                              int row, int halfq)
{
    int node = nbase + row;
    if (node >= N_NODES) node = N_NODES - 1;
    const uint4* hbase = g_hbf + (size_t)node * 16 + cn * 8;
    uint32_t dstBase = sbase + AF_OFF + (uint32_t)(cn * 2) * 8192;
#pragma unroll
    for (int sub = 0; sub < 2; sub++) {
#pragma unroll
        for (int j = 0; j < 2; j++) {
            int g = halfq * 2 + j;
            cp_async16(dstBase + (uint32_t)sub * 8192 + aswz(row, g * 16),
                       hbase + sub * 4 + g);
        }
    }
}

// A chunk cn (2,3) : agg_msg fp32 -> fp16 convert into subslot pair (cn&1)*2
__device__ __forceinline__ void fill_agg(char* sb, int cn, int nbase, int row, int halfq)
{
    int node = nbase + row;
    if (node >= N_NODES) node = N_NODES - 1;
    char* dstBase = sb + AF_OFF + ((cn & 1) * 2) * 8192;
#pragma unroll
    for (int sub = 0; sub < 2; sub++) {
        const float* s = g_agg_msg + (size_t)node * H + (cn - 2) * 64 + sub * 32 + halfq * 16;
#pragma unroll
        for (int j = 0; j < 2; j++) {
            float4 a = *(const float4*)(s + j * 8);
            float4 b = *(const float4*)(s + j * 8 + 4);
            uint4 w = make_uint4(pack2h(a.x, a.y), pack2h(a.z, a.w),
                                 pack2h(b.x, b.y), pack2h(b.z, b.w));
            *(uint4*)(dstBase + sub * 8192 + aswz(row, (halfq * 2 + j) * 16)) = w;
        }
    }
}

__global__ __launch_bounds__(256, 2) void node_kernel_t(
    const float* __restrict__ h,   const float* __restrict__ x,
    const float* __restrict__ bn1, const float* __restrict__ bn2,
    const float* __restrict__ gamma, const float* __restrict__ beta,
    float* __restrict__ out_h, float* __restrict__ out_x)
{
    extern __shared__ char sb[];
    uint32_t sbase = smem_u32(sb);
    int tid = threadIdx.x, lane = tid & 31, wid = tid >> 5;
    int wm = wid & 3, wc = wid >> 2;
    int nbase = blockIdx.x * 128;

    float* sBias = (float*)(sb + BIAS_OFF);   // bn1, bn2, gamma, beta
    float* sS    = (float*)(sb + NSS_OFF);
    float* sQ    = (float*)(sb + NSQ_OFF);
    float* sMu   = (float*)(sb + NMU_OFF);
    float* sInv  = (float*)(sb + NINV_OFF);

    if (tid < 128) {
        sBias[tid]       = bn1[tid];
        sBias[128 + tid] = bn2[tid];
        sBias[256 + tid] = gamma[tid];
        sBias[384 + tid] = beta[tid];
    }

    int row = tid >> 1, halfq = tid & 1;
    float d[2][8][4];

    issueA_node_h(sbase, 0, nbase, row, halfq);
    issueB_node(sbase, 0, tid);
    __syncthreads();   // bias visible
    init_d(d, sBias, 0, lane, wc);

    // STAGE N0 : 4 chunks (K=256)
#pragma unroll 1
    for (int c = 0; c < 4; c++) {
        CP_WAIT_0;
        __syncthreads();
        if (c == 0) issueA_node_h(sbase, 1, nbase, row, halfq);
        issueB_node(sbase, c + 1, tid);   // 1..4
        do_mma<4, false>(sbase, sbase + BB_OFF + (uint32_t)(c & 1) * 16384,
                         (uint32_t)(c & 1) * 16384, lane, wm, wc, d);
        if (c == 1) fill_agg(sb, 2, nbase, row, halfq);
        if (c == 2) fill_agg(sb, 3, nbase, row, halfq);
    }
    __syncthreads();
    silu_store_act(sb, d, lane, wm, wc);   // t1 -> A subslots
    init_d(d, sBias, 1, lane, wc);

    // STAGE N1 : 2 chunks (K=128)
#pragma unroll 1
    for (int c = 0; c < 2; c++) {
        CP_WAIT_0;
        __syncthreads();
        if (c == 0) issueB_node(sbase, 5, tid);
        do_mma<4, false>(sbase, sbase + BB_OFF + (uint32_t)((4 + c) & 1) * 16384,
                         (uint32_t)c * 16384, lane, wm, wc, d);
    }

    // epilogue: y = h + h_upd ; LayerNorm ; out_h ; x_out
    __syncthreads();
#pragma unroll
    for (int mf = 0; mf < 2; mf++) {
        int r0 = wm * 32 + mf * 16 + (lane >> 2);
        int r1 = r0 + 8;
        int n0 = nbase + r0, n1 = nbase + r1;
        size_t hb0 = (size_t)((n0 < N_NODES) ? n0 : N_NODES - 1) * H;
        size_t hb1 = (size_t)((n1 < N_NODES) ? n1 : N_NODES - 1) * H;
        float s0 = 0.f, q0 = 0.f, s1 = 0.f, q1 = 0.f;
#pragma unroll
        for (int nf = 0; nf < 8; nf++) {
            int c0 = wc * 64 + nf * 8 + (lane & 3) * 2;
            float2 h0 = *(const float2*)(h + hb0 + c0);
            float2 h1 = *(const float2*)(h + hb1 + c0);
            float y0 = d[mf][nf][0] + h0.x, y1 = d[mf][nf][1] + h0.y;
            float y2 = d[mf][nf][2] + h1.x, y3 = d[mf][nf][3] + h1.y;
            d[mf][nf][0] = y0; d[mf][nf][1] = y1;
            d[mf][nf][2] = y2; d[mf][nf][3] = y3;
            s0 += y0 + y1; q0 += y0 * y0 + y1 * y1;
            s1 += y2 + y3; q1 += y2 * y2 + y3 * y3;
        }
        int slot = wc * 4 + (lane & 3);
        sS[r0 * 8 + slot] = s0; sQ[r0 * 8 + slot] = q0;
        sS[r1 * 8 + slot] = s1; sQ[r1 * 8 + slot] = q1;
    }
    __syncthreads();
    if (tid < 128) {
        float s = 0.f, q = 0.f;
#pragma unroll
        for (int i = 0; i < 8; i++) { s += sS[tid * 8 + i]; q += sQ[tid * 8 + i]; }
        float mu = s * (1.0f / 128.0f);
        float var = q * (1.0f / 128.0f) - mu * mu;
        sMu[tid] = mu;
        sInv[tid] = rsqrtf(var + 1e-5f);
    }
    __syncthreads();
#pragma unroll
    for (int mf = 0; mf < 2; mf++) {
        int r0 = wm * 32 + mf * 16 + (lane >> 2);
        int r1 = r0 + 8;
        int n0 = nbase + r0, n1 = nbase + r1;
        float mu0 = sMu[r0], inv0 = sInv[r0];
        float mu1 = sMu[r1], inv1 = sInv[r1];
#pragma unroll
        for (int nf = 0; nf < 8; nf++) {
            int c0 = wc * 64 + nf * 8 + (lane & 3) * 2;
            float g0 = sBias[256 + c0], g1 = sBias[256 + c0 + 1];
            float be0 = sBias[384 + c0], be1 = sBias[384 + c0 + 1];
            if (n0 < N_NODES) {
                float2 o;
                o.x = (d[mf][nf][0] - mu0) * inv0 * g0 + be0;
                o.y = (d[mf][nf][1] - mu0) * inv0 * g1 + be1;
                *(float2*)(out_h + (size_t)n0 * H + c0) = o;
            }
            if (n1 < N_NODES) {
                float2 o;
                o.x = (d[mf][nf][2] - mu1) * inv1 * g0 + be0;
                o.y = (d[mf][nf][3] - mu1) * inv1 * g1 + be1;
                *(float2*)(out_h + (size_t)n1 * H + c0) = o;
            }
        }
    }
    // x_out
    for (int i = tid; i < 384; i += 256) {
        int r = i / 3, c = i % 3;
        int node = nbase + r;
        if (node < N_NODES) {
            float cnt = fmaxf(g_agg_coord4[(size_t)node * 4 + 3], 1.0f);
            out_x[(size_t)node * 3 + c] = x[(size_t)node * 3 + c]
                                        + g_agg_coord4[(size_t)node * 4 + c] / cnt;
        }
    }
}

// ---------------------------------------------------------------------------
extern "C" void kernel_launch(void* const* d_in, const int* in_sizes, int n_in,
                              void* d_out, int out_size)
{
    const float* h    = (const float*)d_in[0];
    const float* x    = (const float*)d_in[1];
    const int*   eidx = (const int*)  d_in[2];
    const float* ea   = (const float*)d_in[3];
    const float* W1   = (const float*)d_in[4];
    const float* b1   = (const float*)d_in[5];
    const float* W2   = (const float*)d_in[6];
    const float* b2   = (const float*)d_in[7];
    const float* Wc1  = (const float*)d_in[8];
    const float* bc1  = (const float*)d_in[9];
    const float* Wc2  = (const float*)d_in[10];
    const float* bc2  = (const float*)d_in[11];
    const float* Wn1  = (const float*)d_in[12];
    const float* bn1  = (const float*)d_in[13];
    const float* Wn2  = (const float*)d_in[14];
    const float* bn2  = (const float*)d_in[15];
    const float* gamma = (const float*)d_in[16];
    const float* beta  = (const float*)d_in[17];

    float* out_h = (float*)d_out;
    float* out_x = out_h + (size_t)N_NODES * H;

    cudaFuncSetAttribute(edge_kernel, cudaFuncAttributeMaxDynamicSharedMemorySize, EDGE_SMEM);
    cudaFuncSetAttribute(node_kernel_t, cudaFuncAttributeMaxDynamicSharedMemorySize, NODE_SMEM);

    zero_kernel<<<(N_NODES * H + 255) / 256, 256>>>();
    hbf_kernel<<<(N_NODES * 16 + 255) / 256, 256>>>(h);
    prep_kernel<<<(128 * 288 + 255) / 256, 256>>>(W1, 0, 260, 288);
    prep_kernel<<<(128 * 128 + 255) / 256, 256>>>(W2, 1, 128, 128);
    prep_kernel<<<(128 * 128 + 255) / 256, 256>>>(Wc1, 2, 128, 128);
    prep_kernel<<<(128 * 256 + 255) / 256, 256>>>(Wn1, 3, 256, 256);
    prep_kernel<<<(128 * 128 + 255) / 256, 256>>>(Wn2, 4, 128, 128);
    edge_kernel<<<N_EDGES / 128, 256, EDGE_SMEM>>>(x, eidx, ea, b1, b2, bc1, Wc2, bc2);
    node_kernel_t<<<(N_NODES + 127) / 128, 256, NODE_SMEM>>>(h, x, bn1, bn2, gamma, beta,
                                                             out_h, out_x);
}